// round 3
// baseline (speedup 1.0000x reference)
#include <cuda_runtime.h>
#include <cstddef>
#include <cstdint>

#define B_N 4096
#define HID 256
#define OBS_D 400
#define IN_D 432

// ---------------- scratch (device globals; no allocation allowed) ----------------
__device__ float g_state[14 * B_N * HID];
__device__ float g_samp[4 * B_N * 16];      // prev_pid, samp_sid, samp_sid0, samp_sid1
__device__ float g_obs_emb[B_N * OBS_D];
__device__ float g_xpre[B_N * 1024];        // gate-interleaved: col = unit*4 + gate
__device__ float g_WhhT[256 * 1024];        // [k][unit*4+gate]
__device__ float g_W0T[400 * 1024];
__device__ float g_WextT[32 * 1024];        // rows 0..15: samp cols; 16..31: addr cols
__device__ float g_bias[1024];              // (b_ih + b_hh) interleaved
__device__ float g_rp0[B_N * 2];
__device__ float g_z1[B_N * 100];
__device__ float g_z2[B_N * 100];
__device__ float g_rp0emb[B_N * 16];

__device__ __forceinline__ float sigf(float x) { return 1.f / (1.f + __expf(-x)); }
__device__ __forceinline__ float tanh_fast(float x) { return 2.f / (1.f + __expf(-2.f * x)) - 1.f; }

// ---------------- weight prep: transpose + gate-interleave ----------------
__global__ void prep_weights_kernel(const float* __restrict__ W_ih, const float* __restrict__ b_ih,
                                    const float* __restrict__ W_hh, const float* __restrict__ b_hh,
                                    float* __restrict__ WhhT, float* __restrict__ W0T,
                                    float* __restrict__ WextT, float* __restrict__ bias) {
    int idx = blockIdx.x * blockDim.x + threadIdx.x;
    int stride = gridDim.x * blockDim.x;
    for (int i = idx; i < 256 * 1024; i += stride) {
        int k = i >> 10, c = i & 1023, u = c >> 2, g = c & 3;
        WhhT[i] = W_hh[(size_t)(g * 256 + u) * 256 + k];
    }
    for (int i = idx; i < 400 * 1024; i += stride) {
        int k = i >> 10, c = i & 1023, u = c >> 2, g = c & 3;
        W0T[i] = W_ih[(size_t)(g * 256 + u) * IN_D + k];
    }
    for (int i = idx; i < 32 * 1024; i += stride) {
        int k = i >> 10, c = i & 1023, u = c >> 2, g = c & 3;
        WextT[i] = W_ih[(size_t)(g * 256 + u) * IN_D + 400 + k];
    }
    for (int i = idx; i < 1024; i += stride) {
        int u = i >> 2, g = i & 3;
        bias[i] = b_ih[g * 256 + u] + b_hh[g * 256 + u];
    }
}

// ---------------- embedding gathers ----------------
__global__ void gather_kernel(const int* __restrict__ pid, const int* __restrict__ sid,
                              const int* __restrict__ sid0, const int* __restrict__ sid1,
                              const float* __restrict__ pid_emb, const float* __restrict__ sid_emb,
                              float* __restrict__ s_pid, float* __restrict__ s_sid,
                              float* __restrict__ s_sid0, float* __restrict__ s_sid1) {
    int i = blockIdx.x * blockDim.x + threadIdx.x;
    if (i >= B_N * 16) return;
    int b = i >> 4, k = i & 15;
    s_pid[i]  = pid_emb[pid[b]  * 16 + k];
    s_sid[i]  = sid_emb[sid[b]  * 16 + k];
    s_sid0[i] = sid_emb[sid0[b] * 16 + k];
    s_sid1[i] = sid_emb[sid1[b] * 16 + k];
}

// ---------------- fused conv1+conv2+pool, ic-chunked for 2 blocks/SM ----------------
#define CONV_CH 8
__global__ void __launch_bounds__(256, 2) conv_fused_kernel(
    const float* __restrict__ obs, const float* __restrict__ w1, const float* __restrict__ b1,
    const float* __restrict__ w2, const float* __restrict__ b2, float* __restrict__ obs_emb) {
    extern __shared__ float sm[];
    float* s_in = sm;              // 4096
    float* s_w1 = s_in + 4096;     // 288
    float* s_b1 = s_w1 + 288;      // 32
    float* s_w2 = s_b1 + 32;       // 4608
    float* s_b2 = s_w2 + 4608;     // 16
    float* s_c1 = s_b2 + 16;       // 8192 (8 channels of 32x32)
    float* s_c2 = s_c1 + CONV_CH * 1024; // 4096
    int tid = threadIdx.x;
    int b = blockIdx.x;
    const float* in = obs + (size_t)b * 4096;
    for (int i = tid; i < 1024; i += 256) ((float4*)s_in)[i] = ((const float4*)in)[i];
    for (int i = tid; i < 288; i += 256) s_w1[i] = w1[i];
    for (int i = tid; i < 32; i += 256) s_b1[i] = b1[i];
    for (int i = tid; i < 4608; i += 256) s_w2[i] = w2[i];
    for (int i = tid; i < 16; i += 256) s_b2[i] = b2[i];

    // conv2 per-thread tile: 4 oc x 2x2 spatial, accumulated across ic chunks
    int ocg = tid >> 6;
    int oy0 = ((tid >> 3) & 7) * 2;
    int ox0 = (tid & 7) * 2;
    float acc2[4][2][2];
    #pragma unroll
    for (int a = 0; a < 4; a++)
        #pragma unroll
        for (int sy = 0; sy < 2; sy++)
            #pragma unroll
            for (int sx = 0; sx < 2; sx++) acc2[a][sy][sx] = 0.f;
    int iy0b = oy0 * 2 - 1, ix0b = ox0 * 2 - 1;

    for (int cc = 0; cc < 32 / CONV_CH; cc++) {
        __syncthreads();
        // conv1: (1,64,64) -> chunk of CONV_CH channels of (32,32), stride 2, pad 1, relu
        for (int o = tid; o < CONV_CH * 1024; o += 256) {
            int ocl = o >> 10;
            int oc = cc * CONV_CH + ocl;
            int oy = (o >> 5) & 31;
            int ox = o & 31;
            const float* w = s_w1 + oc * 9;
            float acc = s_b1[oc];
            int iy0 = oy * 2 - 1, ix0 = ox * 2 - 1;
            #pragma unroll
            for (int dy = 0; dy < 3; dy++) {
                int iy = iy0 + dy;
                if ((unsigned)iy < 64u) {
                    #pragma unroll
                    for (int dx = 0; dx < 3; dx++) {
                        int ix = ix0 + dx;
                        if ((unsigned)ix < 64u) acc += w[dy * 3 + dx] * s_in[iy * 64 + ix];
                    }
                }
            }
            s_c1[o] = fmaxf(acc, 0.f);
        }
        __syncthreads();
        // conv2 accumulate over this ic chunk
        for (int icl = 0; icl < CONV_CH; icl++) {
            int ic = cc * CONV_CH + icl;
            float inp[5][5];
            #pragma unroll
            for (int r = 0; r < 5; r++) {
                int iy = iy0b + r;
                bool okr = (unsigned)iy < 32u;
                #pragma unroll
                for (int q = 0; q < 5; q++) {
                    int ix = ix0b + q;
                    inp[r][q] = (okr && (unsigned)ix < 32u) ? s_c1[icl * 1024 + iy * 32 + ix] : 0.f;
                }
            }
            #pragma unroll
            for (int o4 = 0; o4 < 4; o4++) {
                const float* w = s_w2 + ((ocg * 4 + o4) * 32 + ic) * 9;
                float wv[9];
                #pragma unroll
                for (int q = 0; q < 9; q++) wv[q] = w[q];
                #pragma unroll
                for (int sy = 0; sy < 2; sy++)
                    #pragma unroll
                    for (int sx = 0; sx < 2; sx++)
                        #pragma unroll
                        for (int dy = 0; dy < 3; dy++)
                            #pragma unroll
                            for (int dx = 0; dx < 3; dx++)
                                acc2[o4][sy][sx] += wv[dy * 3 + dx] * inp[sy * 2 + dy][sx * 2 + dx];
            }
        }
    }
    // conv2 writeback with bias+relu
    #pragma unroll
    for (int o4 = 0; o4 < 4; o4++) {
        float bb = s_b2[ocg * 4 + o4];
        #pragma unroll
        for (int sy = 0; sy < 2; sy++)
            #pragma unroll
            for (int sx = 0; sx < 2; sx++)
                s_c2[(ocg * 4 + o4) * 256 + (oy0 + sy) * 16 + (ox0 + sx)] = fmaxf(acc2[o4][sy][sx] + bb, 0.f);
    }
    __syncthreads();
    // avg pool 3x3 stride 3 VALID -> (16,5,5) -> 400
    for (int o = tid; o < 400; o += 256) {
        int c = o / 25;
        int rem = o - c * 25;
        int py = rem / 5, px = rem - (rem / 5) * 5;
        float s = 0.f;
        #pragma unroll
        for (int dy = 0; dy < 3; dy++)
            #pragma unroll
            for (int dx = 0; dx < 3; dx++)
                s += s_c2[c * 256 + (py * 3 + dy) * 16 + (px * 3 + dx)];
        obs_emb[(size_t)b * OBS_D + o] = s * (1.f / 9.f);
    }
}

// ---------------- high-throughput GEMM core: 128x128 tile, 8x8/thread, double-buffered ----------------
// A: [M, astride] rows row0..row0+127, k-phase cols; astride==0 => broadcast row.
// B: k-major [K][1024], n-slab n0..n0+127. nslabs slabs of k=8.
__device__ __forceinline__ void gemm_phase(
    const float* __restrict__ A, int astride,
    const float* __restrict__ Bp, int nslabs,
    float* As, float* Bs, float acc[8][8],
    int tid, int row0, int n0, int ty8, int tx8)
{
    const int am = tid >> 1, ak = (tid & 1) * 4;
    const int bk = tid >> 5, bn = (tid & 31) * 4;
    float4 a = *(const float4*)&A[(size_t)(row0 + am) * astride + ak];
    float4 bv = *(const float4*)&Bp[(size_t)bk * 1024 + n0 + bn];
    As[(ak + 0) * 128 + am] = a.x;
    As[(ak + 1) * 128 + am] = a.y;
    As[(ak + 2) * 128 + am] = a.z;
    As[(ak + 3) * 128 + am] = a.w;
    *(float4*)&Bs[bk * 128 + bn] = bv;
    __syncthreads();
    for (int s = 0; s < nslabs; s++) {
        int cur = s & 1;
        if (s + 1 < nslabs) {
            a  = *(const float4*)&A[(size_t)(row0 + am) * astride + (s + 1) * 8 + ak];
            bv = *(const float4*)&Bp[(size_t)((s + 1) * 8 + bk) * 1024 + n0 + bn];
        }
        const float* Ac = As + cur * 1024;
        const float* Bc = Bs + cur * 1024;
        #pragma unroll
        for (int k = 0; k < 8; k++) {
            float4 a0 = *(const float4*)&Ac[k * 128 + ty8];
            float4 a1 = *(const float4*)&Ac[k * 128 + ty8 + 4];
            float4 b0 = *(const float4*)&Bc[k * 128 + tx8];
            float4 b1 = *(const float4*)&Bc[k * 128 + tx8 + 4];
            float av[8] = {a0.x, a0.y, a0.z, a0.w, a1.x, a1.y, a1.z, a1.w};
            float bw[8] = {b0.x, b0.y, b0.z, b0.w, b1.x, b1.y, b1.z, b1.w};
            #pragma unroll
            for (int r = 0; r < 8; r++)
                #pragma unroll
                for (int c = 0; c < 8; c++)
                    acc[r][c] += av[r] * bw[c];
        }
        if (s + 1 < nslabs) {
            int nxt = cur ^ 1;
            float* An = As + nxt * 1024;
            float* Bn = Bs + nxt * 1024;
            An[(ak + 0) * 128 + am] = a.x;
            An[(ak + 1) * 128 + am] = a.y;
            An[(ak + 2) * 128 + am] = a.z;
            An[(ak + 3) * 128 + am] = a.w;
            *(float4*)&Bn[bk * 128 + bn] = bv;
        }
        __syncthreads();
    }
}

// ---------------- xpre = obs_emb @ W0T + bias (gate-interleaved cols) ----------------
__global__ void __launch_bounds__(256, 2) gemm_xpre_kernel(
    const float* __restrict__ A, const float* __restrict__ W0T,
    const float* __restrict__ bias, float* __restrict__ out) {
    __shared__ float As[2 * 1024];
    __shared__ float Bs[2 * 1024];
    const int tid = threadIdx.x;
    const int tx8 = (tid & 15) * 8, ty8 = (tid >> 4) * 8;
    const int row0 = blockIdx.y * 128;
    const int n0 = blockIdx.x * 128;
    float acc[8][8];
    #pragma unroll
    for (int r = 0; r < 8; r++)
        #pragma unroll
        for (int c = 0; c < 8; c++) acc[r][c] = 0.f;
    gemm_phase(A, OBS_D, W0T, 50, As, Bs, acc, tid, row0, n0, ty8, tx8);
    float4 bv0 = *(const float4*)&bias[n0 + tx8];
    float4 bv1 = *(const float4*)&bias[n0 + tx8 + 4];
    #pragma unroll
    for (int r = 0; r < 8; r++) {
        size_t b = row0 + ty8 + r;
        float4 o0 = make_float4(acc[r][0] + bv0.x, acc[r][1] + bv0.y, acc[r][2] + bv0.z, acc[r][3] + bv0.w);
        float4 o1 = make_float4(acc[r][4] + bv1.x, acc[r][5] + bv1.y, acc[r][6] + bv1.z, acc[r][7] + bv1.w);
        *(float4*)&out[b * 1024 + n0 + tx8] = o0;
        *(float4*)&out[b * 1024 + n0 + tx8 + 4] = o1;
    }
}

// ---------------- LSTM step: [h|samp|addr] GEMM + fused gate epilogue; z picks branch ----------------
__global__ void __launch_bounds__(256, 2) lstm_step_kernel(
    const float* __restrict__ xpre,
    const float* __restrict__ WhhT, const float* __restrict__ WextT,
    const float* __restrict__ addr_emb,
    const float* h_inA, const float* c_inA, const float* sampA, int aidA, float* h_outA, float* c_outA,
    const float* h_inB, const float* c_inB, const float* sampB, int aidB, float* h_outB, float* c_outB) {
    __shared__ float As[2 * 1024];
    __shared__ float Bs[2 * 1024];
    const float* h_in; const float* c_in; const float* samp; int aid; float* h_out; float* c_out;
    if (blockIdx.z == 0) { h_in = h_inA; c_in = c_inA; samp = sampA; aid = aidA; h_out = h_outA; c_out = c_outA; }
    else                 { h_in = h_inB; c_in = c_inB; samp = sampB; aid = aidB; h_out = h_outB; c_out = c_outB; }
    const int tid = threadIdx.x;
    const int tx8 = (tid & 15) * 8, ty8 = (tid >> 4) * 8;
    const int row0 = blockIdx.y * 128;
    const int n0 = blockIdx.x * 128;
    float acc[8][8];
    #pragma unroll
    for (int r = 0; r < 8; r++)
        #pragma unroll
        for (int c = 0; c < 8; c++) acc[r][c] = 0.f;

    if (h_in) gemm_phase(h_in, 256, WhhT, 32, As, Bs, acc, tid, row0, n0, ty8, tx8);
    if (samp) gemm_phase(samp, 16, WextT, 2, As, Bs, acc, tid, row0, n0, ty8, tx8);
    gemm_phase(addr_emb + aid * 16, 0, WextT + 16 * 1024, 2, As, Bs, acc, tid, row0, n0, ty8, tx8);

    const int u0 = (n0 + tx8) >> 2;
    #pragma unroll
    for (int r = 0; r < 8; r++) {
        size_t b = row0 + ty8 + r;
        const float* xp = xpre + b * 1024 + n0 + tx8;
        float4 xa = *(const float4*)xp;
        float4 xb = *(const float4*)(xp + 4);
        float cold0 = c_in ? c_in[b * 256 + u0] : 0.f;
        float cold1 = c_in ? c_in[b * 256 + u0 + 1] : 0.f;
        float iv = sigf(acc[r][0] + xa.x);
        float fv = sigf(acc[r][1] + xa.y);
        float gv = tanh_fast(acc[r][2] + xa.z);
        float ov = sigf(acc[r][3] + xa.w);
        float cn0 = fv * cold0 + iv * gv;
        float hn0 = ov * tanh_fast(cn0);
        iv = sigf(acc[r][4] + xb.x);
        fv = sigf(acc[r][5] + xb.y);
        gv = tanh_fast(acc[r][6] + xb.z);
        ov = sigf(acc[r][7] + xb.w);
        float cn1 = fv * cold1 + iv * gv;
        float hn1 = ov * tanh_fast(cn1);
        h_out[b * 256 + u0] = hn0;
        h_out[b * 256 + u0 + 1] = hn1;
        c_out[b * 256 + u0] = cn0;
        c_out[b * 256 + u0 + 1] = cn1;
    }
}

// ---------------- heads ----------------
__device__ __forceinline__ float warp_dot256(const float* __restrict__ h, const float* __restrict__ w, int lane) {
    const float* hp = h + lane * 8;
    const float* wp = w + lane * 8;
    float4 a0 = *(const float4*)hp;
    float4 a1 = *(const float4*)(hp + 4);
    float4 b0 = *(const float4*)wp;
    float4 b1 = *(const float4*)(wp + 4);
    float s = a0.x * b0.x + a0.y * b0.y + a0.z * b0.z + a0.w * b0.w
            + a1.x * b1.x + a1.y * b1.y + a1.z * b1.z + a1.w * b1.w;
    #pragma unroll
    for (int off = 16; off; off >>= 1) s += __shfl_down_sync(0xffffffffu, s, off);
    return s;  // valid on lane 0
}

// rp0 head (mid-graph dependency): cols 11,12 + save rp0
__global__ void head_rp_kernel(const float* __restrict__ h, const float* __restrict__ W,
                               const float* __restrict__ bias, const float* __restrict__ eps,
                               int col0, float* __restrict__ out, float* __restrict__ save) {
    int gw = (blockIdx.x * blockDim.x + threadIdx.x) >> 5;
    int lane = threadIdx.x & 31;
    if (gw >= B_N) return;
    const float* hp = h + (size_t)gw * 256;
    float d[4];
    #pragma unroll
    for (int o = 0; o < 4; o++) d[o] = warp_dot256(hp, W + o * 256, lane);
    if (lane == 0) {
        float r0 = d[0] + bias[0] + __expf(d[2] + bias[2]) * eps[(size_t)gw * 2 + 0];
        float r1 = d[1] + bias[1] + __expf(d[3] + bias[3]) * eps[(size_t)gw * 2 + 1];
        out[(size_t)gw * 15 + col0 + 0] = r0;
        out[(size_t)gw * 15 + col0 + 1] = r1;
        if (save) { save[(size_t)gw * 2 + 0] = r0; save[(size_t)gw * 2 + 1] = r1; }
    }
}

// all remaining heads in one kernel at the end
__global__ void final_heads_kernel(
    const float* __restrict__ h0, const float* __restrict__ h1, const float* __restrict__ h2,
    const float* __restrict__ h1b, const float* __restrict__ h2b, const float* __restrict__ h4b,
    const float* __restrict__ pid_w, const float* __restrict__ pid_b,
    const float* __restrict__ sid_w, const float* __restrict__ sid_b,
    const float* __restrict__ rp_w, const float* __restrict__ rp_b,
    const float* __restrict__ eps_rp, const float* __restrict__ eps_rp1,
    float* __restrict__ out) {
    int gw = (blockIdx.x * blockDim.x + threadIdx.x) >> 5;
    int lane = threadIdx.x & 31;
    if (gw >= B_N) return;
    size_t off = (size_t)gw * 256;
    float* o = out + (size_t)gw * 15;
    // pid logits from h0 -> cols 0..2
    for (int q = 0; q < 3; q++) {
        float s = warp_dot256(h0 + off, pid_w + q * 256, lane);
        if (lane == 0) o[q] = s + pid_b[q];
    }
    // sid logits from h1 -> cols 3..4
    for (int q = 0; q < 2; q++) {
        float s = warp_dot256(h1 + off, sid_w + q * 256, lane);
        if (lane == 0) o[3 + q] = s + sid_b[q];
    }
    // rp_b0 from h2 + eps_rp -> cols 5..6
    {
        float d[4];
        #pragma unroll
        for (int q = 0; q < 4; q++) d[q] = warp_dot256(h2 + off, rp_w + q * 256, lane);
        if (lane == 0) {
            o[5] = d[0] + rp_b[0] + __expf(d[2] + rp_b[2]) * eps_rp[(size_t)gw * 2 + 0];
            o[6] = d[1] + rp_b[1] + __expf(d[3] + rp_b[3]) * eps_rp[(size_t)gw * 2 + 1];
        }
    }
    // sid0 from h1b -> cols 7..8
    for (int q = 0; q < 2; q++) {
        float s = warp_dot256(h1b + off, sid_w + q * 256, lane);
        if (lane == 0) o[7 + q] = s + sid_b[q];
    }
    // sid1 from h2b -> cols 9..10
    for (int q = 0; q < 2; q++) {
        float s = warp_dot256(h2b + off, sid_w + q * 256, lane);
        if (lane == 0) o[9 + q] = s + sid_b[q];
    }
    // rp1 from h4b + eps_rp1 -> cols 13..14
    {
        float d[4];
        #pragma unroll
        for (int q = 0; q < 4; q++) d[q] = warp_dot256(h4b + off, rp_w + q * 256, lane);
        if (lane == 0) {
            o[13] = d[0] + rp_b[0] + __expf(d[2] + rp_b[2]) * eps_rp1[(size_t)gw * 2 + 0];
            o[14] = d[1] + rp_b[1] + __expf(d[3] + rp_b[3]) * eps_rp1[(size_t)gw * 2 + 1];
        }
    }
}

// ---------------- MLP: rp0(2) -> 100 -> 100 -> 16 ----------------
__global__ void mlp1_kernel(const float* __restrict__ rp0, const float* __restrict__ w1,
                            const float* __restrict__ b1, float* __restrict__ z1) {
    int i = blockIdx.x * blockDim.x + threadIdx.x;
    if (i >= B_N * 100) return;
    int b = i / 100, j = i - b * 100;
    float v = rp0[b * 2] * w1[j * 2] + rp0[b * 2 + 1] * w1[j * 2 + 1] + b1[j];
    z1[i] = tanh_fast(v);
}

__global__ void __launch_bounds__(128) mlp2_kernel(const float* __restrict__ z1, const float* __restrict__ w2,
                                                   const float* __restrict__ b2, float* __restrict__ z2) {
    __shared__ float w2s[100 * 101];
    __shared__ float z1s[8 * 100];
    __shared__ float b2s[100];
    int tid = threadIdx.x;
    int b0 = blockIdx.x * 8;
    for (int i = tid; i < 100 * 100; i += 128) { int j = i / 100, k = i - j * 100; w2s[j * 101 + k] = w2[i]; }
    for (int i = tid; i < 800; i += 128) z1s[i] = z1[(size_t)b0 * 100 + i];
    for (int i = tid; i < 100; i += 128) b2s[i] = b2[i];
    __syncthreads();
    for (int t = tid; t < 800; t += 128) {
        int r = t / 100, j = t - r * 100;
        float s = b2s[j];
        const float* zz = z1s + r * 100;
        const float* ww = w2s + j * 101;
        #pragma unroll 4
        for (int k = 0; k < 100; k++) s += zz[k] * ww[k];
        z2[(size_t)(b0 + r) * 100 + j] = tanh_fast(s);
    }
}

__global__ void mlp3_kernel(const float* __restrict__ z2, const float* __restrict__ w3,
                            const float* __restrict__ b3, float* __restrict__ remb) {
    int i = blockIdx.x * blockDim.x + threadIdx.x;
    if (i >= B_N * 16) return;
    int b = i >> 4, o = i & 15;
    float s = b3[o];
    const float* zz = z2 + (size_t)b * 100;
    const float* ww = w3 + o * 100;
    #pragma unroll 4
    for (int k = 0; k < 100; k++) s += zz[k] * ww[k];
    remb[i] = s;
}

// ---------------- host ----------------
static float* getsym(const void* symbol) {
    void* p = nullptr;
    cudaGetSymbolAddress(&p, symbol);
    return (float*)p;
}

extern "C" void kernel_launch(void* const* d_in, const int* in_sizes, int n_in,
                              void* d_out, int out_size) {
    const float* obs        = (const float*)d_in[0];
    const int*   program_id = (const int*)  d_in[1];
    const int*   shape_id   = (const int*)  d_in[2];
    const int*   shape_id_0 = (const int*)  d_in[3];
    const int*   shape_id_1 = (const int*)  d_in[4];
    const float* eps_rp     = (const float*)d_in[5];
    const float* eps_rp0    = (const float*)d_in[6];
    const float* eps_rp1    = (const float*)d_in[7];
    const float* conv1_w    = (const float*)d_in[8];
    const float* conv1_b    = (const float*)d_in[9];
    const float* conv2_w    = (const float*)d_in[10];
    const float* conv2_b    = (const float*)d_in[11];
    const float* mlp_w1     = (const float*)d_in[12];
    const float* mlp_b1     = (const float*)d_in[13];
    const float* mlp_w2     = (const float*)d_in[14];
    const float* mlp_b2     = (const float*)d_in[15];
    const float* mlp_w3     = (const float*)d_in[16];
    const float* mlp_b3     = (const float*)d_in[17];
    const float* W_ih       = (const float*)d_in[18];
    const float* b_ih       = (const float*)d_in[19];
    const float* W_hh       = (const float*)d_in[20];
    const float* b_hh       = (const float*)d_in[21];
    const float* addr_emb   = (const float*)d_in[22];
    const float* pid_emb    = (const float*)d_in[23];
    const float* sid_emb    = (const float*)d_in[24];
    const float* pid_ext_w  = (const float*)d_in[25];
    const float* pid_ext_b  = (const float*)d_in[26];
    const float* sid_ext_w  = (const float*)d_in[27];
    const float* sid_ext_b  = (const float*)d_in[28];
    const float* rp_ext_w   = (const float*)d_in[29];
    const float* rp_ext_b   = (const float*)d_in[30];
    float* out = (float*)d_out;

    float* st      = getsym(g_state);
    const int SZ   = B_N * HID;
    float* h0  = st + 0 * SZ;  float* c0  = st + 1 * SZ;
    float* h1  = st + 2 * SZ;  float* c1  = st + 3 * SZ;
    float* h1b = st + 4 * SZ;  float* c1b = st + 5 * SZ;
    float* h2  = st + 6 * SZ;  float* c2  = st + 7 * SZ;
    float* h2b = st + 8 * SZ;  float* c2b = st + 9 * SZ;
    float* h3b = st + 10 * SZ; float* c3b = st + 11 * SZ;
    float* h4b = st + 12 * SZ; float* c4b = st + 13 * SZ;

    float* samp   = getsym(g_samp);
    float* s_pid  = samp + 0 * B_N * 16;
    float* s_sid  = samp + 1 * B_N * 16;
    float* s_sid0 = samp + 2 * B_N * 16;
    float* s_sid1 = samp + 3 * B_N * 16;

    float* obs_e  = getsym(g_obs_emb);
    float* xpre   = getsym(g_xpre);
    float* WhhT   = getsym(g_WhhT);
    float* W0T    = getsym(g_W0T);
    float* WextT  = getsym(g_WextT);
    float* bias   = getsym(g_bias);
    float* rp0    = getsym(g_rp0);
    float* z1     = getsym(g_z1);
    float* z2     = getsym(g_z2);
    float* rp0emb = getsym(g_rp0emb);

    const int CONV_SMEM = (4096 + 288 + 32 + 4608 + 16 + CONV_CH * 1024 + 4096) * 4;
    cudaFuncSetAttribute(conv_fused_kernel, cudaFuncAttributeMaxDynamicSharedMemorySize, CONV_SMEM);

    prep_weights_kernel<<<512, 256>>>(W_ih, b_ih, W_hh, b_hh, WhhT, W0T, WextT, bias);
    gather_kernel<<<B_N * 16 / 256, 256>>>(program_id, shape_id, shape_id_0, shape_id_1,
                                           pid_emb, sid_emb, s_pid, s_sid, s_sid0, s_sid1);
    conv_fused_kernel<<<B_N, 256, CONV_SMEM>>>(obs, conv1_w, conv1_b, conv2_w, conv2_b, obs_e);
    gemm_xpre_kernel<<<dim3(8, B_N / 128), 256>>>(obs_e, W0T, bias, xpre);

    dim3 g1(8, B_N / 128, 1);
    dim3 g2(8, B_N / 128, 2);
    // step0: h=c=0, samp=0, aid=0
    lstm_step_kernel<<<g1, 256>>>(xpre, WhhT, WextT, addr_emb,
        nullptr, nullptr, nullptr, 0, h0, c0,
        nullptr, nullptr, nullptr, 0, nullptr, nullptr);
    // pair: step1A (aid=1) + step1B (aid=2), both from (h0,c0,s_pid)
    lstm_step_kernel<<<g2, 256>>>(xpre, WhhT, WextT, addr_emb,
        h0, c0, s_pid, 1, h1, c1,
        h0, c0, s_pid, 2, h1b, c1b);
    // pair: step2A (h1,s_sid,aid=4) + step2B (h1b,s_sid0,aid=3)
    lstm_step_kernel<<<g2, 256>>>(xpre, WhhT, WextT, addr_emb,
        h1, c1, s_sid, 4, h2, c2,
        h1b, c1b, s_sid0, 3, h2b, c2b);
    // step3B
    lstm_step_kernel<<<g1, 256>>>(xpre, WhhT, WextT, addr_emb,
        h2b, c2b, s_sid1, 5, h3b, c3b,
        nullptr, nullptr, nullptr, 0, nullptr, nullptr);
    head_rp_kernel<<<B_N / 8, 256>>>(h3b, rp_ext_w, rp_ext_b, eps_rp0, 11, out, rp0);
    // MLP on rp0
    mlp1_kernel<<<(B_N * 100 + 255) / 256, 256>>>(rp0, mlp_w1, mlp_b1, z1);
    mlp2_kernel<<<B_N / 8, 128>>>(z1, mlp_w2, mlp_b2, z2);
    mlp3_kernel<<<B_N * 16 / 256, 256>>>(z2, mlp_w3, mlp_b3, rp0emb);
    // step4B
    lstm_step_kernel<<<g1, 256>>>(xpre, WhhT, WextT, addr_emb,
        h3b, c3b, rp0emb, 6, h4b, c4b,
        nullptr, nullptr, nullptr, 0, nullptr, nullptr);
    // all remaining heads
    final_heads_kernel<<<B_N / 8, 256>>>(h0, h1, h2, h1b, h2b, h4b,
        pid_ext_w, pid_ext_b, sid_ext_w, sid_ext_b, rp_ext_w, rp_ext_b,
        eps_rp, eps_rp1, out);
}

// round 4
// speedup vs baseline: 1.9863x; 1.9863x over previous
#include <cuda_runtime.h>
#include <cstddef>
#include <cstdint>

#define B_N 4096
#define HID 256
#define OBS_D 400
#define IN_D 432

// ---------------- scratch (device globals; no allocation allowed) ----------------
__device__ float g_state[14 * B_N * HID];
__device__ float g_samp[4 * B_N * 16];      // prev_pid, samp_sid, samp_sid0, samp_sid1
__device__ float g_obs_emb[B_N * OBS_D];
__device__ float g_xpre[B_N * 1024];
__device__ float g_WhhT[256 * 1024];
__device__ float g_W0T[400 * 1024];
__device__ float g_WextT[32 * 1024];        // rows 0..15: samp cols of W_ih; 16..31: addr cols
__device__ float g_bias[1024];              // b_ih + b_hh
__device__ float g_rp0[B_N * 2];
__device__ float g_z1[B_N * 100];
__device__ float g_z2[B_N * 100];
__device__ float g_rp0emb[B_N * 16];

__device__ __forceinline__ float sigf(float x) { return 1.f / (1.f + __expf(-x)); }
__device__ __forceinline__ float tanh_fast(float x) { return 2.f / (1.f + __expf(-2.f * x)) - 1.f; }

#define FMA4(A_, s_, W_) { (A_).x += (s_)*(W_).x; (A_).y += (s_)*(W_).y; (A_).z += (s_)*(W_).z; (A_).w += (s_)*(W_).w; }

// ---------------- weight prep: transposes for coalesced GEMM loads ----------------
__global__ void prep_weights_kernel(const float* __restrict__ W_ih, const float* __restrict__ b_ih,
                                    const float* __restrict__ W_hh, const float* __restrict__ b_hh,
                                    float* __restrict__ WhhT, float* __restrict__ W0T,
                                    float* __restrict__ WextT, float* __restrict__ bias) {
    int idx = blockIdx.x * blockDim.x + threadIdx.x;
    int stride = gridDim.x * blockDim.x;
    for (int i = idx; i < 256 * 1024; i += stride) { int k = i >> 10, j = i & 1023; WhhT[i] = W_hh[(size_t)j * 256 + k]; }
    for (int i = idx; i < 400 * 1024; i += stride) { int k = i >> 10, j = i & 1023; W0T[i] = W_ih[(size_t)j * IN_D + k]; }
    for (int i = idx; i < 32 * 1024;  i += stride) { int k = i >> 10, j = i & 1023; WextT[i] = W_ih[(size_t)j * IN_D + 400 + k]; }
    for (int i = idx; i < 1024; i += stride) bias[i] = b_ih[i] + b_hh[i];
}

// ---------------- embedding gathers ----------------
__global__ void gather_kernel(const int* __restrict__ pid, const int* __restrict__ sid,
                              const int* __restrict__ sid0, const int* __restrict__ sid1,
                              const float* __restrict__ pid_emb, const float* __restrict__ sid_emb,
                              float* __restrict__ s_pid, float* __restrict__ s_sid,
                              float* __restrict__ s_sid0, float* __restrict__ s_sid1) {
    int i = blockIdx.x * blockDim.x + threadIdx.x;
    if (i >= B_N * 16) return;
    int b = i >> 4, k = i & 15;
    s_pid[i]  = pid_emb[pid[b]  * 16 + k];
    s_sid[i]  = sid_emb[sid[b]  * 16 + k];
    s_sid0[i] = sid_emb[sid0[b] * 16 + k];
    s_sid1[i] = sid_emb[sid1[b] * 16 + k];
}

// ---------------- fused conv1+conv2+pool, ic-chunked, 2 blocks/SM ----------------
#define CONV_CH 8
__global__ void __launch_bounds__(256, 2) conv_fused_kernel(
    const float* __restrict__ obs, const float* __restrict__ w1, const float* __restrict__ b1,
    const float* __restrict__ w2, const float* __restrict__ b2, float* __restrict__ obs_emb) {
    extern __shared__ float sm[];
    float* s_in = sm;              // 4096
    float* s_w1 = s_in + 4096;     // 288
    float* s_b1 = s_w1 + 288;      // 32
    float* s_w2 = s_b1 + 32;       // 4608
    float* s_b2 = s_w2 + 4608;     // 16
    float* s_c1 = s_b2 + 16;       // 8192 (CONV_CH channels of 32x32)
    float* s_c2 = s_c1 + CONV_CH * 1024; // 4096
    int tid = threadIdx.x;
    int b = blockIdx.x;
    const float* in = obs + (size_t)b * 4096;
    for (int i = tid; i < 1024; i += 256) ((float4*)s_in)[i] = ((const float4*)in)[i];
    for (int i = tid; i < 288; i += 256) s_w1[i] = w1[i];
    for (int i = tid; i < 32; i += 256) s_b1[i] = b1[i];
    for (int i = tid; i < 4608; i += 256) s_w2[i] = w2[i];
    for (int i = tid; i < 16; i += 256) s_b2[i] = b2[i];

    // conv2 per-thread tile: 4 oc x 2x2 spatial, accumulated across ic chunks
    const int ocg = tid >> 6;
    const int oy0 = ((tid >> 3) & 7) * 2;
    const int ox0 = (tid & 7) * 2;
    float acc2[4][2][2];
    #pragma unroll
    for (int a = 0; a < 4; a++)
        #pragma unroll
        for (int sy = 0; sy < 2; sy++)
            #pragma unroll
            for (int sx = 0; sx < 2; sx++) acc2[a][sy][sx] = 0.f;
    const int iy0b = oy0 * 2 - 1, ix0b = ox0 * 2 - 1;

    // conv1 per-thread 2x2 spatial tile coords (uniform oc per iteration)
    const int c1y = ((tid >> 4) & 15) * 2;   // output y base (0..30)
    const int c1x = (tid & 15) * 2;          // output x base (0..30)
    const int c1iy0 = c1y * 2 - 1;
    const int c1ix0 = c1x * 2 - 1;

    for (int cc = 0; cc < 32 / CONV_CH; cc++) {
        __syncthreads();
        // conv1: (1,64,64) -> chunk of CONV_CH channels of (32,32), stride 2, pad 1, relu
        // each iteration: one oc (uniform across block), thread computes 2x2 outputs
        #pragma unroll
        for (int it = 0; it < CONV_CH; it++) {
            int oc = cc * CONV_CH + it;
            float wv[9];
            #pragma unroll
            for (int q = 0; q < 9; q++) wv[q] = s_w1[oc * 9 + q];   // broadcast
            float bb = s_b1[oc];
            float inp[5][5];
            #pragma unroll
            for (int r = 0; r < 5; r++) {
                int iy = c1iy0 + r;
                bool okr = (unsigned)iy < 64u;
                #pragma unroll
                for (int q = 0; q < 5; q++) {
                    int ix = c1ix0 + q;
                    inp[r][q] = (okr && (unsigned)ix < 64u) ? s_in[iy * 64 + ix] : 0.f;
                }
            }
            #pragma unroll
            for (int sy = 0; sy < 2; sy++)
                #pragma unroll
                for (int sx = 0; sx < 2; sx++) {
                    float acc = bb;
                    #pragma unroll
                    for (int dy = 0; dy < 3; dy++)
                        #pragma unroll
                        for (int dx = 0; dx < 3; dx++)
                            acc += wv[dy * 3 + dx] * inp[sy * 2 + dy][sx * 2 + dx];
                    s_c1[it * 1024 + (c1y + sy) * 32 + (c1x + sx)] = fmaxf(acc, 0.f);
                }
        }
        __syncthreads();
        // conv2 accumulate over this ic chunk
        #pragma unroll
        for (int icl = 0; icl < CONV_CH; icl++) {
            int ic = cc * CONV_CH + icl;
            float inp[5][5];
            #pragma unroll
            for (int r = 0; r < 5; r++) {
                int iy = iy0b + r;
                bool okr = (unsigned)iy < 32u;
                #pragma unroll
                for (int q = 0; q < 5; q++) {
                    int ix = ix0b + q;
                    inp[r][q] = (okr && (unsigned)ix < 32u) ? s_c1[icl * 1024 + iy * 32 + ix] : 0.f;
                }
            }
            #pragma unroll
            for (int o4 = 0; o4 < 4; o4++) {
                const float* w = s_w2 + ((ocg * 4 + o4) * 32 + ic) * 9;
                float wv[9];
                #pragma unroll
                for (int q = 0; q < 9; q++) wv[q] = w[q];
                #pragma unroll
                for (int sy = 0; sy < 2; sy++)
                    #pragma unroll
                    for (int sx = 0; sx < 2; sx++)
                        #pragma unroll
                        for (int dy = 0; dy < 3; dy++)
                            #pragma unroll
                            for (int dx = 0; dx < 3; dx++)
                                acc2[o4][sy][sx] += wv[dy * 3 + dx] * inp[sy * 2 + dy][sx * 2 + dx];
            }
        }
    }
    // conv2 writeback with bias+relu
    #pragma unroll
    for (int o4 = 0; o4 < 4; o4++) {
        float bb = s_b2[ocg * 4 + o4];
        #pragma unroll
        for (int sy = 0; sy < 2; sy++)
            #pragma unroll
            for (int sx = 0; sx < 2; sx++)
                s_c2[(ocg * 4 + o4) * 256 + (oy0 + sy) * 16 + (ox0 + sx)] = fmaxf(acc2[o4][sy][sx] + bb, 0.f);
    }
    __syncthreads();
    // avg pool 3x3 stride 3 VALID -> (16,5,5) -> 400
    for (int o = tid; o < 400; o += 256) {
        int c = o / 25;
        int rem = o - c * 25;
        int py = rem / 5, px = rem - (rem / 5) * 5;
        float s = 0.f;
        #pragma unroll
        for (int dy = 0; dy < 3; dy++)
            #pragma unroll
            for (int dx = 0; dx < 3; dx++)
                s += s_c2[c * 256 + (py * 3 + dy) * 16 + (px * 3 + dx)];
        obs_emb[(size_t)b * OBS_D + o] = s * (1.f / 9.f);
    }
}

// ---------------- xpre = obs_emb @ W0T + (b_ih+b_hh) : [B,400]x[400,1024] (R1 core) ----------------
__global__ void __launch_bounds__(256) gemm_xpre_kernel(
    const float* __restrict__ A, const float* __restrict__ W0T,
    const float* __restrict__ bias, float* __restrict__ out) {
    __shared__ float As[16 * 64];
    __shared__ float Ws[16 * 128];
    int tid = threadIdx.x;
    int tx = tid & 31, ty = tid >> 5;
    int row0 = blockIdx.y * 64;
    int jb = blockIdx.x * 128;
    int a_r = tid >> 2, a_k = (tid & 3) * 4;
    float4 acc[8];
    #pragma unroll
    for (int r = 0; r < 8; r++) acc[r] = make_float4(0.f, 0.f, 0.f, 0.f);
    for (int k0 = 0; k0 < 400; k0 += 16) {
        float4 av = *(const float4*)&A[(size_t)(row0 + a_r) * OBS_D + k0 + a_k];
        As[(a_k + 0) * 64 + a_r] = av.x;
        As[(a_k + 1) * 64 + a_r] = av.y;
        As[(a_k + 2) * 64 + a_r] = av.z;
        As[(a_k + 3) * 64 + a_r] = av.w;
        #pragma unroll
        for (int q = 0; q < 2; q++) {
            int idx = tid + 256 * q;
            int kk = idx >> 5, c4 = (idx & 31) * 4;
            *(float4*)&Ws[kk * 128 + c4] = *(const float4*)&W0T[(size_t)(k0 + kk) * 1024 + jb + c4];
        }
        __syncthreads();
        #pragma unroll
        for (int kk = 0; kk < 16; kk++) {
            float4 w = *(float4*)&Ws[kk * 128 + tx * 4];
            float4 a0 = *(float4*)&As[kk * 64 + ty * 8];
            float4 a1 = *(float4*)&As[kk * 64 + ty * 8 + 4];
            FMA4(acc[0], a0.x, w); FMA4(acc[1], a0.y, w); FMA4(acc[2], a0.z, w); FMA4(acc[3], a0.w, w);
            FMA4(acc[4], a1.x, w); FMA4(acc[5], a1.y, w); FMA4(acc[6], a1.z, w); FMA4(acc[7], a1.w, w);
        }
        __syncthreads();
    }
    float4 bv = *(const float4*)&bias[jb + tx * 4];
    #pragma unroll
    for (int r = 0; r < 8; r++) {
        size_t b = row0 + ty * 8 + r;
        float4 o = acc[r];
        o.x += bv.x; o.y += bv.y; o.z += bv.z; o.w += bv.w;
        *(float4*)&out[b * 1024 + jb + tx * 4] = o;
    }
}

// ---------------- LSTM step (R1 core, branch-paired via blockIdx.z) ----------------
#define STEP_TILE() \
    __syncthreads(); \
    _Pragma("unroll") \
    for (int kk = 0; kk < 16; kk++) { \
        float4 a = *(float4*)&As[kk * 64 + ty4]; \
        _Pragma("unroll") \
        for (int gt = 0; gt < 4; gt++) { \
            float4 w = *(float4*)&Ws[(gt * 16 + kk) * 64 + tx4]; \
            FMA4(acc[gt][0], a.x, w); \
            FMA4(acc[gt][1], a.y, w); \
            FMA4(acc[gt][2], a.z, w); \
            FMA4(acc[gt][3], a.w, w); \
        } \
    } \
    __syncthreads();

__global__ void __launch_bounds__(256) lstm_step_kernel(
    const float* __restrict__ xpre,
    const float* __restrict__ WhhT, const float* __restrict__ WextT,
    const float* __restrict__ addr_emb,
    const float* h_inA, const float* c_inA, const float* sampA, int aidA, float* h_outA, float* c_outA,
    const float* h_inB, const float* c_inB, const float* sampB, int aidB, float* h_outB, float* c_outB) {
    __shared__ float As[16 * 64];
    __shared__ float Ws[4 * 16 * 64];
    const float* h_in; const float* c_in; const float* samp; int aid; float* h_out; float* c_out;
    if (blockIdx.z == 0) { h_in = h_inA; c_in = c_inA; samp = sampA; aid = aidA; h_out = h_outA; c_out = c_outA; }
    else                 { h_in = h_inB; c_in = c_inB; samp = sampB; aid = aidB; h_out = h_outB; c_out = c_outB; }
    const int tid = threadIdx.x;
    const int tx4 = (tid & 15) * 4;
    const int ty4 = (tid >> 4) * 4;
    const int row0 = blockIdx.y * 64;
    const int j0 = blockIdx.x * 64;
    const int a_r = tid >> 2;
    const int a_k = (tid & 3) * 4;
    float4 acc[4][4];
    #pragma unroll
    for (int gt = 0; gt < 4; gt++)
        #pragma unroll
        for (int r = 0; r < 4; r++) acc[gt][r] = make_float4(0.f, 0.f, 0.f, 0.f);

    if (h_in) {
        for (int k0 = 0; k0 < 256; k0 += 16) {
            float4 av = *(const float4*)&h_in[(size_t)(row0 + a_r) * 256 + k0 + a_k];
            As[(a_k + 0) * 64 + a_r] = av.x;
            As[(a_k + 1) * 64 + a_r] = av.y;
            As[(a_k + 2) * 64 + a_r] = av.z;
            As[(a_k + 3) * 64 + a_r] = av.w;
            #pragma unroll
            for (int q = 0; q < 4; q++) {
                int idx = tid + 256 * q;
                int kk = (idx >> 4) & 15;
                int gt = idx >> 8;
                int c4 = (idx & 15) * 4;
                *(float4*)&Ws[(idx >> 4) * 64 + c4] = *(const float4*)&WhhT[(size_t)(k0 + kk) * 1024 + gt * 256 + j0 + c4];
            }
            STEP_TILE()
        }
    }
    if (samp) {
        float4 av = *(const float4*)&samp[(size_t)(row0 + a_r) * 16 + a_k];
        As[(a_k + 0) * 64 + a_r] = av.x;
        As[(a_k + 1) * 64 + a_r] = av.y;
        As[(a_k + 2) * 64 + a_r] = av.z;
        As[(a_k + 3) * 64 + a_r] = av.w;
        #pragma unroll
        for (int q = 0; q < 4; q++) {
            int idx = tid + 256 * q;
            int kk = (idx >> 4) & 15;
            int gt = idx >> 8;
            int c4 = (idx & 15) * 4;
            *(float4*)&Ws[(idx >> 4) * 64 + c4] = *(const float4*)&WextT[(size_t)kk * 1024 + gt * 256 + j0 + c4];
        }
        STEP_TILE()
    }
    {
        float4 av = *(const float4*)&addr_emb[aid * 16 + a_k];
        As[(a_k + 0) * 64 + a_r] = av.x;
        As[(a_k + 1) * 64 + a_r] = av.y;
        As[(a_k + 2) * 64 + a_r] = av.z;
        As[(a_k + 3) * 64 + a_r] = av.w;
        #pragma unroll
        for (int q = 0; q < 4; q++) {
            int idx = tid + 256 * q;
            int kk = (idx >> 4) & 15;
            int gt = idx >> 8;
            int c4 = (idx & 15) * 4;
            *(float4*)&Ws[(idx >> 4) * 64 + c4] = *(const float4*)&WextT[(size_t)(16 + kk) * 1024 + gt * 256 + j0 + c4];
        }
        STEP_TILE()
    }
    // fused gate epilogue
    #pragma unroll
    for (int r = 0; r < 4; r++) {
        size_t b = row0 + ty4 + r;
        float4 xi = *(const float4*)&xpre[b * 1024 + 0   + j0 + tx4];
        float4 xf = *(const float4*)&xpre[b * 1024 + 256 + j0 + tx4];
        float4 xg = *(const float4*)&xpre[b * 1024 + 512 + j0 + tx4];
        float4 xo = *(const float4*)&xpre[b * 1024 + 768 + j0 + tx4];
        float4 cold = make_float4(0.f, 0.f, 0.f, 0.f);
        if (c_in) cold = *(const float4*)&c_in[b * 256 + j0 + tx4];
        float4 hv, cv;
        #define GATE(comp) { \
            float iv = acc[0][r].comp + xi.comp; \
            float fv = acc[1][r].comp + xf.comp; \
            float gv = acc[2][r].comp + xg.comp; \
            float ov = acc[3][r].comp + xo.comp; \
            float cn = sigf(fv) * cold.comp + sigf(iv) * tanh_fast(gv); \
            cv.comp = cn; \
            hv.comp = sigf(ov) * tanh_fast(cn); }
        GATE(x) GATE(y) GATE(z) GATE(w)
        #undef GATE
        *(float4*)&h_out[b * 256 + j0 + tx4] = hv;
        *(float4*)&c_out[b * 256 + j0 + tx4] = cv;
    }
}

// ---------------- heads ----------------
__device__ __forceinline__ float warp_dot256(const float* __restrict__ h, const float* __restrict__ w, int lane) {
    const float* hp = h + lane * 8;
    const float* wp = w + lane * 8;
    float4 a0 = *(const float4*)hp;
    float4 a1 = *(const float4*)(hp + 4);
    float4 b0 = *(const float4*)wp;
    float4 b1 = *(const float4*)(wp + 4);
    float s = a0.x * b0.x + a0.y * b0.y + a0.z * b0.z + a0.w * b0.w
            + a1.x * b1.x + a1.y * b1.y + a1.z * b1.z + a1.w * b1.w;
    #pragma unroll
    for (int off = 16; off; off >>= 1) s += __shfl_down_sync(0xffffffffu, s, off);
    return s;  // valid on lane 0
}

// rp0 head (mid-graph dependency): cols 11,12 + save rp0
__global__ void head_rp_kernel(const float* __restrict__ h, const float* __restrict__ W,
                               const float* __restrict__ bias, const float* __restrict__ eps,
                               int col0, float* __restrict__ out, float* __restrict__ save) {
    int gw = (blockIdx.x * blockDim.x + threadIdx.x) >> 5;
    int lane = threadIdx.x & 31;
    if (gw >= B_N) return;
    const float* hp = h + (size_t)gw * 256;
    float d[4];
    #pragma unroll
    for (int o = 0; o < 4; o++) d[o] = warp_dot256(hp, W + o * 256, lane);
    if (lane == 0) {
        float r0 = d[0] + bias[0] + __expf(d[2] + bias[2]) * eps[(size_t)gw * 2 + 0];
        float r1 = d[1] + bias[1] + __expf(d[3] + bias[3]) * eps[(size_t)gw * 2 + 1];
        out[(size_t)gw * 15 + col0 + 0] = r0;
        out[(size_t)gw * 15 + col0 + 1] = r1;
        if (save) { save[(size_t)gw * 2 + 0] = r0; save[(size_t)gw * 2 + 1] = r1; }
    }
}

// all remaining heads in one kernel at the end
__global__ void final_heads_kernel(
    const float* __restrict__ h0, const float* __restrict__ h1, const float* __restrict__ h2,
    const float* __restrict__ h1b, const float* __restrict__ h2b, const float* __restrict__ h4b,
    const float* __restrict__ pid_w, const float* __restrict__ pid_b,
    const float* __restrict__ sid_w, const float* __restrict__ sid_b,
    const float* __restrict__ rp_w, const float* __restrict__ rp_b,
    const float* __restrict__ eps_rp, const float* __restrict__ eps_rp1,
    float* __restrict__ out) {
    int gw = (blockIdx.x * blockDim.x + threadIdx.x) >> 5;
    int lane = threadIdx.x & 31;
    if (gw >= B_N) return;
    size_t off = (size_t)gw * 256;
    float* o = out + (size_t)gw * 15;
    // pid logits from h0 -> cols 0..2
    for (int q = 0; q < 3; q++) {
        float s = warp_dot256(h0 + off, pid_w + q * 256, lane);
        if (lane == 0) o[q] = s + pid_b[q];
    }
    // sid logits from h1 -> cols 3..4
    for (int q = 0; q < 2; q++) {
        float s = warp_dot256(h1 + off, sid_w + q * 256, lane);
        if (lane == 0) o[3 + q] = s + sid_b[q];
    }
    // rp_b0 from h2 + eps_rp -> cols 5..6
    {
        float d[4];
        #pragma unroll
        for (int q = 0; q < 4; q++) d[q] = warp_dot256(h2 + off, rp_w + q * 256, lane);
        if (lane == 0) {
            o[5] = d[0] + rp_b[0] + __expf(d[2] + rp_b[2]) * eps_rp[(size_t)gw * 2 + 0];
            o[6] = d[1] + rp_b[1] + __expf(d[3] + rp_b[3]) * eps_rp[(size_t)gw * 2 + 1];
        }
    }
    // sid0 from h1b -> cols 7..8
    for (int q = 0; q < 2; q++) {
        float s = warp_dot256(h1b + off, sid_w + q * 256, lane);
        if (lane == 0) o[7 + q] = s + sid_b[q];
    }
    // sid1 from h2b -> cols 9..10
    for (int q = 0; q < 2; q++) {
        float s = warp_dot256(h2b + off, sid_w + q * 256, lane);
        if (lane == 0) o[9 + q] = s + sid_b[q];
    }
    // rp1 from h4b + eps_rp1 -> cols 13..14
    {
        float d[4];
        #pragma unroll
        for (int q = 0; q < 4; q++) d[q] = warp_dot256(h4b + off, rp_w + q * 256, lane);
        if (lane == 0) {
            o[13] = d[0] + rp_b[0] + __expf(d[2] + rp_b[2]) * eps_rp1[(size_t)gw * 2 + 0];
            o[14] = d[1] + rp_b[1] + __expf(d[3] + rp_b[3]) * eps_rp1[(size_t)gw * 2 + 1];
        }
    }
}

// ---------------- MLP: rp0(2) -> 100 -> 100 -> 16 ----------------
__global__ void mlp1_kernel(const float* __restrict__ rp0, const float* __restrict__ w1,
                            const float* __restrict__ b1, float* __restrict__ z1) {
    int i = blockIdx.x * blockDim.x + threadIdx.x;
    if (i >= B_N * 100) return;
    int b = i / 100, j = i - b * 100;
    float v = rp0[b * 2] * w1[j * 2] + rp0[b * 2 + 1] * w1[j * 2 + 1] + b1[j];
    z1[i] = tanh_fast(v);
}

__global__ void __launch_bounds__(128) mlp2_kernel(const float* __restrict__ z1, const float* __restrict__ w2,
                                                   const float* __restrict__ b2, float* __restrict__ z2) {
    __shared__ float w2s[100 * 101];
    __shared__ float z1s[8 * 100];
    __shared__ float b2s[100];
    int tid = threadIdx.x;
    int b0 = blockIdx.x * 8;
    for (int i = tid; i < 100 * 100; i += 128) { int j = i / 100, k = i - j * 100; w2s[j * 101 + k] = w2[i]; }
    for (int i = tid; i < 800; i += 128) z1s[i] = z1[(size_t)b0 * 100 + i];
    for (int i = tid; i < 100; i += 128) b2s[i] = b2[i];
    __syncthreads();
    for (int t = tid; t < 800; t += 128) {
        int r = t / 100, j = t - r * 100;
        float s = b2s[j];
        const float* zz = z1s + r * 100;
        const float* ww = w2s + j * 101;
        #pragma unroll 4
        for (int k = 0; k < 100; k++) s += zz[k] * ww[k];
        z2[(size_t)(b0 + r) * 100 + j] = tanh_fast(s);
    }
}

__global__ void mlp3_kernel(const float* __restrict__ z2, const float* __restrict__ w3,
                            const float* __restrict__ b3, float* __restrict__ remb) {
    int i = blockIdx.x * blockDim.x + threadIdx.x;
    if (i >= B_N * 16) return;
    int b = i >> 4, o = i & 15;
    float s = b3[o];
    const float* zz = z2 + (size_t)b * 100;
    const float* ww = w3 + o * 100;
    #pragma unroll 4
    for (int k = 0; k < 100; k++) s += zz[k] * ww[k];
    remb[i] = s;
}

// ---------------- host ----------------
static float* getsym(const void* symbol) {
    void* p = nullptr;
    cudaGetSymbolAddress(&p, symbol);
    return (float*)p;
}

extern "C" void kernel_launch(void* const* d_in, const int* in_sizes, int n_in,
                              void* d_out, int out_size) {
    const float* obs        = (const float*)d_in[0];
    const int*   program_id = (const int*)  d_in[1];
    const int*   shape_id   = (const int*)  d_in[2];
    const int*   shape_id_0 = (const int*)  d_in[3];
    const int*   shape_id_1 = (const int*)  d_in[4];
    const float* eps_rp     = (const float*)d_in[5];
    const float* eps_rp0    = (const float*)d_in[6];
    const float* eps_rp1    = (const float*)d_in[7];
    const float* conv1_w    = (const float*)d_in[8];
    const float* conv1_b    = (const float*)d_in[9];
    const float* conv2_w    = (const float*)d_in[10];
    const float* conv2_b    = (const float*)d_in[11];
    const float* mlp_w1     = (const float*)d_in[12];
    const float* mlp_b1     = (const float*)d_in[13];
    const float* mlp_w2     = (const float*)d_in[14];
    const float* mlp_b2     = (const float*)d_in[15];
    const float* mlp_w3     = (const float*)d_in[16];
    const float* mlp_b3     = (const float*)d_in[17];
    const float* W_ih       = (const float*)d_in[18];
    const float* b_ih       = (const float*)d_in[19];
    const float* W_hh       = (const float*)d_in[20];
    const float* b_hh       = (const float*)d_in[21];
    const float* addr_emb   = (const float*)d_in[22];
    const float* pid_emb    = (const float*)d_in[23];
    const float* sid_emb    = (const float*)d_in[24];
    const float* pid_ext_w  = (const float*)d_in[25];
    const float* pid_ext_b  = (const float*)d_in[26];
    const float* sid_ext_w  = (const float*)d_in[27];
    const float* sid_ext_b  = (const float*)d_in[28];
    const float* rp_ext_w   = (const float*)d_in[29];
    const float* rp_ext_b   = (const float*)d_in[30];
    float* out = (float*)d_out;

    float* st      = getsym(g_state);
    const int SZ   = B_N * HID;
    float* h0  = st + 0 * SZ;  float* c0  = st + 1 * SZ;
    float* h1  = st + 2 * SZ;  float* c1  = st + 3 * SZ;
    float* h1b = st + 4 * SZ;  float* c1b = st + 5 * SZ;
    float* h2  = st + 6 * SZ;  float* c2  = st + 7 * SZ;
    float* h2b = st + 8 * SZ;  float* c2b = st + 9 * SZ;
    float* h3b = st + 10 * SZ; float* c3b = st + 11 * SZ;
    float* h4b = st + 12 * SZ; float* c4b = st + 13 * SZ;

    float* samp   = getsym(g_samp);
    float* s_pid  = samp + 0 * B_N * 16;
    float* s_sid  = samp + 1 * B_N * 16;
    float* s_sid0 = samp + 2 * B_N * 16;
    float* s_sid1 = samp + 3 * B_N * 16;

    float* obs_e  = getsym(g_obs_emb);
    float* xpre   = getsym(g_xpre);
    float* WhhT   = getsym(g_WhhT);
    float* W0T    = getsym(g_W0T);
    float* WextT  = getsym(g_WextT);
    float* bias   = getsym(g_bias);
    float* rp0    = getsym(g_rp0);
    float* z1     = getsym(g_z1);
    float* z2     = getsym(g_z2);
    float* rp0emb = getsym(g_rp0emb);

    const int CONV_SMEM = (4096 + 288 + 32 + 4608 + 16 + CONV_CH * 1024 + 4096) * 4;
    cudaFuncSetAttribute(conv_fused_kernel, cudaFuncAttributeMaxDynamicSharedMemorySize, CONV_SMEM);

    prep_weights_kernel<<<512, 256>>>(W_ih, b_ih, W_hh, b_hh, WhhT, W0T, WextT, bias);
    gather_kernel<<<B_N * 16 / 256, 256>>>(program_id, shape_id, shape_id_0, shape_id_1,
                                           pid_emb, sid_emb, s_pid, s_sid, s_sid0, s_sid1);
    conv_fused_kernel<<<B_N, 256, CONV_SMEM>>>(obs, conv1_w, conv1_b, conv2_w, conv2_b, obs_e);
    gemm_xpre_kernel<<<dim3(8, B_N / 64), 256>>>(obs_e, W0T, bias, xpre);

    dim3 g1(4, B_N / 64, 1);
    dim3 g2(4, B_N / 64, 2);
    // step0: h=c=0, samp=0, aid=0
    lstm_step_kernel<<<g1, 256>>>(xpre, WhhT, WextT, addr_emb,
        nullptr, nullptr, nullptr, 0, h0, c0,
        nullptr, nullptr, nullptr, 0, nullptr, nullptr);
    // pair: step1A (aid=1) + step1B (aid=2), both from (h0,c0,s_pid)
    lstm_step_kernel<<<g2, 256>>>(xpre, WhhT, WextT, addr_emb,
        h0, c0, s_pid, 1, h1, c1,
        h0, c0, s_pid, 2, h1b, c1b);
    // pair: step2A (h1,s_sid,aid=4) + step2B (h1b,s_sid0,aid=3)
    lstm_step_kernel<<<g2, 256>>>(xpre, WhhT, WextT, addr_emb,
        h1, c1, s_sid, 4, h2, c2,
        h1b, c1b, s_sid0, 3, h2b, c2b);
    // step3B
    lstm_step_kernel<<<g1, 256>>>(xpre, WhhT, WextT, addr_emb,
        h2b, c2b, s_sid1, 5, h3b, c3b,
        nullptr, nullptr, nullptr, 0, nullptr, nullptr);
    head_rp_kernel<<<B_N / 8, 256>>>(h3b, rp_ext_w, rp_ext_b, eps_rp0, 11, out, rp0);
    // MLP on rp0
    mlp1_kernel<<<(B_N * 100 + 255) / 256, 256>>>(rp0, mlp_w1, mlp_b1, z1);
    mlp2_kernel<<<B_N / 8, 128>>>(z1, mlp_w2, mlp_b2, z2);
    mlp3_kernel<<<B_N * 16 / 256, 256>>>(z2, mlp_w3, mlp_b3, rp0emb);
    // step4B
    lstm_step_kernel<<<g1, 256>>>(xpre, WhhT, WextT, addr_emb,
        h3b, c3b, rp0emb, 6, h4b, c4b,
        nullptr, nullptr, nullptr, 0, nullptr, nullptr);
    // all remaining heads
    final_heads_kernel<<<B_N / 8, 256>>>(h0, h1, h2, h1b, h2b, h4b,
        pid_ext_w, pid_ext_b, sid_ext_w, sid_ext_b, rp_ext_w, rp_ext_b,
        eps_rp, eps_rp1, out);
}

// round 5
// speedup vs baseline: 2.0325x; 1.0233x over previous
#include <cuda_runtime.h>
#include <cstddef>
#include <cstdint>

#define B_N 4096
#define HID 256
#define OBS_D 400
#define IN_D 432

// ---------------- scratch (device globals; no allocation allowed) ----------------
__device__ float g_state[14 * B_N * HID];
__device__ float g_samp[4 * B_N * 16];      // prev_pid, samp_sid, samp_sid0, samp_sid1
__device__ float g_obs_emb[B_N * OBS_D];
__device__ float g_xpre[B_N * 1024];
__device__ float g_WhhT[256 * 1024];
__device__ float g_W0T[400 * 1024];
__device__ float g_WextT[32 * 1024];        // rows 0..15: samp cols of W_ih; 16..31: addr cols
__device__ float g_bias[1024];              // b_ih + b_hh
__device__ float g_rp0[B_N * 2];
__device__ float g_z1[B_N * 100];
__device__ float g_z2[B_N * 100];
__device__ float g_rp0emb[B_N * 16];

__device__ __forceinline__ float sigf(float x) { return 1.f / (1.f + __expf(-x)); }
__device__ __forceinline__ float tanh_fast(float x) { return 2.f / (1.f + __expf(-2.f * x)) - 1.f; }

__device__ __forceinline__ uint32_t f2tf32(float x) {
    uint32_t r;
    asm("cvt.rna.tf32.f32 %0, %1;" : "=r"(r) : "f"(x));
    return r;
}

#define MMA_TF32(c, a, b) \
    asm volatile("mma.sync.aligned.m16n8k8.row.col.f32.tf32.tf32.f32 " \
        "{%0,%1,%2,%3}, {%4,%5,%6,%7}, {%8,%9}, {%0,%1,%2,%3};" \
        : "+f"((c)[0]), "+f"((c)[1]), "+f"((c)[2]), "+f"((c)[3]) \
        : "r"((a)[0]), "r"((a)[1]), "r"((a)[2]), "r"((a)[3]), "r"((b)[0]), "r"((b)[1]))

#define FMA4(A_, s_, W_) { (A_).x += (s_)*(W_).x; (A_).y += (s_)*(W_).y; (A_).z += (s_)*(W_).z; (A_).w += (s_)*(W_).w; }

// ---------------- weight prep: transposes for coalesced GEMM loads ----------------
__global__ void prep_weights_kernel(const float* __restrict__ W_ih, const float* __restrict__ b_ih,
                                    const float* __restrict__ W_hh, const float* __restrict__ b_hh,
                                    float* __restrict__ WhhT, float* __restrict__ W0T,
                                    float* __restrict__ WextT, float* __restrict__ bias) {
    int idx = blockIdx.x * blockDim.x + threadIdx.x;
    int stride = gridDim.x * blockDim.x;
    for (int i = idx; i < 256 * 1024; i += stride) { int k = i >> 10, j = i & 1023; WhhT[i] = W_hh[(size_t)j * 256 + k]; }
    for (int i = idx; i < 400 * 1024; i += stride) { int k = i >> 10, j = i & 1023; W0T[i] = W_ih[(size_t)j * IN_D + k]; }
    for (int i = idx; i < 32 * 1024;  i += stride) { int k = i >> 10, j = i & 1023; WextT[i] = W_ih[(size_t)j * IN_D + 400 + k]; }
    for (int i = idx; i < 1024; i += stride) bias[i] = b_ih[i] + b_hh[i];
}

// ---------------- embedding gathers ----------------
__global__ void gather_kernel(const int* __restrict__ pid, const int* __restrict__ sid,
                              const int* __restrict__ sid0, const int* __restrict__ sid1,
                              const float* __restrict__ pid_emb, const float* __restrict__ sid_emb,
                              float* __restrict__ s_pid, float* __restrict__ s_sid,
                              float* __restrict__ s_sid0, float* __restrict__ s_sid1) {
    int i = blockIdx.x * blockDim.x + threadIdx.x;
    if (i >= B_N * 16) return;
    int b = i >> 4, k = i & 15;
    s_pid[i]  = pid_emb[pid[b]  * 16 + k];
    s_sid[i]  = sid_emb[sid[b]  * 16 + k];
    s_sid0[i] = sid_emb[sid0[b] * 16 + k];
    s_sid1[i] = sid_emb[sid1[b] * 16 + k];
}

// ---------------- fused conv1+conv2+pool, ic-chunked, 2 blocks/SM (unchanged R3/R4) ----------------
#define CONV_CH 8
__global__ void __launch_bounds__(256, 2) conv_fused_kernel(
    const float* __restrict__ obs, const float* __restrict__ w1, const float* __restrict__ b1,
    const float* __restrict__ w2, const float* __restrict__ b2, float* __restrict__ obs_emb) {
    extern __shared__ float sm[];
    float* s_in = sm;              // 4096
    float* s_w1 = s_in + 4096;     // 288
    float* s_b1 = s_w1 + 288;      // 32
    float* s_w2 = s_b1 + 32;       // 4608
    float* s_b2 = s_w2 + 4608;     // 16
    float* s_c1 = s_b2 + 16;       // CONV_CH*1024
    float* s_c2 = s_c1 + CONV_CH * 1024; // 4096
    int tid = threadIdx.x;
    int b = blockIdx.x;
    const float* in = obs + (size_t)b * 4096;
    for (int i = tid; i < 1024; i += 256) ((float4*)s_in)[i] = ((const float4*)in)[i];
    for (int i = tid; i < 288; i += 256) s_w1[i] = w1[i];
    for (int i = tid; i < 32; i += 256) s_b1[i] = b1[i];
    for (int i = tid; i < 4608; i += 256) s_w2[i] = w2[i];
    for (int i = tid; i < 16; i += 256) s_b2[i] = b2[i];

    const int ocg = tid >> 6;
    const int oy0 = ((tid >> 3) & 7) * 2;
    const int ox0 = (tid & 7) * 2;
    float acc2[4][2][2];
    #pragma unroll
    for (int a = 0; a < 4; a++)
        #pragma unroll
        for (int sy = 0; sy < 2; sy++)
            #pragma unroll
            for (int sx = 0; sx < 2; sx++) acc2[a][sy][sx] = 0.f;
    const int iy0b = oy0 * 2 - 1, ix0b = ox0 * 2 - 1;

    const int c1y = ((tid >> 4) & 15) * 2;
    const int c1x = (tid & 15) * 2;
    const int c1iy0 = c1y * 2 - 1;
    const int c1ix0 = c1x * 2 - 1;

    for (int cc = 0; cc < 32 / CONV_CH; cc++) {
        __syncthreads();
        #pragma unroll
        for (int it = 0; it < CONV_CH; it++) {
            int oc = cc * CONV_CH + it;
            float wv[9];
            #pragma unroll
            for (int q = 0; q < 9; q++) wv[q] = s_w1[oc * 9 + q];
            float bb = s_b1[oc];
            float inp[5][5];
            #pragma unroll
            for (int r = 0; r < 5; r++) {
                int iy = c1iy0 + r;
                bool okr = (unsigned)iy < 64u;
                #pragma unroll
                for (int q = 0; q < 5; q++) {
                    int ix = c1ix0 + q;
                    inp[r][q] = (okr && (unsigned)ix < 64u) ? s_in[iy * 64 + ix] : 0.f;
                }
            }
            #pragma unroll
            for (int sy = 0; sy < 2; sy++)
                #pragma unroll
                for (int sx = 0; sx < 2; sx++) {
                    float acc = bb;
                    #pragma unroll
                    for (int dy = 0; dy < 3; dy++)
                        #pragma unroll
                        for (int dx = 0; dx < 3; dx++)
                            acc += wv[dy * 3 + dx] * inp[sy * 2 + dy][sx * 2 + dx];
                    s_c1[it * 1024 + (c1y + sy) * 32 + (c1x + sx)] = fmaxf(acc, 0.f);
                }
        }
        __syncthreads();
        #pragma unroll
        for (int icl = 0; icl < CONV_CH; icl++) {
            int ic = cc * CONV_CH + icl;
            float inp[5][5];
            #pragma unroll
            for (int r = 0; r < 5; r++) {
                int iy = iy0b + r;
                bool okr = (unsigned)iy < 32u;
                #pragma unroll
                for (int q = 0; q < 5; q++) {
                    int ix = ix0b + q;
                    inp[r][q] = (okr && (unsigned)ix < 32u) ? s_c1[icl * 1024 + iy * 32 + ix] : 0.f;
                }
            }
            #pragma unroll
            for (int o4 = 0; o4 < 4; o4++) {
                const float* w = s_w2 + ((ocg * 4 + o4) * 32 + ic) * 9;
                float wv[9];
                #pragma unroll
                for (int q = 0; q < 9; q++) wv[q] = w[q];
                #pragma unroll
                for (int sy = 0; sy < 2; sy++)
                    #pragma unroll
                    for (int sx = 0; sx < 2; sx++)
                        #pragma unroll
                        for (int dy = 0; dy < 3; dy++)
                            #pragma unroll
                            for (int dx = 0; dx < 3; dx++)
                                acc2[o4][sy][sx] += wv[dy * 3 + dx] * inp[sy * 2 + dy][sx * 2 + dx];
            }
        }
    }
    #pragma unroll
    for (int o4 = 0; o4 < 4; o4++) {
        float bb = s_b2[ocg * 4 + o4];
        #pragma unroll
        for (int sy = 0; sy < 2; sy++)
            #pragma unroll
            for (int sx = 0; sx < 2; sx++)
                s_c2[(ocg * 4 + o4) * 256 + (oy0 + sy) * 16 + (ox0 + sx)] = fmaxf(acc2[o4][sy][sx] + bb, 0.f);
    }
    __syncthreads();
    for (int o = tid; o < 400; o += 256) {
        int c = o / 25;
        int rem = o - c * 25;
        int py = rem / 5, px = rem - (rem / 5) * 5;
        float s = 0.f;
        #pragma unroll
        for (int dy = 0; dy < 3; dy++)
            #pragma unroll
            for (int dx = 0; dx < 3; dx++)
                s += s_c2[c * 256 + (py * 3 + dy) * 16 + (px * 3 + dx)];
        obs_emb[(size_t)b * OBS_D + o] = s * (1.f / 9.f);
    }
}

// ---------------- xpre = obs_emb @ W0T + (b_ih+b_hh) (unchanged R1 core) ----------------
__global__ void __launch_bounds__(256) gemm_xpre_kernel(
    const float* __restrict__ A, const float* __restrict__ W0T,
    const float* __restrict__ bias, float* __restrict__ out) {
    __shared__ float As[16 * 64];
    __shared__ float Ws[16 * 128];
    int tid = threadIdx.x;
    int tx = tid & 31, ty = tid >> 5;
    int row0 = blockIdx.y * 64;
    int jb = blockIdx.x * 128;
    int a_r = tid >> 2, a_k = (tid & 3) * 4;
    float4 acc[8];
    #pragma unroll
    for (int r = 0; r < 8; r++) acc[r] = make_float4(0.f, 0.f, 0.f, 0.f);
    for (int k0 = 0; k0 < 400; k0 += 16) {
        float4 av = *(const float4*)&A[(size_t)(row0 + a_r) * OBS_D + k0 + a_k];
        As[(a_k + 0) * 64 + a_r] = av.x;
        As[(a_k + 1) * 64 + a_r] = av.y;
        As[(a_k + 2) * 64 + a_r] = av.z;
        As[(a_k + 3) * 64 + a_r] = av.w;
        #pragma unroll
        for (int q = 0; q < 2; q++) {
            int idx = tid + 256 * q;
            int kk = idx >> 5, c4 = (idx & 31) * 4;
            *(float4*)&Ws[kk * 128 + c4] = *(const float4*)&W0T[(size_t)(k0 + kk) * 1024 + jb + c4];
        }
        __syncthreads();
        #pragma unroll
        for (int kk = 0; kk < 16; kk++) {
            float4 w = *(float4*)&Ws[kk * 128 + tx * 4];
            float4 a0 = *(float4*)&As[kk * 64 + ty * 8];
            float4 a1 = *(float4*)&As[kk * 64 + ty * 8 + 4];
            FMA4(acc[0], a0.x, w); FMA4(acc[1], a0.y, w); FMA4(acc[2], a0.z, w); FMA4(acc[3], a0.w, w);
            FMA4(acc[4], a1.x, w); FMA4(acc[5], a1.y, w); FMA4(acc[6], a1.z, w); FMA4(acc[7], a1.w, w);
        }
        __syncthreads();
    }
    float4 bv = *(const float4*)&bias[jb + tx * 4];
    #pragma unroll
    for (int r = 0; r < 8; r++) {
        size_t b = row0 + ty * 8 + r;
        float4 o = acc[r];
        o.x += bv.x; o.y += bv.y; o.z += bv.z; o.w += bv.w;
        *(float4*)&out[b * 1024 + jb + tx * 4] = o;
    }
}

// ---------------- tf32 tensor-core LSTM step ----------------
// Block: m32 rows x all 4 gates x 64 units (256 gate-cols). 8 warps:
// warp w -> gate g=w>>1, units u0w=(w&1)*32; warp tile m32n32 = 2x4 mma(m16n8k8).
__device__ __forceinline__ void lstm_tf32_phase(
    const float* __restrict__ A, int astride,
    const float* __restrict__ Bsrc, int nslabs, int u_base,
    uint32_t* __restrict__ sA, uint32_t* __restrict__ sB,
    float acc[2][4][4], int tid, int grp, int tig, int cbase)
{
    const int am = tid >> 3, ak = (tid & 7) * 2;
    const int bkr = tid >> 4, bc0 = (tid & 15) * 16;
    const int bj = ((bc0 >> 6) << 8) + u_base + (bc0 & 63);
    for (int s = 0; s < nslabs; s++) {
        // stage A slab (32 x 16, fp32 -> tf32), row stride 20 (conflict-free)
        float2 av = *(const float2*)&A[(size_t)am * astride + s * 16 + ak];
        uint2 at; at.x = f2tf32(av.x); at.y = f2tf32(av.y);
        *(uint2*)&sA[am * 20 + ak] = at;
        // stage B slab (16 x 256 gate-cols), row stride 264 (conflict-free)
        const float* bp = Bsrc + (size_t)(s * 16 + bkr) * 1024 + bj;
        #pragma unroll
        for (int q = 0; q < 4; q++) {
            float4 v = ((const float4*)bp)[q];
            uint4 u4; u4.x = f2tf32(v.x); u4.y = f2tf32(v.y); u4.z = f2tf32(v.z); u4.w = f2tf32(v.w);
            *(uint4*)&sB[bkr * 264 + bc0 + q * 4] = u4;
        }
        __syncthreads();
        #pragma unroll
        for (int k8 = 0; k8 < 16; k8 += 8) {
            uint32_t a[2][4], b[4][2];
            #pragma unroll
            for (int mi = 0; mi < 2; mi++) {
                int r = mi * 16 + grp;
                a[mi][0] = sA[r * 20 + k8 + tig];
                a[mi][1] = sA[(r + 8) * 20 + k8 + tig];
                a[mi][2] = sA[r * 20 + k8 + tig + 4];
                a[mi][3] = sA[(r + 8) * 20 + k8 + tig + 4];
            }
            #pragma unroll
            for (int ni = 0; ni < 4; ni++) {
                b[ni][0] = sB[(k8 + tig) * 264 + cbase + ni * 8 + grp];
                b[ni][1] = sB[(k8 + tig + 4) * 264 + cbase + ni * 8 + grp];
            }
            #pragma unroll
            for (int mi = 0; mi < 2; mi++)
                #pragma unroll
                for (int ni = 0; ni < 4; ni++)
                    MMA_TF32(acc[mi][ni], a[mi], b[ni]);
        }
        __syncthreads();
    }
}

__global__ void __launch_bounds__(256) lstm_step_tf32_kernel(
    const float* __restrict__ xpre,
    const float* __restrict__ WhhT, const float* __restrict__ WextT,
    const float* __restrict__ addr_emb,
    const float* h_inA, const float* c_inA, const float* sampA, int aidA, float* h_outA, float* c_outA,
    const float* h_inB, const float* c_inB, const float* sampB, int aidB, float* h_outB, float* c_outB) {
    __shared__ __align__(16) unsigned char smraw[33792];
    uint32_t* sA = (uint32_t*)smraw;                 // [32][20]
    uint32_t* sB = (uint32_t*)(smraw + 32 * 20 * 4); // [16][264]
    float* sAcc = (float*)smraw;                     // [4][32][66] (reused after GEMM)

    const float* h_in; const float* c_in; const float* samp; int aid; float* h_out; float* c_out;
    if (blockIdx.z == 0) { h_in = h_inA; c_in = c_inA; samp = sampA; aid = aidA; h_out = h_outA; c_out = c_outA; }
    else                 { h_in = h_inB; c_in = c_inB; samp = sampB; aid = aidB; h_out = h_outB; c_out = c_outB; }

    const int tid = threadIdx.x;
    const int lane = tid & 31, w = tid >> 5;
    const int grp = lane >> 2, tig = lane & 3;
    const int g = w >> 1, u0w = (w & 1) * 32;
    const int cbase = g * 64 + u0w;
    const int u_base = blockIdx.x * 64;
    const int row0 = blockIdx.y * 32;

    float acc[2][4][4];
    #pragma unroll
    for (int mi = 0; mi < 2; mi++)
        #pragma unroll
        for (int ni = 0; ni < 4; ni++)
            #pragma unroll
            for (int q = 0; q < 4; q++) acc[mi][ni][q] = 0.f;

    if (h_in) lstm_tf32_phase(h_in + (size_t)row0 * 256, 256, WhhT, 16, u_base, sA, sB, acc, tid, grp, tig, cbase);
    if (samp) lstm_tf32_phase(samp + (size_t)row0 * 16, 16, WextT, 1, u_base, sA, sB, acc, tid, grp, tig, cbase);
    lstm_tf32_phase(addr_emb + aid * 16, 0, WextT + 16 * 1024, 1, u_base, sA, sB, acc, tid, grp, tig, cbase);

    // scatter acc -> sAcc gate planes (safe: phase ends with a sync)
    #pragma unroll
    for (int mi = 0; mi < 2; mi++)
        #pragma unroll
        for (int ni = 0; ni < 4; ni++) {
            int col = u0w + ni * 8 + tig * 2;
            int r0 = mi * 16 + grp;
            *(float2*)&sAcc[(g * 32 + r0) * 66 + col]     = make_float2(acc[mi][ni][0], acc[mi][ni][1]);
            *(float2*)&sAcc[(g * 32 + r0 + 8) * 66 + col] = make_float2(acc[mi][ni][2], acc[mi][ni][3]);
        }
    __syncthreads();

    // fused gate epilogue: thread -> (8 m-rows, 1 unit)
    const int u = tid & 63;
    const int mb = (tid >> 6) * 8;
    const int ug = u_base + u;
    #pragma unroll
    for (int i = 0; i < 8; i++) {
        int m = mb + i;
        size_t b = (size_t)(row0 + m);
        float zi = sAcc[(0 * 32 + m) * 66 + u];
        float zf = sAcc[(1 * 32 + m) * 66 + u];
        float zg = sAcc[(2 * 32 + m) * 66 + u];
        float zo = sAcc[(3 * 32 + m) * 66 + u];
        const float* xp = xpre + b * 1024;
        float iv = sigf(zi + xp[ug]);
        float fv = sigf(zf + xp[256 + ug]);
        float gv = tanh_fast(zg + xp[512 + ug]);
        float ov = sigf(zo + xp[768 + ug]);
        float cold = c_in ? c_in[b * 256 + ug] : 0.f;
        float cn = fv * cold + iv * gv;
        h_out[b * 256 + ug] = ov * tanh_fast(cn);
        c_out[b * 256 + ug] = cn;
    }
}

// ---------------- heads ----------------
__device__ __forceinline__ float warp_dot256(const float* __restrict__ h, const float* __restrict__ w, int lane) {
    const float* hp = h + lane * 8;
    const float* wp = w + lane * 8;
    float4 a0 = *(const float4*)hp;
    float4 a1 = *(const float4*)(hp + 4);
    float4 b0 = *(const float4*)wp;
    float4 b1 = *(const float4*)(wp + 4);
    float s = a0.x * b0.x + a0.y * b0.y + a0.z * b0.z + a0.w * b0.w
            + a1.x * b1.x + a1.y * b1.y + a1.z * b1.z + a1.w * b1.w;
    #pragma unroll
    for (int off = 16; off; off >>= 1) s += __shfl_down_sync(0xffffffffu, s, off);
    return s;  // valid on lane 0
}

__global__ void head_rp_kernel(const float* __restrict__ h, const float* __restrict__ W,
                               const float* __restrict__ bias, const float* __restrict__ eps,
                               int col0, float* __restrict__ out, float* __restrict__ save) {
    int gw = (blockIdx.x * blockDim.x + threadIdx.x) >> 5;
    int lane = threadIdx.x & 31;
    if (gw >= B_N) return;
    const float* hp = h + (size_t)gw * 256;
    float d[4];
    #pragma unroll
    for (int o = 0; o < 4; o++) d[o] = warp_dot256(hp, W + o * 256, lane);
    if (lane == 0) {
        float r0 = d[0] + bias[0] + __expf(d[2] + bias[2]) * eps[(size_t)gw * 2 + 0];
        float r1 = d[1] + bias[1] + __expf(d[3] + bias[3]) * eps[(size_t)gw * 2 + 1];
        out[(size_t)gw * 15 + col0 + 0] = r0;
        out[(size_t)gw * 15 + col0 + 1] = r1;
        if (save) { save[(size_t)gw * 2 + 0] = r0; save[(size_t)gw * 2 + 1] = r1; }
    }
}

__global__ void final_heads_kernel(
    const float* __restrict__ h0, const float* __restrict__ h1, const float* __restrict__ h2,
    const float* __restrict__ h1b, const float* __restrict__ h2b, const float* __restrict__ h4b,
    const float* __restrict__ pid_w, const float* __restrict__ pid_b,
    const float* __restrict__ sid_w, const float* __restrict__ sid_b,
    const float* __restrict__ rp_w, const float* __restrict__ rp_b,
    const float* __restrict__ eps_rp, const float* __restrict__ eps_rp1,
    float* __restrict__ out) {
    int gw = (blockIdx.x * blockDim.x + threadIdx.x) >> 5;
    int lane = threadIdx.x & 31;
    if (gw >= B_N) return;
    size_t off = (size_t)gw * 256;
    float* o = out + (size_t)gw * 15;
    for (int q = 0; q < 3; q++) {
        float s = warp_dot256(h0 + off, pid_w + q * 256, lane);
        if (lane == 0) o[q] = s + pid_b[q];
    }
    for (int q = 0; q < 2; q++) {
        float s = warp_dot256(h1 + off, sid_w + q * 256, lane);
        if (lane == 0) o[3 + q] = s + sid_b[q];
    }
    {
        float d[4];
        #pragma unroll
        for (int q = 0; q < 4; q++) d[q] = warp_dot256(h2 + off, rp_w + q * 256, lane);
        if (lane == 0) {
            o[5] = d[0] + rp_b[0] + __expf(d[2] + rp_b[2]) * eps_rp[(size_t)gw * 2 + 0];
            o[6] = d[1] + rp_b[1] + __expf(d[3] + rp_b[3]) * eps_rp[(size_t)gw * 2 + 1];
        }
    }
    for (int q = 0; q < 2; q++) {
        float s = warp_dot256(h1b + off, sid_w + q * 256, lane);
        if (lane == 0) o[7 + q] = s + sid_b[q];
    }
    for (int q = 0; q < 2; q++) {
        float s = warp_dot256(h2b + off, sid_w + q * 256, lane);
        if (lane == 0) o[9 + q] = s + sid_b[q];
    }
    {
        float d[4];
        #pragma unroll
        for (int q = 0; q < 4; q++) d[q] = warp_dot256(h4b + off, rp_w + q * 256, lane);
        if (lane == 0) {
            o[13] = d[0] + rp_b[0] + __expf(d[2] + rp_b[2]) * eps_rp1[(size_t)gw * 2 + 0];
            o[14] = d[1] + rp_b[1] + __expf(d[3] + rp_b[3]) * eps_rp1[(size_t)gw * 2 + 1];
        }
    }
}

// ---------------- MLP: rp0(2) -> 100 -> 100 -> 16 ----------------
__global__ void mlp1_kernel(const float* __restrict__ rp0, const float* __restrict__ w1,
                            const float* __restrict__ b1, float* __restrict__ z1) {
    int i = blockIdx.x * blockDim.x + threadIdx.x;
    if (i >= B_N * 100) return;
    int b = i / 100, j = i - b * 100;
    float v = rp0[b * 2] * w1[j * 2] + rp0[b * 2 + 1] * w1[j * 2 + 1] + b1[j];
    z1[i] = tanh_fast(v);
}

__global__ void __launch_bounds__(128) mlp2_kernel(const float* __restrict__ z1, const float* __restrict__ w2,
                                                   const float* __restrict__ b2, float* __restrict__ z2) {
    __shared__ float w2s[100 * 101];
    __shared__ float z1s[8 * 100];
    __shared__ float b2s[100];
    int tid = threadIdx.x;
    int b0 = blockIdx.x * 8;
    for (int i = tid; i < 100 * 100; i += 128) { int j = i / 100, k = i - j * 100; w2s[j * 101 + k] = w2[i]; }
    for (int i = tid; i < 800; i += 128) z1s[i] = z1[(size_t)b0 * 100 + i];
    for (int i = tid; i < 100; i += 128) b2s[i] = b2[i];
    __syncthreads();
    for (int t = tid; t < 800; t += 128) {
        int r = t / 100, j = t - r * 100;
        float s = b2s[j];
        const float* zz = z1s + r * 100;
        const float* ww = w2s + j * 101;
        #pragma unroll 4
        for (int k = 0; k < 100; k++) s += zz[k] * ww[k];
        z2[(size_t)(b0 + r) * 100 + j] = tanh_fast(s);
    }
}

__global__ void mlp3_kernel(const float* __restrict__ z2, const float* __restrict__ w3,
                            const float* __restrict__ b3, float* __restrict__ remb) {
    int i = blockIdx.x * blockDim.x + threadIdx.x;
    if (i >= B_N * 16) return;
    int b = i >> 4, o = i & 15;
    float s = b3[o];
    const float* zz = z2 + (size_t)b * 100;
    const float* ww = w3 + o * 100;
    #pragma unroll 4
    for (int k = 0; k < 100; k++) s += zz[k] * ww[k];
    remb[i] = s;
}

// ---------------- host ----------------
static float* getsym(const void* symbol) {
    void* p = nullptr;
    cudaGetSymbolAddress(&p, symbol);
    return (float*)p;
}

extern "C" void kernel_launch(void* const* d_in, const int* in_sizes, int n_in,
                              void* d_out, int out_size) {
    const float* obs        = (const float*)d_in[0];
    const int*   program_id = (const int*)  d_in[1];
    const int*   shape_id   = (const int*)  d_in[2];
    const int*   shape_id_0 = (const int*)  d_in[3];
    const int*   shape_id_1 = (const int*)  d_in[4];
    const float* eps_rp     = (const float*)d_in[5];
    const float* eps_rp0    = (const float*)d_in[6];
    const float* eps_rp1    = (const float*)d_in[7];
    const float* conv1_w    = (const float*)d_in[8];
    const float* conv1_b    = (const float*)d_in[9];
    const float* conv2_w    = (const float*)d_in[10];
    const float* conv2_b    = (const float*)d_in[11];
    const float* mlp_w1     = (const float*)d_in[12];
    const float* mlp_b1     = (const float*)d_in[13];
    const float* mlp_w2     = (const float*)d_in[14];
    const float* mlp_b2     = (const float*)d_in[15];
    const float* mlp_w3     = (const float*)d_in[16];
    const float* mlp_b3     = (const float*)d_in[17];
    const float* W_ih       = (const float*)d_in[18];
    const float* b_ih       = (const float*)d_in[19];
    const float* W_hh       = (const float*)d_in[20];
    const float* b_hh       = (const float*)d_in[21];
    const float* addr_emb   = (const float*)d_in[22];
    const float* pid_emb    = (const float*)d_in[23];
    const float* sid_emb    = (const float*)d_in[24];
    const float* pid_ext_w  = (const float*)d_in[25];
    const float* pid_ext_b  = (const float*)d_in[26];
    const float* sid_ext_w  = (const float*)d_in[27];
    const float* sid_ext_b  = (const float*)d_in[28];
    const float* rp_ext_w   = (const float*)d_in[29];
    const float* rp_ext_b   = (const float*)d_in[30];
    float* out = (float*)d_out;

    float* st      = getsym(g_state);
    const int SZ   = B_N * HID;
    float* h0  = st + 0 * SZ;  float* c0  = st + 1 * SZ;
    float* h1  = st + 2 * SZ;  float* c1  = st + 3 * SZ;
    float* h1b = st + 4 * SZ;  float* c1b = st + 5 * SZ;
    float* h2  = st + 6 * SZ;  float* c2  = st + 7 * SZ;
    float* h2b = st + 8 * SZ;  float* c2b = st + 9 * SZ;
    float* h3b = st + 10 * SZ; float* c3b = st + 11 * SZ;
    float* h4b = st + 12 * SZ; float* c4b = st + 13 * SZ;

    float* samp   = getsym(g_samp);
    float* s_pid  = samp + 0 * B_N * 16;
    float* s_sid  = samp + 1 * B_N * 16;
    float* s_sid0 = samp + 2 * B_N * 16;
    float* s_sid1 = samp + 3 * B_N * 16;

    float* obs_e  = getsym(g_obs_emb);
    float* xpre   = getsym(g_xpre);
    float* WhhT   = getsym(g_WhhT);
    float* W0T    = getsym(g_W0T);
    float* WextT  = getsym(g_WextT);
    float* bias   = getsym(g_bias);
    float* rp0    = getsym(g_rp0);
    float* z1     = getsym(g_z1);
    float* z2     = getsym(g_z2);
    float* rp0emb = getsym(g_rp0emb);

    const int CONV_SMEM = (4096 + 288 + 32 + 4608 + 16 + CONV_CH * 1024 + 4096) * 4;
    cudaFuncSetAttribute(conv_fused_kernel, cudaFuncAttributeMaxDynamicSharedMemorySize, CONV_SMEM);

    prep_weights_kernel<<<512, 256>>>(W_ih, b_ih, W_hh, b_hh, WhhT, W0T, WextT, bias);
    gather_kernel<<<B_N * 16 / 256, 256>>>(program_id, shape_id, shape_id_0, shape_id_1,
                                           pid_emb, sid_emb, s_pid, s_sid, s_sid0, s_sid1);
    conv_fused_kernel<<<B_N, 256, CONV_SMEM>>>(obs, conv1_w, conv1_b, conv2_w, conv2_b, obs_e);
    gemm_xpre_kernel<<<dim3(8, B_N / 64), 256>>>(obs_e, W0T, bias, xpre);

    dim3 t1(4, B_N / 32, 1);
    dim3 t2(4, B_N / 32, 2);
    // step0: h=c=0, samp=0, aid=0
    lstm_step_tf32_kernel<<<t1, 256>>>(xpre, WhhT, WextT, addr_emb,
        nullptr, nullptr, nullptr, 0, h0, c0,
        nullptr, nullptr, nullptr, 0, nullptr, nullptr);
    // pair: step1A (aid=1) + step1B (aid=2), both from (h0,c0,s_pid)
    lstm_step_tf32_kernel<<<t2, 256>>>(xpre, WhhT, WextT, addr_emb,
        h0, c0, s_pid, 1, h1, c1,
        h0, c0, s_pid, 2, h1b, c1b);
    // pair: step2A (h1,s_sid,aid=4) + step2B (h1b,s_sid0,aid=3)
    lstm_step_tf32_kernel<<<t2, 256>>>(xpre, WhhT, WextT, addr_emb,
        h1, c1, s_sid, 4, h2, c2,
        h1b, c1b, s_sid0, 3, h2b, c2b);
    // step3B
    lstm_step_tf32_kernel<<<t1, 256>>>(xpre, WhhT, WextT, addr_emb,
        h2b, c2b, s_sid1, 5, h3b, c3b,
        nullptr, nullptr, nullptr, 0, nullptr, nullptr);
    head_rp_kernel<<<B_N / 8, 256>>>(h3b, rp_ext_w, rp_ext_b, eps_rp0, 11, out, rp0);
    // MLP on rp0
    mlp1_kernel<<<(B_N * 100 + 255) / 256, 256>>>(rp0, mlp_w1, mlp_b1, z1);
    mlp2_kernel<<<B_N / 8, 128>>>(z1, mlp_w2, mlp_b2, z2);
    mlp3_kernel<<<B_N * 16 / 256, 256>>>(z2, mlp_w3, mlp_b3, rp0emb);
    // step4B
    lstm_step_tf32_kernel<<<t1, 256>>>(xpre, WhhT, WextT, addr_emb,
        h3b, c3b, rp0emb, 6, h4b, c4b,
        nullptr, nullptr, nullptr, 0, nullptr, nullptr);
    // all remaining heads
    final_heads_kernel<<<B_N / 8, 256>>>(h0, h1, h2, h1b, h2b, h4b,
        pid_ext_w, pid_ext_b, sid_ext_w, sid_ext_b, rp_ext_w, rp_ext_b,
        eps_rp, eps_rp1, out);
}

// round 6
// speedup vs baseline: 2.3132x; 1.1381x over previous
#include <cuda_runtime.h>
#include <cstddef>
#include <cstdint>

#define B_N 4096
#define HID 256
#define OBS_D 400
#define IN_D 432

// ---------------- scratch (device globals; no allocation allowed) ----------------
__device__ float g_state[14 * B_N * HID];
__device__ float g_samp[4 * B_N * 16];      // prev_pid, samp_sid, samp_sid0, samp_sid1
__device__ float g_obs_emb[B_N * OBS_D];
__device__ float g_xpre[B_N * 1024];
__device__ float g_WhhT[256 * 1024];
__device__ float g_W0T[400 * 1024];
__device__ float g_WextT[32 * 1024];        // rows 0..15: samp cols of W_ih; 16..31: addr cols
__device__ float g_bias[1024];              // b_ih + b_hh
__device__ float g_rp0[B_N * 2];
__device__ float g_z1[B_N * 100];
__device__ float g_z2[B_N * 100];
__device__ float g_rp0emb[B_N * 16];

__device__ __forceinline__ float sigf(float x) { return 1.f / (1.f + __expf(-x)); }
__device__ __forceinline__ float tanh_fast(float x) { return 2.f / (1.f + __expf(-2.f * x)) - 1.f; }

__device__ __forceinline__ uint32_t f2tf32(float x) {
    uint32_t r;
    asm("cvt.rna.tf32.f32 %0, %1;" : "=r"(r) : "f"(x));
    return r;
}

#define MMA_TF32(c, a, b) \
    asm volatile("mma.sync.aligned.m16n8k8.row.col.f32.tf32.tf32.f32 " \
        "{%0,%1,%2,%3}, {%4,%5,%6,%7}, {%8,%9}, {%0,%1,%2,%3};" \
        : "+f"((c)[0]), "+f"((c)[1]), "+f"((c)[2]), "+f"((c)[3]) \
        : "r"((a)[0]), "r"((a)[1]), "r"((a)[2]), "r"((a)[3]), "r"((b)[0]), "r"((b)[1]))

// ---------------- weight prep: transposes for coalesced GEMM loads ----------------
__global__ void prep_weights_kernel(const float* __restrict__ W_ih, const float* __restrict__ b_ih,
                                    const float* __restrict__ W_hh, const float* __restrict__ b_hh,
                                    float* __restrict__ WhhT, float* __restrict__ W0T,
                                    float* __restrict__ WextT, float* __restrict__ bias) {
    int idx = blockIdx.x * blockDim.x + threadIdx.x;
    int stride = gridDim.x * blockDim.x;
    for (int i = idx; i < 256 * 1024; i += stride) { int k = i >> 10, j = i & 1023; WhhT[i] = W_hh[(size_t)j * 256 + k]; }
    for (int i = idx; i < 400 * 1024; i += stride) { int k = i >> 10, j = i & 1023; W0T[i] = W_ih[(size_t)j * IN_D + k]; }
    for (int i = idx; i < 32 * 1024;  i += stride) { int k = i >> 10, j = i & 1023; WextT[i] = W_ih[(size_t)j * IN_D + 400 + k]; }
    for (int i = idx; i < 1024; i += stride) bias[i] = b_ih[i] + b_hh[i];
}

// ---------------- embedding gathers ----------------
__global__ void gather_kernel(const int* __restrict__ pid, const int* __restrict__ sid,
                              const int* __restrict__ sid0, const int* __restrict__ sid1,
                              const float* __restrict__ pid_emb, const float* __restrict__ sid_emb,
                              float* __restrict__ s_pid, float* __restrict__ s_sid,
                              float* __restrict__ s_sid0, float* __restrict__ s_sid1) {
    int i = blockIdx.x * blockDim.x + threadIdx.x;
    if (i >= B_N * 16) return;
    int b = i >> 4, k = i & 15;
    s_pid[i]  = pid_emb[pid[b]  * 16 + k];
    s_sid[i]  = sid_emb[sid[b]  * 16 + k];
    s_sid0[i] = sid_emb[sid0[b] * 16 + k];
    s_sid1[i] = sid_emb[sid1[b] * 16 + k];
}

// ---------------- fused conv1+conv2+pool, ic-chunked, 2 blocks/SM ----------------
// conv1 input patch hoisted out of oc AND chunk loops (single input channel => invariant)
#define CONV_CH 8
__global__ void __launch_bounds__(256, 2) conv_fused_kernel(
    const float* __restrict__ obs, const float* __restrict__ w1, const float* __restrict__ b1,
    const float* __restrict__ w2, const float* __restrict__ b2, float* __restrict__ obs_emb) {
    extern __shared__ float sm[];
    float* s_in = sm;              // 4096
    float* s_w1 = s_in + 4096;     // 288
    float* s_b1 = s_w1 + 288;      // 32
    float* s_w2 = s_b1 + 32;       // 4608
    float* s_b2 = s_w2 + 4608;     // 16
    float* s_c1 = s_b2 + 16;       // CONV_CH*1024
    float* s_c2 = s_c1 + CONV_CH * 1024; // 4096
    int tid = threadIdx.x;
    int b = blockIdx.x;
    const float* in = obs + (size_t)b * 4096;
    for (int i = tid; i < 1024; i += 256) ((float4*)s_in)[i] = ((const float4*)in)[i];
    for (int i = tid; i < 288; i += 256) s_w1[i] = w1[i];
    for (int i = tid; i < 32; i += 256) s_b1[i] = b1[i];
    for (int i = tid; i < 4608; i += 256) s_w2[i] = w2[i];
    for (int i = tid; i < 16; i += 256) s_b2[i] = b2[i];
    __syncthreads();

    const int ocg = tid >> 6;
    const int oy0 = ((tid >> 3) & 7) * 2;
    const int ox0 = (tid & 7) * 2;
    float acc2[4][2][2];
    #pragma unroll
    for (int a = 0; a < 4; a++)
        #pragma unroll
        for (int sy = 0; sy < 2; sy++)
            #pragma unroll
            for (int sx = 0; sx < 2; sx++) acc2[a][sy][sx] = 0.f;
    const int iy0b = oy0 * 2 - 1, ix0b = ox0 * 2 - 1;

    const int c1y = ((tid >> 4) & 15) * 2;
    const int c1x = (tid & 15) * 2;
    const int c1iy0 = c1y * 2 - 1;
    const int c1ix0 = c1x * 2 - 1;

    // hoisted conv1 input patch (invariant across oc and chunks)
    float inp1[5][5];
    #pragma unroll
    for (int r = 0; r < 5; r++) {
        int iy = c1iy0 + r;
        bool okr = (unsigned)iy < 64u;
        #pragma unroll
        for (int q = 0; q < 5; q++) {
            int ix = c1ix0 + q;
            inp1[r][q] = (okr && (unsigned)ix < 64u) ? s_in[iy * 64 + ix] : 0.f;
        }
    }

    for (int cc = 0; cc < 32 / CONV_CH; cc++) {
        __syncthreads();
        // conv1: 2x2 outputs per thread for each of CONV_CH channels; patch already in regs
        #pragma unroll
        for (int it = 0; it < CONV_CH; it++) {
            int oc = cc * CONV_CH + it;
            float wv[9];
            #pragma unroll
            for (int q = 0; q < 9; q++) wv[q] = s_w1[oc * 9 + q];   // broadcast
            float bb = s_b1[oc];
            #pragma unroll
            for (int sy = 0; sy < 2; sy++)
                #pragma unroll
                for (int sx = 0; sx < 2; sx++) {
                    float acc = bb;
                    #pragma unroll
                    for (int dy = 0; dy < 3; dy++)
                        #pragma unroll
                        for (int dx = 0; dx < 3; dx++)
                            acc += wv[dy * 3 + dx] * inp1[sy * 2 + dy][sx * 2 + dx];
                    s_c1[it * 1024 + (c1y + sy) * 32 + (c1x + sx)] = fmaxf(acc, 0.f);
                }
        }
        __syncthreads();
        // conv2 accumulate over this ic chunk
        #pragma unroll
        for (int icl = 0; icl < CONV_CH; icl++) {
            int ic = cc * CONV_CH + icl;
            float inp[5][5];
            #pragma unroll
            for (int r = 0; r < 5; r++) {
                int iy = iy0b + r;
                bool okr = (unsigned)iy < 32u;
                #pragma unroll
                for (int q = 0; q < 5; q++) {
                    int ix = ix0b + q;
                    inp[r][q] = (okr && (unsigned)ix < 32u) ? s_c1[icl * 1024 + iy * 32 + ix] : 0.f;
                }
            }
            #pragma unroll
            for (int o4 = 0; o4 < 4; o4++) {
                const float* w = s_w2 + ((ocg * 4 + o4) * 32 + ic) * 9;
                float wv[9];
                #pragma unroll
                for (int q = 0; q < 9; q++) wv[q] = w[q];
                #pragma unroll
                for (int sy = 0; sy < 2; sy++)
                    #pragma unroll
                    for (int sx = 0; sx < 2; sx++)
                        #pragma unroll
                        for (int dy = 0; dy < 3; dy++)
                            #pragma unroll
                            for (int dx = 0; dx < 3; dx++)
                                acc2[o4][sy][sx] += wv[dy * 3 + dx] * inp[sy * 2 + dy][sx * 2 + dx];
            }
        }
    }
    #pragma unroll
    for (int o4 = 0; o4 < 4; o4++) {
        float bb = s_b2[ocg * 4 + o4];
        #pragma unroll
        for (int sy = 0; sy < 2; sy++)
            #pragma unroll
            for (int sx = 0; sx < 2; sx++)
                s_c2[(ocg * 4 + o4) * 256 + (oy0 + sy) * 16 + (ox0 + sx)] = fmaxf(acc2[o4][sy][sx] + bb, 0.f);
    }
    __syncthreads();
    for (int o = tid; o < 400; o += 256) {
        int c = o / 25;
        int rem = o - c * 25;
        int py = rem / 5, px = rem - (rem / 5) * 5;
        float s = 0.f;
        #pragma unroll
        for (int dy = 0; dy < 3; dy++)
            #pragma unroll
            for (int dx = 0; dx < 3; dx++)
                s += s_c2[c * 256 + (py * 3 + dy) * 16 + (px * 3 + dx)];
        obs_emb[(size_t)b * OBS_D + o] = s * (1.f / 9.f);
    }
}

// ---------------- shared tf32 GEMM phase (m32 x 256 gate-cols per block, 8 warps) ----------------
__device__ __forceinline__ void lstm_tf32_phase(
    const float* __restrict__ A, int astride,
    const float* __restrict__ Bsrc, int nslabs, int u_base,
    uint32_t* __restrict__ sA, uint32_t* __restrict__ sB,
    float acc[2][4][4], int tid, int grp, int tig, int cbase)
{
    const int am = tid >> 3, ak = (tid & 7) * 2;
    const int bkr = tid >> 4, bc0 = (tid & 15) * 16;
    const int bj = ((bc0 >> 6) << 8) + u_base + (bc0 & 63);
    for (int s = 0; s < nslabs; s++) {
        float2 av = *(const float2*)&A[(size_t)am * astride + s * 16 + ak];
        uint2 at; at.x = f2tf32(av.x); at.y = f2tf32(av.y);
        *(uint2*)&sA[am * 20 + ak] = at;
        const float* bp = Bsrc + (size_t)(s * 16 + bkr) * 1024 + bj;
        #pragma unroll
        for (int q = 0; q < 4; q++) {
            float4 v = ((const float4*)bp)[q];
            uint4 u4; u4.x = f2tf32(v.x); u4.y = f2tf32(v.y); u4.z = f2tf32(v.z); u4.w = f2tf32(v.w);
            *(uint4*)&sB[bkr * 264 + bc0 + q * 4] = u4;
        }
        __syncthreads();
        #pragma unroll
        for (int k8 = 0; k8 < 16; k8 += 8) {
            uint32_t a[2][4], b[4][2];
            #pragma unroll
            for (int mi = 0; mi < 2; mi++) {
                int r = mi * 16 + grp;
                a[mi][0] = sA[r * 20 + k8 + tig];
                a[mi][1] = sA[(r + 8) * 20 + k8 + tig];
                a[mi][2] = sA[r * 20 + k8 + tig + 4];
                a[mi][3] = sA[(r + 8) * 20 + k8 + tig + 4];
            }
            #pragma unroll
            for (int ni = 0; ni < 4; ni++) {
                b[ni][0] = sB[(k8 + tig) * 264 + cbase + ni * 8 + grp];
                b[ni][1] = sB[(k8 + tig + 4) * 264 + cbase + ni * 8 + grp];
            }
            #pragma unroll
            for (int mi = 0; mi < 2; mi++)
                #pragma unroll
                for (int ni = 0; ni < 4; ni++)
                    MMA_TF32(acc[mi][ni], a[mi], b[ni]);
        }
        __syncthreads();
    }
}

// ---------------- xpre = obs_emb @ W0T + bias, tf32 tensor cores ----------------
__global__ void __launch_bounds__(256) gemm_xpre_tf32_kernel(
    const float* __restrict__ A, const float* __restrict__ W0T,
    const float* __restrict__ bias, float* __restrict__ out) {
    __shared__ __align__(16) unsigned char smraw[33792];
    uint32_t* sA = (uint32_t*)smraw;
    uint32_t* sB = (uint32_t*)(smraw + 32 * 20 * 4);
    float* sAcc = (float*)smraw;

    const int tid = threadIdx.x;
    const int lane = tid & 31, w = tid >> 5;
    const int grp = lane >> 2, tig = lane & 3;
    const int g = w >> 1, u0w = (w & 1) * 32;
    const int cbase = g * 64 + u0w;
    const int u_base = blockIdx.x * 64;
    const int row0 = blockIdx.y * 32;

    float acc[2][4][4];
    #pragma unroll
    for (int mi = 0; mi < 2; mi++)
        #pragma unroll
        for (int ni = 0; ni < 4; ni++)
            #pragma unroll
            for (int q = 0; q < 4; q++) acc[mi][ni][q] = 0.f;

    lstm_tf32_phase(A + (size_t)row0 * OBS_D, OBS_D, W0T, 25, u_base, sA, sB, acc, tid, grp, tig, cbase);

    #pragma unroll
    for (int mi = 0; mi < 2; mi++)
        #pragma unroll
        for (int ni = 0; ni < 4; ni++) {
            int col = u0w + ni * 8 + tig * 2;
            int r0 = mi * 16 + grp;
            *(float2*)&sAcc[(g * 32 + r0) * 66 + col]     = make_float2(acc[mi][ni][0], acc[mi][ni][1]);
            *(float2*)&sAcc[(g * 32 + r0 + 8) * 66 + col] = make_float2(acc[mi][ni][2], acc[mi][ni][3]);
        }
    __syncthreads();

    const int u = tid & 63;
    const int mb = (tid >> 6) * 8;
    float bv[4];
    #pragma unroll
    for (int g2 = 0; g2 < 4; g2++) bv[g2] = bias[g2 * 256 + u_base + u];
    #pragma unroll
    for (int i = 0; i < 8; i++) {
        int m = mb + i;
        size_t b = (size_t)(row0 + m);
        #pragma unroll
        for (int g2 = 0; g2 < 4; g2++)
            out[b * 1024 + g2 * 256 + u_base + u] = sAcc[(g2 * 32 + m) * 66 + u] + bv[g2];
    }
}

// ---------------- tf32 tensor-core LSTM step (unchanged R4) ----------------
__global__ void __launch_bounds__(256) lstm_step_tf32_kernel(
    const float* __restrict__ xpre,
    const float* __restrict__ WhhT, const float* __restrict__ WextT,
    const float* __restrict__ addr_emb,
    const float* h_inA, const float* c_inA, const float* sampA, int aidA, float* h_outA, float* c_outA,
    const float* h_inB, const float* c_inB, const float* sampB, int aidB, float* h_outB, float* c_outB) {
    __shared__ __align__(16) unsigned char smraw[33792];
    uint32_t* sA = (uint32_t*)smraw;
    uint32_t* sB = (uint32_t*)(smraw + 32 * 20 * 4);
    float* sAcc = (float*)smraw;

    const float* h_in; const float* c_in; const float* samp; int aid; float* h_out; float* c_out;
    if (blockIdx.z == 0) { h_in = h_inA; c_in = c_inA; samp = sampA; aid = aidA; h_out = h_outA; c_out = c_outA; }
    else                 { h_in = h_inB; c_in = c_inB; samp = sampB; aid = aidB; h_out = h_outB; c_out = c_outB; }

    const int tid = threadIdx.x;
    const int lane = tid & 31, w = tid >> 5;
    const int grp = lane >> 2, tig = lane & 3;
    const int g = w >> 1, u0w = (w & 1) * 32;
    const int cbase = g * 64 + u0w;
    const int u_base = blockIdx.x * 64;
    const int row0 = blockIdx.y * 32;

    float acc[2][4][4];
    #pragma unroll
    for (int mi = 0; mi < 2; mi++)
        #pragma unroll
        for (int ni = 0; ni < 4; ni++)
            #pragma unroll
            for (int q = 0; q < 4; q++) acc[mi][ni][q] = 0.f;

    if (h_in) lstm_tf32_phase(h_in + (size_t)row0 * 256, 256, WhhT, 16, u_base, sA, sB, acc, tid, grp, tig, cbase);
    if (samp) lstm_tf32_phase(samp + (size_t)row0 * 16, 16, WextT, 1, u_base, sA, sB, acc, tid, grp, tig, cbase);
    lstm_tf32_phase(addr_emb + aid * 16, 0, WextT + 16 * 1024, 1, u_base, sA, sB, acc, tid, grp, tig, cbase);

    #pragma unroll
    for (int mi = 0; mi < 2; mi++)
        #pragma unroll
        for (int ni = 0; ni < 4; ni++) {
            int col = u0w + ni * 8 + tig * 2;
            int r0 = mi * 16 + grp;
            *(float2*)&sAcc[(g * 32 + r0) * 66 + col]     = make_float2(acc[mi][ni][0], acc[mi][ni][1]);
            *(float2*)&sAcc[(g * 32 + r0 + 8) * 66 + col] = make_float2(acc[mi][ni][2], acc[mi][ni][3]);
        }
    __syncthreads();

    const int u = tid & 63;
    const int mb = (tid >> 6) * 8;
    const int ug = u_base + u;
    #pragma unroll
    for (int i = 0; i < 8; i++) {
        int m = mb + i;
        size_t b = (size_t)(row0 + m);
        float zi = sAcc[(0 * 32 + m) * 66 + u];
        float zf = sAcc[(1 * 32 + m) * 66 + u];
        float zg = sAcc[(2 * 32 + m) * 66 + u];
        float zo = sAcc[(3 * 32 + m) * 66 + u];
        const float* xp = xpre + b * 1024;
        float iv = sigf(zi + xp[ug]);
        float fv = sigf(zf + xp[256 + ug]);
        float gv = tanh_fast(zg + xp[512 + ug]);
        float ov = sigf(zo + xp[768 + ug]);
        float cold = c_in ? c_in[b * 256 + ug] : 0.f;
        float cn = fv * cold + iv * gv;
        h_out[b * 256 + ug] = ov * tanh_fast(cn);
        c_out[b * 256 + ug] = cn;
    }
}

// ---------------- heads ----------------
__device__ __forceinline__ float warp_dot256(const float* __restrict__ h, const float* __restrict__ w, int lane) {
    const float* hp = h + lane * 8;
    const float* wp = w + lane * 8;
    float4 a0 = *(const float4*)hp;
    float4 a1 = *(const float4*)(hp + 4);
    float4 b0 = *(const float4*)wp;
    float4 b1 = *(const float4*)(wp + 4);
    float s = a0.x * b0.x + a0.y * b0.y + a0.z * b0.z + a0.w * b0.w
            + a1.x * b1.x + a1.y * b1.y + a1.z * b1.z + a1.w * b1.w;
    #pragma unroll
    for (int off = 16; off; off >>= 1) s += __shfl_down_sync(0xffffffffu, s, off);
    return s;  // valid on lane 0
}

__global__ void head_rp_kernel(const float* __restrict__ h, const float* __restrict__ W,
                               const float* __restrict__ bias, const float* __restrict__ eps,
                               int col0, float* __restrict__ out, float* __restrict__ save) {
    int gw = (blockIdx.x * blockDim.x + threadIdx.x) >> 5;
    int lane = threadIdx.x & 31;
    if (gw >= B_N) return;
    const float* hp = h + (size_t)gw * 256;
    float d[4];
    #pragma unroll
    for (int o = 0; o < 4; o++) d[o] = warp_dot256(hp, W + o * 256, lane);
    if (lane == 0) {
        float r0 = d[0] + bias[0] + __expf(d[2] + bias[2]) * eps[(size_t)gw * 2 + 0];
        float r1 = d[1] + bias[1] + __expf(d[3] + bias[3]) * eps[(size_t)gw * 2 + 1];
        out[(size_t)gw * 15 + col0 + 0] = r0;
        out[(size_t)gw * 15 + col0 + 1] = r1;
        if (save) { save[(size_t)gw * 2 + 0] = r0; save[(size_t)gw * 2 + 1] = r1; }
    }
}

__global__ void final_heads_kernel(
    const float* __restrict__ h0, const float* __restrict__ h1, const float* __restrict__ h2,
    const float* __restrict__ h1b, const float* __restrict__ h2b, const float* __restrict__ h4b,
    const float* __restrict__ pid_w, const float* __restrict__ pid_b,
    const float* __restrict__ sid_w, const float* __restrict__ sid_b,
    const float* __restrict__ rp_w, const float* __restrict__ rp_b,
    const float* __restrict__ eps_rp, const float* __restrict__ eps_rp1,
    float* __restrict__ out) {
    int gw = (blockIdx.x * blockDim.x + threadIdx.x) >> 5;
    int lane = threadIdx.x & 31;
    if (gw >= B_N) return;
    size_t off = (size_t)gw * 256;
    float* o = out + (size_t)gw * 15;
    for (int q = 0; q < 3; q++) {
        float s = warp_dot256(h0 + off, pid_w + q * 256, lane);
        if (lane == 0) o[q] = s + pid_b[q];
    }
    for (int q = 0; q < 2; q++) {
        float s = warp_dot256(h1 + off, sid_w + q * 256, lane);
        if (lane == 0) o[3 + q] = s + sid_b[q];
    }
    {
        float d[4];
        #pragma unroll
        for (int q = 0; q < 4; q++) d[q] = warp_dot256(h2 + off, rp_w + q * 256, lane);
        if (lane == 0) {
            o[5] = d[0] + rp_b[0] + __expf(d[2] + rp_b[2]) * eps_rp[(size_t)gw * 2 + 0];
            o[6] = d[1] + rp_b[1] + __expf(d[3] + rp_b[3]) * eps_rp[(size_t)gw * 2 + 1];
        }
    }
    for (int q = 0; q < 2; q++) {
        float s = warp_dot256(h1b + off, sid_w + q * 256, lane);
        if (lane == 0) o[7 + q] = s + sid_b[q];
    }
    for (int q = 0; q < 2; q++) {
        float s = warp_dot256(h2b + off, sid_w + q * 256, lane);
        if (lane == 0) o[9 + q] = s + sid_b[q];
    }
    {
        float d[4];
        #pragma unroll
        for (int q = 0; q < 4; q++) d[q] = warp_dot256(h4b + off, rp_w + q * 256, lane);
        if (lane == 0) {
            o[13] = d[0] + rp_b[0] + __expf(d[2] + rp_b[2]) * eps_rp1[(size_t)gw * 2 + 0];
            o[14] = d[1] + rp_b[1] + __expf(d[3] + rp_b[3]) * eps_rp1[(size_t)gw * 2 + 1];
        }
    }
}

// ---------------- MLP: rp0(2) -> 100 -> 100 -> 16 ----------------
__global__ void mlp1_kernel(const float* __restrict__ rp0, const float* __restrict__ w1,
                            const float* __restrict__ b1, float* __restrict__ z1) {
    int i = blockIdx.x * blockDim.x + threadIdx.x;
    if (i >= B_N * 100) return;
    int b = i / 100, j = i - b * 100;
    float v = rp0[b * 2] * w1[j * 2] + rp0[b * 2 + 1] * w1[j * 2 + 1] + b1[j];
    z1[i] = tanh_fast(v);
}

__global__ void __launch_bounds__(128) mlp2_kernel(const float* __restrict__ z1, const float* __restrict__ w2,
                                                   const float* __restrict__ b2, float* __restrict__ z2) {
    __shared__ float w2s[100 * 101];
    __shared__ float z1s[8 * 100];
    __shared__ float b2s[100];
    int tid = threadIdx.x;
    int b0 = blockIdx.x * 8;
    for (int i = tid; i < 100 * 100; i += 128) { int j = i / 100, k = i - j * 100; w2s[j * 101 + k] = w2[i]; }
    for (int i = tid; i < 800; i += 128) z1s[i] = z1[(size_t)b0 * 100 + i];
    for (int i = tid; i < 100; i += 128) b2s[i] = b2[i];
    __syncthreads();
    for (int t = tid; t < 800; t += 128) {
        int r = t / 100, j = t - r * 100;
        float s = b2s[j];
        const float* zz = z1s + r * 100;
        const float* ww = w2s + j * 101;
        #pragma unroll 4
        for (int k = 0; k < 100; k++) s += zz[k] * ww[k];
        z2[(size_t)(b0 + r) * 100 + j] = tanh_fast(s);
    }
}

__global__ void mlp3_kernel(const float* __restrict__ z2, const float* __restrict__ w3,
                            const float* __restrict__ b3, float* __restrict__ remb) {
    int i = blockIdx.x * blockDim.x + threadIdx.x;
    if (i >= B_N * 16) return;
    int b = i >> 4, o = i & 15;
    float s = b3[o];
    const float* zz = z2 + (size_t)b * 100;
    const float* ww = w3 + o * 100;
    #pragma unroll 4
    for (int k = 0; k < 100; k++) s += zz[k] * ww[k];
    remb[i] = s;
}

// ---------------- host ----------------
static float* getsym(const void* symbol) {
    void* p = nullptr;
    cudaGetSymbolAddress(&p, symbol);
    return (float*)p;
}

extern "C" void kernel_launch(void* const* d_in, const int* in_sizes, int n_in,
                              void* d_out, int out_size) {
    const float* obs        = (const float*)d_in[0];
    const int*   program_id = (const int*)  d_in[1];
    const int*   shape_id   = (const int*)  d_in[2];
    const int*   shape_id_0 = (const int*)  d_in[3];
    const int*   shape_id_1 = (const int*)  d_in[4];
    const float* eps_rp     = (const float*)d_in[5];
    const float* eps_rp0    = (const float*)d_in[6];
    const float* eps_rp1    = (const float*)d_in[7];
    const float* conv1_w    = (const float*)d_in[8];
    const float* conv1_b    = (const float*)d_in[9];
    const float* conv2_w    = (const float*)d_in[10];
    const float* conv2_b    = (const float*)d_in[11];
    const float* mlp_w1     = (const float*)d_in[12];
    const float* mlp_b1     = (const float*)d_in[13];
    const float* mlp_w2     = (const float*)d_in[14];
    const float* mlp_b2     = (const float*)d_in[15];
    const float* mlp_w3     = (const float*)d_in[16];
    const float* mlp_b3     = (const float*)d_in[17];
    const float* W_ih       = (const float*)d_in[18];
    const float* b_ih       = (const float*)d_in[19];
    const float* W_hh       = (const float*)d_in[20];
    const float* b_hh       = (const float*)d_in[21];
    const float* addr_emb   = (const float*)d_in[22];
    const float* pid_emb    = (const float*)d_in[23];
    const float* sid_emb    = (const float*)d_in[24];
    const float* pid_ext_w  = (const float*)d_in[25];
    const float* pid_ext_b  = (const float*)d_in[26];
    const float* sid_ext_w  = (const float*)d_in[27];
    const float* sid_ext_b  = (const float*)d_in[28];
    const float* rp_ext_w   = (const float*)d_in[29];
    const float* rp_ext_b   = (const float*)d_in[30];
    float* out = (float*)d_out;

    float* st      = getsym(g_state);
    const int SZ   = B_N * HID;
    float* h0  = st + 0 * SZ;  float* c0  = st + 1 * SZ;
    float* h1  = st + 2 * SZ;  float* c1  = st + 3 * SZ;
    float* h1b = st + 4 * SZ;  float* c1b = st + 5 * SZ;
    float* h2  = st + 6 * SZ;  float* c2  = st + 7 * SZ;
    float* h2b = st + 8 * SZ;  float* c2b = st + 9 * SZ;
    float* h3b = st + 10 * SZ; float* c3b = st + 11 * SZ;
    float* h4b = st + 12 * SZ; float* c4b = st + 13 * SZ;

    float* samp   = getsym(g_samp);
    float* s_pid  = samp + 0 * B_N * 16;
    float* s_sid  = samp + 1 * B_N * 16;
    float* s_sid0 = samp + 2 * B_N * 16;
    float* s_sid1 = samp + 3 * B_N * 16;

    float* obs_e  = getsym(g_obs_emb);
    float* xpre   = getsym(g_xpre);
    float* WhhT   = getsym(g_WhhT);
    float* W0T    = getsym(g_W0T);
    float* WextT  = getsym(g_WextT);
    float* bias   = getsym(g_bias);
    float* rp0    = getsym(g_rp0);
    float* z1     = getsym(g_z1);
    float* z2     = getsym(g_z2);
    float* rp0emb = getsym(g_rp0emb);

    const int CONV_SMEM = (4096 + 288 + 32 + 4608 + 16 + CONV_CH * 1024 + 4096) * 4;
    cudaFuncSetAttribute(conv_fused_kernel, cudaFuncAttributeMaxDynamicSharedMemorySize, CONV_SMEM);

    prep_weights_kernel<<<512, 256>>>(W_ih, b_ih, W_hh, b_hh, WhhT, W0T, WextT, bias);
    gather_kernel<<<B_N * 16 / 256, 256>>>(program_id, shape_id, shape_id_0, shape_id_1,
                                           pid_emb, sid_emb, s_pid, s_sid, s_sid0, s_sid1);
    conv_fused_kernel<<<B_N, 256, CONV_SMEM>>>(obs, conv1_w, conv1_b, conv2_w, conv2_b, obs_e);
    gemm_xpre_tf32_kernel<<<dim3(4, B_N / 32), 256>>>(obs_e, W0T, bias, xpre);

    dim3 t1(4, B_N / 32, 1);
    dim3 t2(4, B_N / 32, 2);
    // step0: h=c=0, samp=0, aid=0
    lstm_step_tf32_kernel<<<t1, 256>>>(xpre, WhhT, WextT, addr_emb,
        nullptr, nullptr, nullptr, 0, h0, c0,
        nullptr, nullptr, nullptr, 0, nullptr, nullptr);
    // pair: step1A (aid=1) + step1B (aid=2), both from (h0,c0,s_pid)
    lstm_step_tf32_kernel<<<t2, 256>>>(xpre, WhhT, WextT, addr_emb,
        h0, c0, s_pid, 1, h1, c1,
        h0, c0, s_pid, 2, h1b, c1b);
    // pair: step2A (h1,s_sid,aid=4) + step2B (h1b,s_sid0,aid=3)
    lstm_step_tf32_kernel<<<t2, 256>>>(xpre, WhhT, WextT, addr_emb,
        h1, c1, s_sid, 4, h2, c2,
        h1b, c1b, s_sid0, 3, h2b, c2b);
    // step3B
    lstm_step_tf32_kernel<<<t1, 256>>>(xpre, WhhT, WextT, addr_emb,
        h2b, c2b, s_sid1, 5, h3b, c3b,
        nullptr, nullptr, nullptr, 0, nullptr, nullptr);
    head_rp_kernel<<<B_N / 8, 256>>>(h3b, rp_ext_w, rp_ext_b, eps_rp0, 11, out, rp0);
    // MLP on rp0
    mlp1_kernel<<<(B_N * 100 + 255) / 256, 256>>>(rp0, mlp_w1, mlp_b1, z1);
    mlp2_kernel<<<B_N / 8, 128>>>(z1, mlp_w2, mlp_b2, z2);
    mlp3_kernel<<<B_N * 16 / 256, 256>>>(z2, mlp_w3, mlp_b3, rp0emb);
    // step4B
    lstm_step_tf32_kernel<<<t1, 256>>>(xpre, WhhT, WextT, addr_emb,
        h3b, c3b, rp0emb, 6, h4b, c4b,
        nullptr, nullptr, nullptr, 0, nullptr, nullptr);
    // all remaining heads
    final_heads_kernel<<<B_N / 8, 256>>>(h0, h1, h2, h1b, h2b, h4b,
        pid_ext_w, pid_ext_b, sid_ext_w, sid_ext_b, rp_ext_w, rp_ext_b,
        eps_rp, eps_rp1, out);
}

// round 7
// speedup vs baseline: 2.7232x; 1.1772x over previous
#include <cuda_runtime.h>
#include <cstddef>
#include <cstdint>

#define B_N 4096
#define HID 256
#define OBS_D 400
#define IN_D 432

// ---------------- scratch (device globals; no allocation allowed) ----------------
__device__ float g_state[14 * B_N * HID];
__device__ float g_samp[4 * B_N * 16];      // prev_pid, samp_sid, samp_sid0, samp_sid1
__device__ float g_obs_emb[B_N * OBS_D];
__device__ float g_xpre[B_N * 1024];
__device__ float g_WhhT[256 * 1024];
__device__ float g_W0T[400 * 1024];
__device__ float g_WextT[32 * 1024];        // rows 0..15: samp cols of W_ih; 16..31: addr cols
__device__ float g_bias[1024];              // b_ih + b_hh
__device__ float g_rp0[B_N * 2];
__device__ float g_z1[B_N * 100];
__device__ float g_z2[B_N * 100];
__device__ float g_rp0emb[B_N * 16];

__device__ __forceinline__ float sigf(float x) { return 1.f / (1.f + __expf(-x)); }
__device__ __forceinline__ float tanh_fast(float x) { return 2.f / (1.f + __expf(-2.f * x)) - 1.f; }

#define MMA_TF32(c, a, b) \
    asm volatile("mma.sync.aligned.m16n8k8.row.col.f32.tf32.tf32.f32 " \
        "{%0,%1,%2,%3}, {%4,%5,%6,%7}, {%8,%9}, {%0,%1,%2,%3};" \
        : "+f"((c)[0]), "+f"((c)[1]), "+f"((c)[2]), "+f"((c)[3]) \
        : "r"((a)[0]), "r"((a)[1]), "r"((a)[2]), "r"((a)[3]), "r"((b)[0]), "r"((b)[1]))

__device__ __forceinline__ void cp16(uint32_t smem_addr, const void* gptr) {
    asm volatile("cp.async.cg.shared.global [%0], [%1], 16;" :: "r"(smem_addr), "l"(gptr));
}
#define CP_COMMIT() asm volatile("cp.async.commit_group;")
#define CP_WAIT0()  asm volatile("cp.async.wait_group 0;" ::: "memory")

// ---------------- weight prep: transposes for coalesced GEMM loads ----------------
__global__ void prep_weights_kernel(const float* __restrict__ W_ih, const float* __restrict__ b_ih,
                                    const float* __restrict__ W_hh, const float* __restrict__ b_hh,
                                    float* __restrict__ WhhT, float* __restrict__ W0T,
                                    float* __restrict__ WextT, float* __restrict__ bias) {
    int idx = blockIdx.x * blockDim.x + threadIdx.x;
    int stride = gridDim.x * blockDim.x;
    for (int i = idx; i < 256 * 1024; i += stride) { int k = i >> 10, j = i & 1023; WhhT[i] = W_hh[(size_t)j * 256 + k]; }
    for (int i = idx; i < 400 * 1024; i += stride) { int k = i >> 10, j = i & 1023; W0T[i] = W_ih[(size_t)j * IN_D + k]; }
    for (int i = idx; i < 32 * 1024;  i += stride) { int k = i >> 10, j = i & 1023; WextT[i] = W_ih[(size_t)j * IN_D + 400 + k]; }
    for (int i = idx; i < 1024; i += stride) bias[i] = b_ih[i] + b_hh[i];
}

// ---------------- embedding gathers ----------------
__global__ void gather_kernel(const int* __restrict__ pid, const int* __restrict__ sid,
                              const int* __restrict__ sid0, const int* __restrict__ sid1,
                              const float* __restrict__ pid_emb, const float* __restrict__ sid_emb,
                              float* __restrict__ s_pid, float* __restrict__ s_sid,
                              float* __restrict__ s_sid0, float* __restrict__ s_sid1) {
    int i = blockIdx.x * blockDim.x + threadIdx.x;
    if (i >= B_N * 16) return;
    int b = i >> 4, k = i & 15;
    s_pid[i]  = pid_emb[pid[b]  * 16 + k];
    s_sid[i]  = sid_emb[sid[b]  * 16 + k];
    s_sid0[i] = sid_emb[sid0[b] * 16 + k];
    s_sid1[i] = sid_emb[sid1[b] * 16 + k];
}

// ---------------- fused conv1+conv2+pool (unchanged R5) ----------------
#define CONV_CH 8
__global__ void __launch_bounds__(256, 2) conv_fused_kernel(
    const float* __restrict__ obs, const float* __restrict__ w1, const float* __restrict__ b1,
    const float* __restrict__ w2, const float* __restrict__ b2, float* __restrict__ obs_emb) {
    extern __shared__ float sm[];
    float* s_in = sm;
    float* s_w1 = s_in + 4096;
    float* s_b1 = s_w1 + 288;
    float* s_w2 = s_b1 + 32;
    float* s_b2 = s_w2 + 4608;
    float* s_c1 = s_b2 + 16;
    float* s_c2 = s_c1 + CONV_CH * 1024;
    int tid = threadIdx.x;
    int b = blockIdx.x;
    const float* in = obs + (size_t)b * 4096;
    for (int i = tid; i < 1024; i += 256) ((float4*)s_in)[i] = ((const float4*)in)[i];
    for (int i = tid; i < 288; i += 256) s_w1[i] = w1[i];
    for (int i = tid; i < 32; i += 256) s_b1[i] = b1[i];
    for (int i = tid; i < 4608; i += 256) s_w2[i] = w2[i];
    for (int i = tid; i < 16; i += 256) s_b2[i] = b2[i];
    __syncthreads();

    const int ocg = tid >> 6;
    const int oy0 = ((tid >> 3) & 7) * 2;
    const int ox0 = (tid & 7) * 2;
    float acc2[4][2][2];
    #pragma unroll
    for (int a = 0; a < 4; a++)
        #pragma unroll
        for (int sy = 0; sy < 2; sy++)
            #pragma unroll
            for (int sx = 0; sx < 2; sx++) acc2[a][sy][sx] = 0.f;
    const int iy0b = oy0 * 2 - 1, ix0b = ox0 * 2 - 1;

    const int c1y = ((tid >> 4) & 15) * 2;
    const int c1x = (tid & 15) * 2;
    const int c1iy0 = c1y * 2 - 1;
    const int c1ix0 = c1x * 2 - 1;

    float inp1[5][5];
    #pragma unroll
    for (int r = 0; r < 5; r++) {
        int iy = c1iy0 + r;
        bool okr = (unsigned)iy < 64u;
        #pragma unroll
        for (int q = 0; q < 5; q++) {
            int ix = c1ix0 + q;
            inp1[r][q] = (okr && (unsigned)ix < 64u) ? s_in[iy * 64 + ix] : 0.f;
        }
    }

    for (int cc = 0; cc < 32 / CONV_CH; cc++) {
        __syncthreads();
        #pragma unroll
        for (int it = 0; it < CONV_CH; it++) {
            int oc = cc * CONV_CH + it;
            float wv[9];
            #pragma unroll
            for (int q = 0; q < 9; q++) wv[q] = s_w1[oc * 9 + q];
            float bb = s_b1[oc];
            #pragma unroll
            for (int sy = 0; sy < 2; sy++)
                #pragma unroll
                for (int sx = 0; sx < 2; sx++) {
                    float acc = bb;
                    #pragma unroll
                    for (int dy = 0; dy < 3; dy++)
                        #pragma unroll
                        for (int dx = 0; dx < 3; dx++)
                            acc += wv[dy * 3 + dx] * inp1[sy * 2 + dy][sx * 2 + dx];
                    s_c1[it * 1024 + (c1y + sy) * 32 + (c1x + sx)] = fmaxf(acc, 0.f);
                }
        }
        __syncthreads();
        #pragma unroll
        for (int icl = 0; icl < CONV_CH; icl++) {
            int ic = cc * CONV_CH + icl;
            float inp[5][5];
            #pragma unroll
            for (int r = 0; r < 5; r++) {
                int iy = iy0b + r;
                bool okr = (unsigned)iy < 32u;
                #pragma unroll
                for (int q = 0; q < 5; q++) {
                    int ix = ix0b + q;
                    inp[r][q] = (okr && (unsigned)ix < 32u) ? s_c1[icl * 1024 + iy * 32 + ix] : 0.f;
                }
            }
            #pragma unroll
            for (int o4 = 0; o4 < 4; o4++) {
                const float* w = s_w2 + ((ocg * 4 + o4) * 32 + ic) * 9;
                float wv[9];
                #pragma unroll
                for (int q = 0; q < 9; q++) wv[q] = w[q];
                #pragma unroll
                for (int sy = 0; sy < 2; sy++)
                    #pragma unroll
                    for (int sx = 0; sx < 2; sx++)
                        #pragma unroll
                        for (int dy = 0; dy < 3; dy++)
                            #pragma unroll
                            for (int dx = 0; dx < 3; dx++)
                                acc2[o4][sy][sx] += wv[dy * 3 + dx] * inp[sy * 2 + dy][sx * 2 + dx];
            }
        }
    }
    #pragma unroll
    for (int o4 = 0; o4 < 4; o4++) {
        float bb = s_b2[ocg * 4 + o4];
        #pragma unroll
        for (int sy = 0; sy < 2; sy++)
            #pragma unroll
            for (int sx = 0; sx < 2; sx++)
                s_c2[(ocg * 4 + o4) * 256 + (oy0 + sy) * 16 + (ox0 + sx)] = fmaxf(acc2[o4][sy][sx] + bb, 0.f);
    }
    __syncthreads();
    for (int o = tid; o < 400; o += 256) {
        int c = o / 25;
        int rem = o - c * 25;
        int py = rem / 5, px = rem - (rem / 5) * 5;
        float s = 0.f;
        #pragma unroll
        for (int dy = 0; dy < 3; dy++)
            #pragma unroll
            for (int dx = 0; dx < 3; dx++)
                s += s_c2[c * 256 + (py * 3 + dy) * 16 + (px * 3 + dx)];
        obs_emb[(size_t)b * OBS_D + o] = s * (1.f / 9.f);
    }
}

// ---------------- tf32 GEMM phase v2: m64 x 256 cols, cp.async double-buffered ----------------
// 8 warps: mhalf = w>>2 (m32 sub-tile), cw = w&3 (u_warp = cw*16).
// Warp n-tiles t=0..7: gate g=t>>1, unit-half uh=t&1 -> col g*64 + u_warp + uh*8.
// smem words: sA[2][64*20], sB[2][16*264]; raw fp32 bits fed to tf32 mma (HW truncates).
__device__ __forceinline__ void tf32_gemm_phase(
    const float* __restrict__ A, int astride,
    const float* __restrict__ Bsrc, int nslabs, int u_base,
    uint32_t* __restrict__ sm, uint32_t smaddr,
    float acc[2][8][4],
    int tid, int grp, int tig, int mrow_base, int u_warp)
{
    const int am = tid >> 2, ak = (tid & 3) * 4;
    const int bkr = tid >> 4, bc0 = (tid & 15) * 16;
    const int bj = ((bc0 >> 6) << 8) + u_base + (bc0 & 63);
    uint32_t* sAp[2] = { sm, sm + 1280 };
    uint32_t* sBp[2] = { sm + 2560, sm + 2560 + 4224 };
    const uint32_t sAo[2] = { smaddr, smaddr + 5120u };
    const uint32_t sBo[2] = { smaddr + 10240u, smaddr + 10240u + 16896u };

    // prologue: stage slab 0 into buf 0
    cp16(sAo[0] + (uint32_t)(am * 20 + ak) * 4u, A + (size_t)am * astride + ak);
    {
        const float* bp = Bsrc + (size_t)bkr * 1024 + bj;
        #pragma unroll
        for (int q = 0; q < 4; q++)
            cp16(sBo[0] + (uint32_t)(bkr * 264 + bc0 + q * 4) * 4u, bp + q * 4);
    }
    CP_COMMIT();

    for (int s = 0; s < nslabs; s++) {
        CP_WAIT0();
        __syncthreads();
        if (s + 1 < nslabs) {
            int nb = (s + 1) & 1;
            cp16(sAo[nb] + (uint32_t)(am * 20 + ak) * 4u, A + (size_t)am * astride + (s + 1) * 16 + ak);
            const float* bp = Bsrc + (size_t)((s + 1) * 16 + bkr) * 1024 + bj;
            #pragma unroll
            for (int q = 0; q < 4; q++)
                cp16(sBo[nb] + (uint32_t)(bkr * 264 + bc0 + q * 4) * 4u, bp + q * 4);
            CP_COMMIT();
        }
        const uint32_t* cA = sAp[s & 1];
        const uint32_t* cB = sBp[s & 1];
        #pragma unroll
        for (int k8 = 0; k8 < 16; k8 += 8) {
            uint32_t a[2][4], b[8][2];
            #pragma unroll
            for (int mi = 0; mi < 2; mi++) {
                int r = mrow_base + mi * 16 + grp;
                a[mi][0] = cA[r * 20 + k8 + tig];
                a[mi][1] = cA[(r + 8) * 20 + k8 + tig];
                a[mi][2] = cA[r * 20 + k8 + tig + 4];
                a[mi][3] = cA[(r + 8) * 20 + k8 + tig + 4];
            }
            #pragma unroll
            for (int t = 0; t < 8; t++) {
                int col = (t >> 1) * 64 + u_warp + (t & 1) * 8 + grp;
                b[t][0] = cB[(k8 + tig) * 264 + col];
                b[t][1] = cB[(k8 + tig + 4) * 264 + col];
            }
            #pragma unroll
            for (int mi = 0; mi < 2; mi++)
                #pragma unroll
                for (int t = 0; t < 8; t++)
                    MMA_TF32(acc[mi][t], a[mi], b[t]);
        }
        __syncthreads();
    }
}

// ---------------- xpre = obs_emb @ W0T + bias (tf32 v2) ----------------
__global__ void __launch_bounds__(256, 2) gemm_xpre_tf32_kernel(
    const float* __restrict__ A, const float* __restrict__ W0T,
    const float* __restrict__ bias, float* __restrict__ out) {
    __shared__ __align__(16) uint32_t sm[2 * 1280 + 2 * 4224];
    uint32_t smaddr = (uint32_t)__cvta_generic_to_shared(sm);

    const int tid = threadIdx.x;
    const int lane = tid & 31, w = tid >> 5;
    const int grp = lane >> 2, tig = lane & 3;
    const int mrow_base = (w >> 2) * 32;
    const int u_warp = (w & 3) * 16;
    const int u_base = blockIdx.x * 64;
    const int row0 = blockIdx.y * 64;

    float acc[2][8][4];
    #pragma unroll
    for (int mi = 0; mi < 2; mi++)
        #pragma unroll
        for (int t = 0; t < 8; t++)
            #pragma unroll
            for (int q = 0; q < 4; q++) acc[mi][t][q] = 0.f;

    tf32_gemm_phase(A + (size_t)row0 * OBS_D, OBS_D, W0T, 25, u_base, sm, smaddr,
                    acc, tid, grp, tig, mrow_base, u_warp);

    // register epilogue: add bias, store
    #pragma unroll
    for (int mi = 0; mi < 2; mi++)
        #pragma unroll
        for (int rr = 0; rr < 2; rr++) {
            size_t b = (size_t)(row0 + mrow_base + mi * 16 + grp + rr * 8);
            #pragma unroll
            for (int t = 0; t < 8; t++) {
                int g = t >> 1, uh = t & 1;
                int col = g * 256 + u_base + u_warp + uh * 8 + 2 * tig;
                float2 bv = *(const float2*)&bias[col];
                float2 o = make_float2(acc[mi][t][rr * 2 + 0] + bv.x, acc[mi][t][rr * 2 + 1] + bv.y);
                *(float2*)&out[b * 1024 + col] = o;
            }
        }
}

// ---------------- tf32 LSTM step v2: GEMM + register-resident gate epilogue ----------------
__global__ void __launch_bounds__(256, 2) lstm_step_tf32_kernel(
    const float* __restrict__ xpre,
    const float* __restrict__ WhhT, const float* __restrict__ WextT,
    const float* __restrict__ addr_emb,
    const float* h_inA, const float* c_inA, const float* sampA, int aidA, float* h_outA, float* c_outA,
    const float* h_inB, const float* c_inB, const float* sampB, int aidB, float* h_outB, float* c_outB) {
    __shared__ __align__(16) uint32_t sm[2 * 1280 + 2 * 4224];
    uint32_t smaddr = (uint32_t)__cvta_generic_to_shared(sm);

    const float* h_in; const float* c_in; const float* samp; int aid; float* h_out; float* c_out;
    if (blockIdx.z == 0) { h_in = h_inA; c_in = c_inA; samp = sampA; aid = aidA; h_out = h_outA; c_out = c_outA; }
    else                 { h_in = h_inB; c_in = c_inB; samp = sampB; aid = aidB; h_out = h_outB; c_out = c_outB; }

    const int tid = threadIdx.x;
    const int lane = tid & 31, w = tid >> 5;
    const int grp = lane >> 2, tig = lane & 3;
    const int mrow_base = (w >> 2) * 32;
    const int u_warp = (w & 3) * 16;
    const int u_base = blockIdx.x * 64;
    const int row0 = blockIdx.y * 64;

    float acc[2][8][4];
    #pragma unroll
    for (int mi = 0; mi < 2; mi++)
        #pragma unroll
        for (int t = 0; t < 8; t++)
            #pragma unroll
            for (int q = 0; q < 4; q++) acc[mi][t][q] = 0.f;

    if (h_in) tf32_gemm_phase(h_in + (size_t)row0 * 256, 256, WhhT, 16, u_base, sm, smaddr,
                              acc, tid, grp, tig, mrow_base, u_warp);
    if (samp) tf32_gemm_phase(samp + (size_t)row0 * 16, 16, WextT, 1, u_base, sm, smaddr,
                              acc, tid, grp, tig, mrow_base, u_warp);
    tf32_gemm_phase(addr_emb + aid * 16, 0, WextT + 16 * 1024, 1, u_base, sm, smaddr,
                    acc, tid, grp, tig, mrow_base, u_warp);

    // register-resident gate epilogue: thread holds i,f,g,o for its (row, unit-pair)s
    const int ub = u_base + u_warp;
    #pragma unroll
    for (int mi = 0; mi < 2; mi++)
        #pragma unroll
        for (int rr = 0; rr < 2; rr++) {
            size_t b = (size_t)(row0 + mrow_base + mi * 16 + grp + rr * 8);
            const float* xp = xpre + b * 1024;
            #pragma unroll
            for (int uh = 0; uh < 2; uh++) {
                int ug = ub + uh * 8 + 2 * tig;
                float2 xi = *(const float2*)&xp[0 * 256 + ug];
                float2 xf = *(const float2*)&xp[1 * 256 + ug];
                float2 xg = *(const float2*)&xp[2 * 256 + ug];
                float2 xo = *(const float2*)&xp[3 * 256 + ug];
                float2 cold = c_in ? *(const float2*)&c_in[b * 256 + ug] : make_float2(0.f, 0.f);
                int q0 = rr * 2;
                float i0 = sigf(acc[mi][0 + uh][q0]     + xi.x);
                float i1 = sigf(acc[mi][0 + uh][q0 + 1] + xi.y);
                float f0 = sigf(acc[mi][2 + uh][q0]     + xf.x);
                float f1 = sigf(acc[mi][2 + uh][q0 + 1] + xf.y);
                float g0 = tanh_fast(acc[mi][4 + uh][q0]     + xg.x);
                float g1 = tanh_fast(acc[mi][4 + uh][q0 + 1] + xg.y);
                float o0 = sigf(acc[mi][6 + uh][q0]     + xo.x);
                float o1 = sigf(acc[mi][6 + uh][q0 + 1] + xo.y);
                float cn0 = f0 * cold.x + i0 * g0;
                float cn1 = f1 * cold.y + i1 * g1;
                *(float2*)&c_out[b * 256 + ug] = make_float2(cn0, cn1);
                *(float2*)&h_out[b * 256 + ug] = make_float2(o0 * tanh_fast(cn0), o1 * tanh_fast(cn1));
            }
        }
}

// ---------------- heads ----------------
__device__ __forceinline__ float warp_dot256(const float* __restrict__ h, const float* __restrict__ w, int lane) {
    const float* hp = h + lane * 8;
    const float* wp = w + lane * 8;
    float4 a0 = *(const float4*)hp;
    float4 a1 = *(const float4*)(hp + 4);
    float4 b0 = *(const float4*)wp;
    float4 b1 = *(const float4*)(wp + 4);
    float s = a0.x * b0.x + a0.y * b0.y + a0.z * b0.z + a0.w * b0.w
            + a1.x * b1.x + a1.y * b1.y + a1.z * b1.z + a1.w * b1.w;
    #pragma unroll
    for (int off = 16; off; off >>= 1) s += __shfl_down_sync(0xffffffffu, s, off);
    return s;  // valid on lane 0
}

__global__ void head_rp_kernel(const float* __restrict__ h, const float* __restrict__ W,
                               const float* __restrict__ bias, const float* __restrict__ eps,
                               int col0, float* __restrict__ out, float* __restrict__ save) {
    int gw = (blockIdx.x * blockDim.x + threadIdx.x) >> 5;
    int lane = threadIdx.x & 31;
    if (gw >= B_N) return;
    const float* hp = h + (size_t)gw * 256;
    float d[4];
    #pragma unroll
    for (int o = 0; o < 4; o++) d[o] = warp_dot256(hp, W + o * 256, lane);
    if (lane == 0) {
        float r0 = d[0] + bias[0] + __expf(d[2] + bias[2]) * eps[(size_t)gw * 2 + 0];
        float r1 = d[1] + bias[1] + __expf(d[3] + bias[3]) * eps[(size_t)gw * 2 + 1];
        out[(size_t)gw * 15 + col0 + 0] = r0;
        out[(size_t)gw * 15 + col0 + 1] = r1;
        if (save) { save[(size_t)gw * 2 + 0] = r0; save[(size_t)gw * 2 + 1] = r1; }
    }
}

__global__ void final_heads_kernel(
    const float* __restrict__ h0, const float* __restrict__ h1, const float* __restrict__ h2,
    const float* __restrict__ h1b, const float* __restrict__ h2b, const float* __restrict__ h4b,
    const float* __restrict__ pid_w, const float* __restrict__ pid_b,
    const float* __restrict__ sid_w, const float* __restrict__ sid_b,
    const float* __restrict__ rp_w, const float* __restrict__ rp_b,
    const float* __restrict__ eps_rp, const float* __restrict__ eps_rp1,
    float* __restrict__ out) {
    int gw = (blockIdx.x * blockDim.x + threadIdx.x) >> 5;
    int lane = threadIdx.x & 31;
    if (gw >= B_N) return;
    size_t off = (size_t)gw * 256;
    float* o = out + (size_t)gw * 15;
    for (int q = 0; q < 3; q++) {
        float s = warp_dot256(h0 + off, pid_w + q * 256, lane);
        if (lane == 0) o[q] = s + pid_b[q];
    }
    for (int q = 0; q < 2; q++) {
        float s = warp_dot256(h1 + off, sid_w + q * 256, lane);
        if (lane == 0) o[3 + q] = s + sid_b[q];
    }
    {
        float d[4];
        #pragma unroll
        for (int q = 0; q < 4; q++) d[q] = warp_dot256(h2 + off, rp_w + q * 256, lane);
        if (lane == 0) {
            o[5] = d[0] + rp_b[0] + __expf(d[2] + rp_b[2]) * eps_rp[(size_t)gw * 2 + 0];
            o[6] = d[1] + rp_b[1] + __expf(d[3] + rp_b[3]) * eps_rp[(size_t)gw * 2 + 1];
        }
    }
    for (int q = 0; q < 2; q++) {
        float s = warp_dot256(h1b + off, sid_w + q * 256, lane);
        if (lane == 0) o[7 + q] = s + sid_b[q];
    }
    for (int q = 0; q < 2; q++) {
        float s = warp_dot256(h2b + off, sid_w + q * 256, lane);
        if (lane == 0) o[9 + q] = s + sid_b[q];
    }
    {
        float d[4];
        #pragma unroll
        for (int q = 0; q < 4; q++) d[q] = warp_dot256(h4b + off, rp_w + q * 256, lane);
        if (lane == 0) {
            o[13] = d[0] + rp_b[0] + __expf(d[2] + rp_b[2]) * eps_rp1[(size_t)gw * 2 + 0];
            o[14] = d[1] + rp_b[1] + __expf(d[3] + rp_b[3]) * eps_rp1[(size_t)gw * 2 + 1];
        }
    }
}

// ---------------- MLP: rp0(2) -> 100 -> 100 -> 16 ----------------
__global__ void mlp1_kernel(const float* __restrict__ rp0, const float* __restrict__ w1,
                            const float* __restrict__ b1, float* __restrict__ z1) {
    int i = blockIdx.x * blockDim.x + threadIdx.x;
    if (i >= B_N * 100) return;
    int b = i / 100, j = i - b * 100;
    float v = rp0[b * 2] * w1[j * 2] + rp0[b * 2 + 1] * w1[j * 2 + 1] + b1[j];
    z1[i] = tanh_fast(v);
}

__global__ void __launch_bounds__(128) mlp2_kernel(const float* __restrict__ z1, const float* __restrict__ w2,
                                                   const float* __restrict__ b2, float* __restrict__ z2) {
    __shared__ float w2s[100 * 101];
    __shared__ float z1s[8 * 100];
    __shared__ float b2s[100];
    int tid = threadIdx.x;
    int b0 = blockIdx.x * 8;
    for (int i = tid; i < 100 * 100; i += 128) { int j = i / 100, k = i - j * 100; w2s[j * 101 + k] = w2[i]; }
    for (int i = tid; i < 800; i += 128) z1s[i] = z1[(size_t)b0 * 100 + i];
    for (int i = tid; i < 100; i += 128) b2s[i] = b2[i];
    __syncthreads();
    for (int t = tid; t < 800; t += 128) {
        int r = t / 100, j = t - r * 100;
        float s = b2s[j];
        const float* zz = z1s + r * 100;
        const float* ww = w2s + j * 101;
        #pragma unroll 4
        for (int k = 0; k < 100; k++) s += zz[k] * ww[k];
        z2[(size_t)(b0 + r) * 100 + j] = tanh_fast(s);
    }
}

__global__ void mlp3_kernel(const float* __restrict__ z2, const float* __restrict__ w3,
                            const float* __restrict__ b3, float* __restrict__ remb) {
    int i = blockIdx.x * blockDim.x + threadIdx.x;
    if (i >= B_N * 16) return;
    int b = i >> 4, o = i & 15;
    float s = b3[o];
    const float* zz = z2 + (size_t)b * 100;
    const float* ww = w3 + o * 100;
    #pragma unroll 4
    for (int k = 0; k < 100; k++) s += zz[k] * ww[k];
    remb[i] = s;
}

// ---------------- host ----------------
static float* getsym(const void* symbol) {
    void* p = nullptr;
    cudaGetSymbolAddress(&p, symbol);
    return (float*)p;
}

extern "C" void kernel_launch(void* const* d_in, const int* in_sizes, int n_in,
                              void* d_out, int out_size) {
    const float* obs        = (const float*)d_in[0];
    const int*   program_id = (const int*)  d_in[1];
    const int*   shape_id   = (const int*)  d_in[2];
    const int*   shape_id_0 = (const int*)  d_in[3];
    const int*   shape_id_1 = (const int*)  d_in[4];
    const float* eps_rp     = (const float*)d_in[5];
    const float* eps_rp0    = (const float*)d_in[6];
    const float* eps_rp1    = (const float*)d_in[7];
    const float* conv1_w    = (const float*)d_in[8];
    const float* conv1_b    = (const float*)d_in[9];
    const float* conv2_w    = (const float*)d_in[10];
    const float* conv2_b    = (const float*)d_in[11];
    const float* mlp_w1     = (const float*)d_in[12];
    const float* mlp_b1     = (const float*)d_in[13];
    const float* mlp_w2     = (const float*)d_in[14];
    const float* mlp_b2     = (const float*)d_in[15];
    const float* mlp_w3     = (const float*)d_in[16];
    const float* mlp_b3     = (const float*)d_in[17];
    const float* W_ih       = (const float*)d_in[18];
    const float* b_ih       = (const float*)d_in[19];
    const float* W_hh       = (const float*)d_in[20];
    const float* b_hh       = (const float*)d_in[21];
    const float* addr_emb   = (const float*)d_in[22];
    const float* pid_emb    = (const float*)d_in[23];
    const float* sid_emb    = (const float*)d_in[24];
    const float* pid_ext_w  = (const float*)d_in[25];
    const float* pid_ext_b  = (const float*)d_in[26];
    const float* sid_ext_w  = (const float*)d_in[27];
    const float* sid_ext_b  = (const float*)d_in[28];
    const float* rp_ext_w   = (const float*)d_in[29];
    const float* rp_ext_b   = (const float*)d_in[30];
    float* out = (float*)d_out;

    float* st      = getsym(g_state);
    const int SZ   = B_N * HID;
    float* h0  = st + 0 * SZ;  float* c0  = st + 1 * SZ;
    float* h1  = st + 2 * SZ;  float* c1  = st + 3 * SZ;
    float* h1b = st + 4 * SZ;  float* c1b = st + 5 * SZ;
    float* h2  = st + 6 * SZ;  float* c2  = st + 7 * SZ;
    float* h2b = st + 8 * SZ;  float* c2b = st + 9 * SZ;
    float* h3b = st + 10 * SZ; float* c3b = st + 11 * SZ;
    float* h4b = st + 12 * SZ; float* c4b = st + 13 * SZ;

    float* samp   = getsym(g_samp);
    float* s_pid  = samp + 0 * B_N * 16;
    float* s_sid  = samp + 1 * B_N * 16;
    float* s_sid0 = samp + 2 * B_N * 16;
    float* s_sid1 = samp + 3 * B_N * 16;

    float* obs_e  = getsym(g_obs_emb);
    float* xpre   = getsym(g_xpre);
    float* WhhT   = getsym(g_WhhT);
    float* W0T    = getsym(g_W0T);
    float* WextT  = getsym(g_WextT);
    float* bias   = getsym(g_bias);
    float* rp0    = getsym(g_rp0);
    float* z1     = getsym(g_z1);
    float* z2     = getsym(g_z2);
    float* rp0emb = getsym(g_rp0emb);

    const int CONV_SMEM = (4096 + 288 + 32 + 4608 + 16 + CONV_CH * 1024 + 4096) * 4;
    cudaFuncSetAttribute(conv_fused_kernel, cudaFuncAttributeMaxDynamicSharedMemorySize, CONV_SMEM);

    prep_weights_kernel<<<512, 256>>>(W_ih, b_ih, W_hh, b_hh, WhhT, W0T, WextT, bias);
    gather_kernel<<<B_N * 16 / 256, 256>>>(program_id, shape_id, shape_id_0, shape_id_1,
                                           pid_emb, sid_emb, s_pid, s_sid, s_sid0, s_sid1);
    conv_fused_kernel<<<B_N, 256, CONV_SMEM>>>(obs, conv1_w, conv1_b, conv2_w, conv2_b, obs_e);
    gemm_xpre_tf32_kernel<<<dim3(4, B_N / 64), 256>>>(obs_e, W0T, bias, xpre);

    dim3 t1(4, B_N / 64, 1);
    dim3 t2(4, B_N / 64, 2);
    // step0: h=c=0, samp=0, aid=0
    lstm_step_tf32_kernel<<<t1, 256>>>(xpre, WhhT, WextT, addr_emb,
        nullptr, nullptr, nullptr, 0, h0, c0,
        nullptr, nullptr, nullptr, 0, nullptr, nullptr);
    // pair: step1A (aid=1) + step1B (aid=2), both from (h0,c0,s_pid)
    lstm_step_tf32_kernel<<<t2, 256>>>(xpre, WhhT, WextT, addr_emb,
        h0, c0, s_pid, 1, h1, c1,
        h0, c0, s_pid, 2, h1b, c1b);
    // pair: step2A (h1,s_sid,aid=4) + step2B (h1b,s_sid0,aid=3)
    lstm_step_tf32_kernel<<<t2, 256>>>(xpre, WhhT, WextT, addr_emb,
        h1, c1, s_sid, 4, h2, c2,
        h1b, c1b, s_sid0, 3, h2b, c2b);
    // step3B
    lstm_step_tf32_kernel<<<t1, 256>>>(xpre, WhhT, WextT, addr_emb,
        h2b, c2b, s_sid1, 5, h3b, c3b,
        nullptr, nullptr, nullptr, 0, nullptr, nullptr);
    head_rp_kernel<<<B_N / 8, 256>>>(h3b, rp_ext_w, rp_ext_b, eps_rp0, 11, out, rp0);
    // MLP on rp0
    mlp1_kernel<<<(B_N * 100 + 255) / 256, 256>>>(rp0, mlp_w1, mlp_b1, z1);
    mlp2_kernel<<<B_N / 8, 128>>>(z1, mlp_w2, mlp_b2, z2);
    mlp3_kernel<<<B_N * 16 / 256, 256>>>(z2, mlp_w3, mlp_b3, rp0emb);
    // step4B
    lstm_step_tf32_kernel<<<t1, 256>>>(xpre, WhhT, WextT, addr_emb,
        h3b, c3b, rp0emb, 6, h4b, c4b,
        nullptr, nullptr, nullptr, 0, nullptr, nullptr);
    // all remaining heads
    final_heads_kernel<<<B_N / 8, 256>>>(h0, h1, h2, h1b, h2b, h4b,
        pid_ext_w, pid_ext_b, sid_ext_w, sid_ext_b, rp_ext_w, rp_ext_b,
        eps_rp, eps_rp1, out);
}

// round 9
// speedup vs baseline: 3.2038x; 1.1765x over previous
#include <cuda_runtime.h>
#include <cstddef>
#include <cstdint>

#define B_N 4096
#define HID 256
#define OBS_D 400
#define IN_D 432

// ---------------- scratch (device globals; no allocation allowed) ----------------
__device__ float g_state[14 * B_N * HID];
__device__ float g_samp[4 * B_N * 16];      // prev_pid, samp_sid, samp_sid0, samp_sid1
__device__ float g_obs_emb[B_N * OBS_D];
__device__ float g_xpre[B_N * 1024];
__device__ float g_WhhT[256 * 1024];
__device__ float g_W0T[400 * 1024];
__device__ float g_WextT[32 * 1024];        // rows 0..15: samp cols of W_ih; 16..31: addr cols
__device__ float g_bias[1024];              // b_ih + b_hh
__device__ float g_rp0[B_N * 2];
__device__ float g_z1[B_N * 100];
__device__ float g_z2[B_N * 100];
__device__ float g_rp0emb[B_N * 16];

__device__ __forceinline__ float sigf(float x) { return 1.f / (1.f + __expf(-x)); }
__device__ __forceinline__ float tanh_fast(float x) { return 2.f / (1.f + __expf(-2.f * x)) - 1.f; }

#define MMA_TF32(c, a, b) \
    asm volatile("mma.sync.aligned.m16n8k8.row.col.f32.tf32.tf32.f32 " \
        "{%0,%1,%2,%3}, {%4,%5,%6,%7}, {%8,%9}, {%0,%1,%2,%3};" \
        : "+f"((c)[0]), "+f"((c)[1]), "+f"((c)[2]), "+f"((c)[3]) \
        : "r"((a)[0]), "r"((a)[1]), "r"((a)[2]), "r"((a)[3]), "r"((b)[0]), "r"((b)[1]))

__device__ __forceinline__ void cp16(uint32_t smem_addr, const void* gptr) {
    asm volatile("cp.async.cg.shared.global [%0], [%1], 16;" :: "r"(smem_addr), "l"(gptr));
}
#define CP_COMMIT() asm volatile("cp.async.commit_group;")
#define CP_WAIT0()  asm volatile("cp.async.wait_group 0;" ::: "memory")

// ---------------- weight prep: transposes for coalesced GEMM loads ----------------
__global__ void prep_weights_kernel(const float* __restrict__ W_ih, const float* __restrict__ b_ih,
                                    const float* __restrict__ W_hh, const float* __restrict__ b_hh,
                                    float* __restrict__ WhhT, float* __restrict__ W0T,
                                    float* __restrict__ WextT, float* __restrict__ bias) {
    int idx = blockIdx.x * blockDim.x + threadIdx.x;
    int stride = gridDim.x * blockDim.x;
    for (int i = idx; i < 256 * 1024; i += stride) { int k = i >> 10, j = i & 1023; WhhT[i] = W_hh[(size_t)j * 256 + k]; }
    for (int i = idx; i < 400 * 1024; i += stride) { int k = i >> 10, j = i & 1023; W0T[i] = W_ih[(size_t)j * IN_D + k]; }
    for (int i = idx; i < 32 * 1024;  i += stride) { int k = i >> 10, j = i & 1023; WextT[i] = W_ih[(size_t)j * IN_D + 400 + k]; }
    for (int i = idx; i < 1024; i += stride) bias[i] = b_ih[i] + b_hh[i];
}

// ---------------- embedding gathers ----------------
__global__ void gather_kernel(const int* __restrict__ pid, const int* __restrict__ sid,
                              const int* __restrict__ sid0, const int* __restrict__ sid1,
                              const float* __restrict__ pid_emb, const float* __restrict__ sid_emb,
                              float* __restrict__ s_pid, float* __restrict__ s_sid,
                              float* __restrict__ s_sid0, float* __restrict__ s_sid1) {
    int i = blockIdx.x * blockDim.x + threadIdx.x;
    if (i >= B_N * 16) return;
    int b = i >> 4, k = i & 15;
    s_pid[i]  = pid_emb[pid[b]  * 16 + k];
    s_sid[i]  = sid_emb[sid[b]  * 16 + k];
    s_sid0[i] = sid_emb[sid0[b] * 16 + k];
    s_sid1[i] = sid_emb[sid1[b] * 16 + k];
}

// ---------------- fused conv: scalar conv1 + tf32-mma conv2 + pool ----------------
// conv2 as per-sample implicit GEMM: M=256 outputs (16x16), N=16 oc, K=288 (32ic*9).
// conv1 output stored zero-haloed [ch][33][33] so the A-gather needs no bounds checks.
// smem word layout:
//   s_in 4096 | s_w1 288 | s_b1 32 | s_w2 4608 | s_b2 16 | s_ko 72 | s_w2p 1224 | s_c1p 8712 | s_c2 4096
#define CONV_SMEM_WORDS (4096 + 288 + 32 + 4608 + 16 + 72 + 1224 + 8712 + 4096)
__global__ void __launch_bounds__(256, 2) conv_fused_kernel(
    const float* __restrict__ obs, const float* __restrict__ w1, const float* __restrict__ b1,
    const float* __restrict__ w2, const float* __restrict__ b2, float* __restrict__ obs_emb) {
    extern __shared__ float sm[];
    float* s_in  = sm;
    float* s_w1  = s_in + 4096;
    float* s_b1  = s_w1 + 288;
    float* s_w2  = s_b1 + 32;
    float* s_b2  = s_w2 + 4608;
    int*   s_ko  = (int*)(s_b2 + 16);      // 72-entry k -> (icl,dy,dx) offset LUT
    float* s_w2p = s_b2 + 16 + 72;         // [72][17] per-chunk B panel
    float* s_c1p = s_w2p + 1224;           // 8 ch x 33 x 33 padded conv1 chunk
    float* s_c2  = s_c1p + 8712;           // [16 oc][256]
    int tid = threadIdx.x;
    int b = blockIdx.x;
    const float* in = obs + (size_t)b * 4096;
    for (int i = tid; i < 1024; i += 256) ((float4*)s_in)[i] = ((const float4*)in)[i];
    for (int i = tid; i < 288; i += 256) s_w1[i] = w1[i];
    for (int i = tid; i < 32; i += 256) s_b1[i] = b1[i];
    for (int i = tid; i < 4608; i += 256) s_w2[i] = w2[i];
    for (int i = tid; i < 16; i += 256) s_b2[i] = b2[i];
    for (int i = tid; i < 8712; i += 256) s_c1p[i] = 0.f;   // halo stays zero forever
    if (tid < 72) {
        int icl = tid / 9, rem = tid - icl * 9, dy = rem / 3, dx = rem - dy * 3;
        s_ko[tid] = icl * 1089 + dy * 33 + dx;
    }
    __syncthreads();

    const int lane = tid & 31, w = tid >> 5;
    const int grp = lane >> 2, tig = lane & 3;

    // conv1 per-thread 2x2 output tile; input patch hoisted (single input channel)
    const int c1y = ((tid >> 4) & 15) * 2;
    const int c1x = (tid & 15) * 2;
    const int c1iy0 = c1y * 2 - 1;
    const int c1ix0 = c1x * 2 - 1;
    float inp1[5][5];
    #pragma unroll
    for (int r = 0; r < 5; r++) {
        int iy = c1iy0 + r;
        bool okr = (unsigned)iy < 64u;
        #pragma unroll
        for (int q = 0; q < 5; q++) {
            int ix = c1ix0 + q;
            inp1[r][q] = (okr && (unsigned)ix < 64u) ? s_in[iy * 64 + ix] : 0.f;
        }
    }

    // conv2 accumulators: warp w owns m-tiles 2w, 2w+1 (oy = mtile); both n-tiles (oc 0-7, 8-15)
    float acc[2][2][4];
    #pragma unroll
    for (int mt = 0; mt < 2; mt++)
        #pragma unroll
        for (int t = 0; t < 2; t++)
            #pragma unroll
            for (int q = 0; q < 4; q++) acc[mt][t][q] = 0.f;

    for (int cc = 0; cc < 4; cc++) {
        // conv1: 8 channels of this chunk into padded layout
        #pragma unroll
        for (int it = 0; it < 8; it++) {
            int oc = cc * 8 + it;
            float wv[9];
            #pragma unroll
            for (int q = 0; q < 9; q++) wv[q] = s_w1[oc * 9 + q];   // broadcast
            float bb = s_b1[oc];
            #pragma unroll
            for (int sy = 0; sy < 2; sy++)
                #pragma unroll
                for (int sx = 0; sx < 2; sx++) {
                    float a = bb;
                    #pragma unroll
                    for (int dy = 0; dy < 3; dy++)
                        #pragma unroll
                        for (int dx = 0; dx < 3; dx++)
                            a += wv[dy * 3 + dx] * inp1[sy * 2 + dy][sx * 2 + dx];
                    s_c1p[it * 1089 + (c1y + sy + 1) * 33 + (c1x + sx + 1)] = fmaxf(a, 0.f);
                }
        }
        // B panel for this chunk: w2p[k][n], k = icl*9 + tap, n = oc (coalesced smem reads)
        for (int i = tid; i < 1152; i += 256) {
            int n = i / 72, k = i - n * 72;
            s_w2p[k * 17 + n] = s_w2[n * 288 + cc * 72 + k];
        }
        __syncthreads();
        // implicit-GEMM mma over this chunk's K=72 (9 k8-slabs)
        #pragma unroll
        for (int kk = 0; kk < 9; kk++) {
            int kb = kk * 8;
            int ko1 = s_ko[kb + tig], ko2 = s_ko[kb + tig + 4];
            uint32_t a[2][4], bf[2][2];
            #pragma unroll
            for (int mt = 0; mt < 2; mt++) {
                int mtile = w * 2 + mt;
                int base1 = mtile * 66 + grp * 2;          // oy*66 + ox*2, ox=grp
                int base2 = mtile * 66 + (grp + 8) * 2;    // ox=grp+8
                a[mt][0] = __float_as_uint(s_c1p[ko1 + base1]);
                a[mt][1] = __float_as_uint(s_c1p[ko1 + base2]);
                a[mt][2] = __float_as_uint(s_c1p[ko2 + base1]);
                a[mt][3] = __float_as_uint(s_c1p[ko2 + base2]);
            }
            #pragma unroll
            for (int t = 0; t < 2; t++) {
                bf[t][0] = __float_as_uint(s_w2p[(kb + tig) * 17 + t * 8 + grp]);
                bf[t][1] = __float_as_uint(s_w2p[(kb + tig + 4) * 17 + t * 8 + grp]);
            }
            #pragma unroll
            for (int mt = 0; mt < 2; mt++)
                #pragma unroll
                for (int t = 0; t < 2; t++)
                    MMA_TF32(acc[mt][t], a[mt], bf[t]);
        }
        __syncthreads();  // protect s_c1p/w2p overwrite next chunk
    }

    // epilogue: bias + relu, scatter C fragments to s_c2[oc][m]
    #pragma unroll
    for (int mt = 0; mt < 2; mt++) {
        int mtile = w * 2 + mt;
        int m1 = mtile * 16 + grp, m2 = m1 + 8;
        #pragma unroll
        for (int t = 0; t < 2; t++) {
            int oc0 = t * 8 + 2 * tig;
            float bb0 = s_b2[oc0], bb1 = s_b2[oc0 + 1];
            s_c2[oc0 * 256 + m1]       = fmaxf(acc[mt][t][0] + bb0, 0.f);
            s_c2[(oc0 + 1) * 256 + m1] = fmaxf(acc[mt][t][1] + bb1, 0.f);
            s_c2[oc0 * 256 + m2]       = fmaxf(acc[mt][t][2] + bb0, 0.f);
            s_c2[(oc0 + 1) * 256 + m2] = fmaxf(acc[mt][t][3] + bb1, 0.f);
        }
    }
    __syncthreads();
    // avg pool 3x3 stride 3 VALID -> (16,5,5) -> 400
    for (int o = tid; o < 400; o += 256) {
        int c = o / 25;
        int rem = o - c * 25;
        int py = rem / 5, px = rem - (rem / 5) * 5;
        float s = 0.f;
        #pragma unroll
        for (int dy = 0; dy < 3; dy++)
            #pragma unroll
            for (int dx = 0; dx < 3; dx++)
                s += s_c2[c * 256 + (py * 3 + dy) * 16 + (px * 3 + dx)];
        obs_emb[(size_t)b * OBS_D + o] = s * (1.f / 9.f);
    }
}

// ---------------- tf32 GEMM phase v2: m64 x 256 cols, cp.async double-buffered ----------------
__device__ __forceinline__ void tf32_gemm_phase(
    const float* __restrict__ A, int astride,
    const float* __restrict__ Bsrc, int nslabs, int u_base,
    uint32_t* __restrict__ sm, uint32_t smaddr,
    float acc[2][8][4],
    int tid, int grp, int tig, int mrow_base, int u_warp)
{
    const int am = tid >> 2, ak = (tid & 3) * 4;
    const int bkr = tid >> 4, bc0 = (tid & 15) * 16;
    const int bj = ((bc0 >> 6) << 8) + u_base + (bc0 & 63);
    uint32_t* sAp[2] = { sm, sm + 1280 };
    uint32_t* sBp[2] = { sm + 2560, sm + 2560 + 4224 };
    const uint32_t sAo[2] = { smaddr, smaddr + 5120u };
    const uint32_t sBo[2] = { smaddr + 10240u, smaddr + 10240u + 16896u };

    cp16(sAo[0] + (uint32_t)(am * 20 + ak) * 4u, A + (size_t)am * astride + ak);
    {
        const float* bp = Bsrc + (size_t)bkr * 1024 + bj;
        #pragma unroll
        for (int q = 0; q < 4; q++)
            cp16(sBo[0] + (uint32_t)(bkr * 264 + bc0 + q * 4) * 4u, bp + q * 4);
    }
    CP_COMMIT();

    for (int s = 0; s < nslabs; s++) {
        CP_WAIT0();
        __syncthreads();
        if (s + 1 < nslabs) {
            int nb = (s + 1) & 1;
            cp16(sAo[nb] + (uint32_t)(am * 20 + ak) * 4u, A + (size_t)am * astride + (s + 1) * 16 + ak);
            const float* bp = Bsrc + (size_t)((s + 1) * 16 + bkr) * 1024 + bj;
            #pragma unroll
            for (int q = 0; q < 4; q++)
                cp16(sBo[nb] + (uint32_t)(bkr * 264 + bc0 + q * 4) * 4u, bp + q * 4);
            CP_COMMIT();
        }
        const uint32_t* cA = sAp[s & 1];
        const uint32_t* cB = sBp[s & 1];
        #pragma unroll
        for (int k8 = 0; k8 < 16; k8 += 8) {
            uint32_t a[2][4], b[8][2];
            #pragma unroll
            for (int mi = 0; mi < 2; mi++) {
                int r = mrow_base + mi * 16 + grp;
                a[mi][0] = cA[r * 20 + k8 + tig];
                a[mi][1] = cA[(r + 8) * 20 + k8 + tig];
                a[mi][2] = cA[r * 20 + k8 + tig + 4];
                a[mi][3] = cA[(r + 8) * 20 + k8 + tig + 4];
            }
            #pragma unroll
            for (int t = 0; t < 8; t++) {
                int col = (t >> 1) * 64 + u_warp + (t & 1) * 8 + grp;
                b[t][0] = cB[(k8 + tig) * 264 + col];
                b[t][1] = cB[(k8 + tig + 4) * 264 + col];
            }
            #pragma unroll
            for (int mi = 0; mi < 2; mi++)
                #pragma unroll
                for (int t = 0; t < 8; t++)
                    MMA_TF32(acc[mi][t], a[mi], b[t]);
        }
        __syncthreads();
    }
}

// ---------------- xpre = obs_emb @ W0T + bias (tf32 v2) ----------------
__global__ void __launch_bounds__(256, 2) gemm_xpre_tf32_kernel(
    const float* __restrict__ A, const float* __restrict__ W0T,
    const float* __restrict__ bias, float* __restrict__ out) {
    __shared__ __align__(16) uint32_t sm[2 * 1280 + 2 * 4224];
    uint32_t smaddr = (uint32_t)__cvta_generic_to_shared(sm);

    const int tid = threadIdx.x;
    const int lane = tid & 31, w = tid >> 5;
    const int grp = lane >> 2, tig = lane & 3;
    const int mrow_base = (w >> 2) * 32;
    const int u_warp = (w & 3) * 16;
    const int u_base = blockIdx.x * 64;
    const int row0 = blockIdx.y * 64;

    float acc[2][8][4];
    #pragma unroll
    for (int mi = 0; mi < 2; mi++)
        #pragma unroll
        for (int t = 0; t < 8; t++)
            #pragma unroll
            for (int q = 0; q < 4; q++) acc[mi][t][q] = 0.f;

    tf32_gemm_phase(A + (size_t)row0 * OBS_D, OBS_D, W0T, 25, u_base, sm, smaddr,
                    acc, tid, grp, tig, mrow_base, u_warp);

    #pragma unroll
    for (int mi = 0; mi < 2; mi++)
        #pragma unroll
        for (int rr = 0; rr < 2; rr++) {
            size_t b = (size_t)(row0 + mrow_base + mi * 16 + grp + rr * 8);
            #pragma unroll
            for (int t = 0; t < 8; t++) {
                int g = t >> 1, uh = t & 1;
                int col = g * 256 + u_base + u_warp + uh * 8 + 2 * tig;
                float2 bv = *(const float2*)&bias[col];
                float2 o = make_float2(acc[mi][t][rr * 2 + 0] + bv.x, acc[mi][t][rr * 2 + 1] + bv.y);
                *(float2*)&out[b * 1024 + col] = o;
            }
        }
}

// ---------------- tf32 LSTM step v2: GEMM + register-resident gate epilogue ----------------
__global__ void __launch_bounds__(256, 2) lstm_step_tf32_kernel(
    const float* __restrict__ xpre,
    const float* __restrict__ WhhT, const float* __restrict__ WextT,
    const float* __restrict__ addr_emb,
    const float* h_inA, const float* c_inA, const float* sampA, int aidA, float* h_outA, float* c_outA,
    const float* h_inB, const float* c_inB, const float* sampB, int aidB, float* h_outB, float* c_outB) {
    __shared__ __align__(16) uint32_t sm[2 * 1280 + 2 * 4224];
    uint32_t smaddr = (uint32_t)__cvta_generic_to_shared(sm);

    const float* h_in; const float* c_in; const float* samp; int aid; float* h_out; float* c_out;
    if (blockIdx.z == 0) { h_in = h_inA; c_in = c_inA; samp = sampA; aid = aidA; h_out = h_outA; c_out = c_outA; }
    else                 { h_in = h_inB; c_in = c_inB; samp = sampB; aid = aidB; h_out = h_outB; c_out = c_outB; }

    const int tid = threadIdx.x;
    const int lane = tid & 31, w = tid >> 5;
    const int grp = lane >> 2, tig = lane & 3;
    const int mrow_base = (w >> 2) * 32;
    const int u_warp = (w & 3) * 16;
    const int u_base = blockIdx.x * 64;
    const int row0 = blockIdx.y * 64;

    float acc[2][8][4];
    #pragma unroll
    for (int mi = 0; mi < 2; mi++)
        #pragma unroll
        for (int t = 0; t < 8; t++)
            #pragma unroll
            for (int q = 0; q < 4; q++) acc[mi][t][q] = 0.f;

    if (h_in) tf32_gemm_phase(h_in + (size_t)row0 * 256, 256, WhhT, 16, u_base, sm, smaddr,
                              acc, tid, grp, tig, mrow_base, u_warp);
    if (samp) tf32_gemm_phase(samp + (size_t)row0 * 16, 16, WextT, 1, u_base, sm, smaddr,
                              acc, tid, grp, tig, mrow_base, u_warp);
    tf32_gemm_phase(addr_emb + aid * 16, 0, WextT + 16 * 1024, 1, u_base, sm, smaddr,
                    acc, tid, grp, tig, mrow_base, u_warp);

    const int ub = u_base + u_warp;
    #pragma unroll
    for (int mi = 0; mi < 2; mi++)
        #pragma unroll
        for (int rr = 0; rr < 2; rr++) {
            size_t b = (size_t)(row0 + mrow_base + mi * 16 + grp + rr * 8);
            const float* xp = xpre + b * 1024;
            #pragma unroll
            for (int uh = 0; uh < 2; uh++) {
                int ug = ub + uh * 8 + 2 * tig;
                float2 xi = *(const float2*)&xp[0 * 256 + ug];
                float2 xf = *(const float2*)&xp[1 * 256 + ug];
                float2 xg = *(const float2*)&xp[2 * 256 + ug];
                float2 xo = *(const float2*)&xp[3 * 256 + ug];
                float2 cold = c_in ? *(const float2*)&c_in[b * 256 + ug] : make_float2(0.f, 0.f);
                int q0 = rr * 2;
                float i0 = sigf(acc[mi][0 + uh][q0]     + xi.x);
                float i1 = sigf(acc[mi][0 + uh][q0 + 1] + xi.y);
                float f0 = sigf(acc[mi][2 + uh][q0]     + xf.x);
                float f1 = sigf(acc[mi][2 + uh][q0 + 1] + xf.y);
                float g0 = tanh_fast(acc[mi][4 + uh][q0]     + xg.x);
                float g1 = tanh_fast(acc[mi][4 + uh][q0 + 1] + xg.y);
                float o0 = sigf(acc[mi][6 + uh][q0]     + xo.x);
                float o1 = sigf(acc[mi][6 + uh][q0 + 1] + xo.y);
                float cn0 = f0 * cold.x + i0 * g0;
                float cn1 = f1 * cold.y + i1 * g1;
                *(float2*)&c_out[b * 256 + ug] = make_float2(cn0, cn1);
                *(float2*)&h_out[b * 256 + ug] = make_float2(o0 * tanh_fast(cn0), o1 * tanh_fast(cn1));
            }
        }
}

// ---------------- heads ----------------
__device__ __forceinline__ float warp_dot256(const float* __restrict__ h, const float* __restrict__ w, int lane) {
    const float* hp = h + lane * 8;
    const float* wp = w + lane * 8;
    float4 a0 = *(const float4*)hp;
    float4 a1 = *(const float4*)(hp + 4);
    float4 b0 = *(const float4*)wp;
    float4 b1 = *(const float4*)(wp + 4);
    float s = a0.x * b0.x + a0.y * b0.y + a0.z * b0.z + a0.w * b0.w
            + a1.x * b1.x + a1.y * b1.y + a1.z * b1.z + a1.w * b1.w;
    #pragma unroll
    for (int off = 16; off; off >>= 1) s += __shfl_down_sync(0xffffffffu, s, off);
    return s;  // valid on lane 0
}

__global__ void head_rp_kernel(const float* __restrict__ h, const float* __restrict__ W,
                               const float* __restrict__ bias, const float* __restrict__ eps,
                               int col0, float* __restrict__ out, float* __restrict__ save) {
    int gw = (blockIdx.x * blockDim.x + threadIdx.x) >> 5;
    int lane = threadIdx.x & 31;
    if (gw >= B_N) return;
    const float* hp = h + (size_t)gw * 256;
    float d[4];
    #pragma unroll
    for (int o = 0; o < 4; o++) d[o] = warp_dot256(hp, W + o * 256, lane);
    if (lane == 0) {
        float r0 = d[0] + bias[0] + __expf(d[2] + bias[2]) * eps[(size_t)gw * 2 + 0];
        float r1 = d[1] + bias[1] + __expf(d[3] + bias[3]) * eps[(size_t)gw * 2 + 1];
        out[(size_t)gw * 15 + col0 + 0] = r0;
        out[(size_t)gw * 15 + col0 + 1] = r1;
        if (save) { save[(size_t)gw * 2 + 0] = r0; save[(size_t)gw * 2 + 1] = r1; }
    }
}

__global__ void final_heads_kernel(
    const float* __restrict__ h0, const float* __restrict__ h1, const float* __restrict__ h2,
    const float* __restrict__ h1b, const float* __restrict__ h2b, const float* __restrict__ h4b,
    const float* __restrict__ pid_w, const float* __restrict__ pid_b,
    const float* __restrict__ sid_w, const float* __restrict__ sid_b,
    const float* __restrict__ rp_w, const float* __restrict__ rp_b,
    const float* __restrict__ eps_rp, const float* __restrict__ eps_rp1,
    float* __restrict__ out) {
    int gw = (blockIdx.x * blockDim.x + threadIdx.x) >> 5;
    int lane = threadIdx.x & 31;
    if (gw >= B_N) return;
    size_t off = (size_t)gw * 256;
    float* o = out + (size_t)gw * 15;
    for (int q = 0; q < 3; q++) {
        float s = warp_dot256(h0 + off, pid_w + q * 256, lane);
        if (lane == 0) o[q] = s + pid_b[q];
    }
    for (int q = 0; q < 2; q++) {
        float s = warp_dot256(h1 + off, sid_w + q * 256, lane);
        if (lane == 0) o[3 + q] = s + sid_b[q];
    }
    {
        float d[4];
        #pragma unroll
        for (int q = 0; q < 4; q++) d[q] = warp_dot256(h2 + off, rp_w + q * 256, lane);
        if (lane == 0) {
            o[5] = d[0] + rp_b[0] + __expf(d[2] + rp_b[2]) * eps_rp[(size_t)gw * 2 + 0];
            o[6] = d[1] + rp_b[1] + __expf(d[3] + rp_b[3]) * eps_rp[(size_t)gw * 2 + 1];
        }
    }
    for (int q = 0; q < 2; q++) {
        float s = warp_dot256(h1b + off, sid_w + q * 256, lane);
        if (lane == 0) o[7 + q] = s + sid_b[q];
    }
    for (int q = 0; q < 2; q++) {
        float s = warp_dot256(h2b + off, sid_w + q * 256, lane);
        if (lane == 0) o[9 + q] = s + sid_b[q];
    }
    {
        float d[4];
        #pragma unroll
        for (int q = 0; q < 4; q++) d[q] = warp_dot256(h4b + off, rp_w + q * 256, lane);
        if (lane == 0) {
            o[13] = d[0] + rp_b[0] + __expf(d[2] + rp_b[2]) * eps_rp1[(size_t)gw * 2 + 0];
            o[14] = d[1] + rp_b[1] + __expf(d[3] + rp_b[3]) * eps_rp1[(size_t)gw * 2 + 1];
        }
    }
}

// ---------------- MLP: rp0(2) -> 100 -> 100 -> 16 ----------------
__global__ void mlp1_kernel(const float* __restrict__ rp0, const float* __restrict__ w1,
                            const float* __restrict__ b1, float* __restrict__ z1) {
    int i = blockIdx.x * blockDim.x + threadIdx.x;
    if (i >= B_N * 100) return;
    int b = i / 100, j = i - b * 100;
    float v = rp0[b * 2] * w1[j * 2] + rp0[b * 2 + 1] * w1[j * 2 + 1] + b1[j];
    z1[i] = tanh_fast(v);
}

__global__ void __launch_bounds__(128) mlp2_kernel(const float* __restrict__ z1, const float* __restrict__ w2,
                                                   const float* __restrict__ b2, float* __restrict__ z2) {
    __shared__ float w2s[100 * 101];
    __shared__ float z1s[8 * 100];
    __shared__ float b2s[100];
    int tid = threadIdx.x;
    int b0 = blockIdx.x * 8;
    for (int i = tid; i < 100 * 100; i += 128) { int j = i / 100, k = i - j * 100; w2s[j * 101 + k] = w2[i]; }
    for (int i = tid; i < 800; i += 128) z1s[i] = z1[(size_t)b0 * 100 + i];
    for (int i = tid; i < 100; i += 128) b2s[i] = b2[i];
    __syncthreads();
    for (int t = tid; t < 800; t += 128) {
        int r = t / 100, j = t - r * 100;
        float s = b2s[j];
        const float* zz = z1s + r * 100;
        const float* ww = w2s + j * 101;
        #pragma unroll 4
        for (int k = 0; k < 100; k++) s += zz[k] * ww[k];
        z2[(size_t)(b0 + r) * 100 + j] = tanh_fast(s);
    }
}

__global__ void mlp3_kernel(const float* __restrict__ z2, const float* __restrict__ w3,
                            const float* __restrict__ b3, float* __restrict__ remb) {
    int i = blockIdx.x * blockDim.x + threadIdx.x;
    if (i >= B_N * 16) return;
    int b = i >> 4, o = i & 15;
    float s = b3[o];
    const float* zz = z2 + (size_t)b * 100;
    const float* ww = w3 + o * 100;
    #pragma unroll 4
    for (int k = 0; k < 100; k++) s += zz[k] * ww[k];
    remb[i] = s;
}

// ---------------- host ----------------
static float* getsym(const void* symbol) {
    void* p = nullptr;
    cudaGetSymbolAddress(&p, symbol);
    return (float*)p;
}

extern "C" void kernel_launch(void* const* d_in, const int* in_sizes, int n_in,
                              void* d_out, int out_size) {
    const float* obs        = (const float*)d_in[0];
    const int*   program_id = (const int*)  d_in[1];
    const int*   shape_id   = (const int*)  d_in[2];
    const int*   shape_id_0 = (const int*)  d_in[3];
    const int*   shape_id_1 = (const int*)  d_in[4];
    const float* eps_rp     = (const float*)d_in[5];
    const float* eps_rp0    = (const float*)d_in[6];
    const float* eps_rp1    = (const float*)d_in[7];
    const float* conv1_w    = (const float*)d_in[8];
    const float* conv1_b    = (const float*)d_in[9];
    const float* conv2_w    = (const float*)d_in[10];
    const float* conv2_b    = (const float*)d_in[11];
    const float* mlp_w1     = (const float*)d_in[12];
    const float* mlp_b1     = (const float*)d_in[13];
    const float* mlp_w2     = (const float*)d_in[14];
    const float* mlp_b2     = (const float*)d_in[15];
    const float* mlp_w3     = (const float*)d_in[16];
    const float* mlp_b3     = (const float*)d_in[17];
    const float* W_ih       = (const float*)d_in[18];
    const float* b_ih       = (const float*)d_in[19];
    const float* W_hh       = (const float*)d_in[20];
    const float* b_hh       = (const float*)d_in[21];
    const float* addr_emb   = (const float*)d_in[22];
    const float* pid_emb    = (const float*)d_in[23];
    const float* sid_emb    = (const float*)d_in[24];
    const float* pid_ext_w  = (const float*)d_in[25];
    const float* pid_ext_b  = (const float*)d_in[26];
    const float* sid_ext_w  = (const float*)d_in[27];
    const float* sid_ext_b  = (const float*)d_in[28];
    const float* rp_ext_w   = (const float*)d_in[29];
    const float* rp_ext_b   = (const float*)d_in[30];
    float* out = (float*)d_out;

    float* st      = getsym(g_state);
    const int SZ   = B_N * HID;
    float* h0  = st + 0 * SZ;  float* c0  = st + 1 * SZ;
    float* h1  = st + 2 * SZ;  float* c1  = st + 3 * SZ;
    float* h1b = st + 4 * SZ;  float* c1b = st + 5 * SZ;
    float* h2  = st + 6 * SZ;  float* c2  = st + 7 * SZ;
    float* h2b = st + 8 * SZ;  float* c2b = st + 9 * SZ;
    float* h3b = st + 10 * SZ; float* c3b = st + 11 * SZ;
    float* h4b = st + 12 * SZ; float* c4b = st + 13 * SZ;

    float* samp   = getsym(g_samp);
    float* s_pid  = samp + 0 * B_N * 16;
    float* s_sid  = samp + 1 * B_N * 16;
    float* s_sid0 = samp + 2 * B_N * 16;
    float* s_sid1 = samp + 3 * B_N * 16;

    float* obs_e  = getsym(g_obs_emb);
    float* xpre   = getsym(g_xpre);
    float* WhhT   = getsym(g_WhhT);
    float* W0T    = getsym(g_W0T);
    float* WextT  = getsym(g_WextT);
    float* bias   = getsym(g_bias);
    float* rp0    = getsym(g_rp0);
    float* z1     = getsym(g_z1);
    float* z2     = getsym(g_z2);
    float* rp0emb = getsym(g_rp0emb);

    const int CONV_SMEM = CONV_SMEM_WORDS * 4;
    cudaFuncSetAttribute(conv_fused_kernel, cudaFuncAttributeMaxDynamicSharedMemorySize, CONV_SMEM);

    prep_weights_kernel<<<512, 256>>>(W_ih, b_ih, W_hh, b_hh, WhhT, W0T, WextT, bias);
    gather_kernel<<<B_N * 16 / 256, 256>>>(program_id, shape_id, shape_id_0, shape_id_1,
                                           pid_emb, sid_emb, s_pid, s_sid, s_sid0, s_sid1);
    conv_fused_kernel<<<B_N, 256, CONV_SMEM>>>(obs, conv1_w, conv1_b, conv2_w, conv2_b, obs_e);
    gemm_xpre_tf32_kernel<<<dim3(4, B_N / 64), 256>>>(obs_e, W0T, bias, xpre);

    dim3 t1(4, B_N / 64, 1);
    dim3 t2(4, B_N / 64, 2);
    // step0: h=c=0, samp=0, aid=0
    lstm_step_tf32_kernel<<<t1, 256>>>(xpre, WhhT, WextT, addr_emb,
        nullptr, nullptr, nullptr, 0, h0, c0,
        nullptr, nullptr, nullptr, 0, nullptr, nullptr);
    // pair: step1A (aid=1) + step1B (aid=2), both from (h0,c0,s_pid)
    lstm_step_tf32_kernel<<<t2, 256>>>(xpre, WhhT, WextT, addr_emb,
        h0, c0, s_pid, 1, h1, c1,
        h0, c0, s_pid, 2, h1b, c1b);
    // pair: step2A (h1,s_sid,aid=4) + step2B (h1b,s_sid0,aid=3)
    lstm_step_tf32_kernel<<<t2, 256>>>(xpre, WhhT, WextT, addr_emb,
        h1, c1, s_sid, 4, h2, c2,
        h1b, c1b, s_sid0, 3, h2b, c2b);
    // step3B
    lstm_step_tf32_kernel<<<t1, 256>>>(xpre, WhhT, WextT, addr_emb,
        h2b, c2b, s_sid1, 5, h3b, c3b,
        nullptr, nullptr, nullptr, 0, nullptr, nullptr);
    head_rp_kernel<<<B_N / 8, 256>>>(h3b, rp_ext_w, rp_ext_b, eps_rp0, 11, out, rp0);
    // MLP on rp0
    mlp1_kernel<<<(B_N * 100 + 255) / 256, 256>>>(rp0, mlp_w1, mlp_b1, z1);
    mlp2_kernel<<<B_N / 8, 128>>>(z1, mlp_w2, mlp_b2, z2);
    mlp3_kernel<<<B_N * 16 / 256, 256>>>(z2, mlp_w3, mlp_b3, rp0emb);
    // step4B
    lstm_step_tf32_kernel<<<t1, 256>>>(xpre, WhhT, WextT, addr_emb,
        h3b, c3b, rp0emb, 6, h4b, c4b,
        nullptr, nullptr, nullptr, 0, nullptr, nullptr);
    // all remaining heads
    final_heads_kernel<<<B_N / 8, 256>>>(h0, h1, h2, h1b, h2b, h4b,
        pid_ext_w, pid_ext_b, sid_ext_w, sid_ext_b, rp_ext_w, rp_ext_b,
        eps_rp, eps_rp1, out);
}

// round 10
// speedup vs baseline: 3.4755x; 1.0848x over previous
#include <cuda_runtime.h>
#include <cstddef>
#include <cstdint>

#define B_N 4096
#define HID 256
#define OBS_D 400
#define IN_D 432

// ---------------- scratch (device globals; no allocation allowed) ----------------
__device__ float g_state[14 * B_N * HID];
__device__ float g_samp[4 * B_N * 16];      // prev_pid, samp_sid, samp_sid0, samp_sid1
__device__ float g_obs_emb[B_N * OBS_D];
__device__ float g_xpre[B_N * 1024];        // obs @ W0T (no bias)
__device__ float g_WhhT[256 * 1024];
__device__ float g_W0T[400 * 1024];
__device__ float g_WextT[32 * 1024];        // rows 0..15: samp cols; 16..31: addr cols
__device__ float g_bias[1024];              // b_ih + b_hh
__device__ float g_addrpre[7 * 1024];       // addr_emb[aid] @ WextT_addr + bias
__device__ float g_rp0[B_N * 2];
__device__ float g_z1[B_N * 100];
__device__ float g_z2[B_N * 100];
__device__ float g_rp0emb[B_N * 16];

__device__ __forceinline__ float sigf(float x) { return 1.f / (1.f + __expf(-x)); }
__device__ __forceinline__ float tanh_fast(float x) { return 2.f / (1.f + __expf(-2.f * x)) - 1.f; }

#define MMA_TF32(c, a, b) \
    asm volatile("mma.sync.aligned.m16n8k8.row.col.f32.tf32.tf32.f32 " \
        "{%0,%1,%2,%3}, {%4,%5,%6,%7}, {%8,%9}, {%0,%1,%2,%3};" \
        : "+f"((c)[0]), "+f"((c)[1]), "+f"((c)[2]), "+f"((c)[3]) \
        : "r"((a)[0]), "r"((a)[1]), "r"((a)[2]), "r"((a)[3]), "r"((b)[0]), "r"((b)[1]))

__device__ __forceinline__ void cp16(uint32_t smem_addr, const void* gptr) {
    asm volatile("cp.async.cg.shared.global [%0], [%1], 16;" :: "r"(smem_addr), "l"(gptr));
}
#define CP_COMMIT() asm volatile("cp.async.commit_group;")
#define CP_WAIT0()  asm volatile("cp.async.wait_group 0;" ::: "memory")

// ---------------- weight prep ----------------
__global__ void prep_weights_kernel(const float* __restrict__ W_ih, const float* __restrict__ b_ih,
                                    const float* __restrict__ W_hh, const float* __restrict__ b_hh,
                                    float* __restrict__ WhhT, float* __restrict__ W0T,
                                    float* __restrict__ WextT, float* __restrict__ bias) {
    int idx = blockIdx.x * blockDim.x + threadIdx.x;
    int stride = gridDim.x * blockDim.x;
    for (int i = idx; i < 256 * 1024; i += stride) { int k = i >> 10, j = i & 1023; WhhT[i] = W_hh[(size_t)j * 256 + k]; }
    for (int i = idx; i < 400 * 1024; i += stride) { int k = i >> 10, j = i & 1023; W0T[i] = W_ih[(size_t)j * IN_D + k]; }
    for (int i = idx; i < 32 * 1024;  i += stride) { int k = i >> 10, j = i & 1023; WextT[i] = W_ih[(size_t)j * IN_D + 400 + k]; }
    for (int i = idx; i < 1024; i += stride) bias[i] = b_ih[i] + b_hh[i];
}

// ---------------- embedding gathers + addrpre precompute (runs after prep, stream-ordered) ----------------
__global__ void gather_kernel(const int* __restrict__ pid, const int* __restrict__ sid,
                              const int* __restrict__ sid0, const int* __restrict__ sid1,
                              const float* __restrict__ pid_emb, const float* __restrict__ sid_emb,
                              const float* __restrict__ addr_emb, const float* __restrict__ WextT,
                              const float* __restrict__ bias, float* __restrict__ addrpre,
                              float* __restrict__ s_pid, float* __restrict__ s_sid,
                              float* __restrict__ s_sid0, float* __restrict__ s_sid1) {
    int i = blockIdx.x * blockDim.x + threadIdx.x;
    if (i < 7 * 1024) {
        int aid = i >> 10, j = i & 1023;
        float s = bias[j];
        #pragma unroll
        for (int k = 0; k < 16; k++)
            s += addr_emb[aid * 16 + k] * WextT[(size_t)(16 + k) * 1024 + j];
        addrpre[i] = s;
    }
    if (i >= B_N * 16) return;
    int b = i >> 4, k = i & 15;
    s_pid[i]  = pid_emb[pid[b]  * 16 + k];
    s_sid[i]  = sid_emb[sid[b]  * 16 + k];
    s_sid0[i] = sid_emb[sid0[b] * 16 + k];
    s_sid1[i] = sid_emb[sid1[b] * 16 + k];
}

// ---------------- fused conv: scalar conv1 + tf32-mma conv2 + pool ----------------
// smem: s_in 4096 | s_w1 288 | s_b1 32 | s_b2 16 | s_ko 72 | s_w2p 4896 ([288][17]) | s_c1p 8712 | s_c2 4096
#define CONV_SMEM_WORDS (4096 + 288 + 32 + 16 + 72 + 4896 + 8712 + 4096)
__global__ void __launch_bounds__(256, 2) conv_fused_kernel(
    const float* __restrict__ obs, const float* __restrict__ w1, const float* __restrict__ b1,
    const float* __restrict__ w2, const float* __restrict__ b2, float* __restrict__ obs_emb) {
    extern __shared__ float sm[];
    float* s_in  = sm;
    float* s_w1  = s_in + 4096;
    float* s_b1  = s_w1 + 288;
    float* s_b2  = s_b1 + 32;
    int*   s_ko  = (int*)(s_b2 + 16);
    float* s_w2p = s_b2 + 16 + 72;         // [288][17] full B panel
    float* s_c1p = s_w2p + 4896;           // 8 ch x 33 x 33 padded conv1 chunk
    float* s_c2  = s_c1p + 8712;           // [16 oc][256]
    int tid = threadIdx.x;
    int b = blockIdx.x;
    const float* in = obs + (size_t)b * 4096;
    for (int i = tid; i < 1024; i += 256) ((float4*)s_in)[i] = ((const float4*)in)[i];
    for (int i = tid; i < 288; i += 256) s_w1[i] = w1[i];
    for (int i = tid; i < 32; i += 256) s_b1[i] = b1[i];
    for (int i = tid; i < 16; i += 256) s_b2[i] = b2[i];
    for (int i = tid; i < 4608; i += 256) { int n = i / 288, kk = i - n * 288; s_w2p[kk * 17 + n] = w2[i]; }
    for (int i = tid; i < 8712; i += 256) s_c1p[i] = 0.f;   // halo stays zero
    if (tid < 72) {
        int icl = tid / 9, rem = tid - icl * 9, dy = rem / 3, dx = rem - dy * 3;
        s_ko[tid] = icl * 1089 + dy * 33 + dx;
    }
    __syncthreads();

    const int lane = tid & 31, w = tid >> 5;
    const int grp = lane >> 2, tig = lane & 3;

    const int c1y = ((tid >> 4) & 15) * 2;
    const int c1x = (tid & 15) * 2;
    const int c1iy0 = c1y * 2 - 1;
    const int c1ix0 = c1x * 2 - 1;
    float inp1[5][5];
    #pragma unroll
    for (int r = 0; r < 5; r++) {
        int iy = c1iy0 + r;
        bool okr = (unsigned)iy < 64u;
        #pragma unroll
        for (int q = 0; q < 5; q++) {
            int ix = c1ix0 + q;
            inp1[r][q] = (okr && (unsigned)ix < 64u) ? s_in[iy * 64 + ix] : 0.f;
        }
    }

    float acc[2][2][4];
    #pragma unroll
    for (int mt = 0; mt < 2; mt++)
        #pragma unroll
        for (int t = 0; t < 2; t++)
            #pragma unroll
            for (int q = 0; q < 4; q++) acc[mt][t][q] = 0.f;

    for (int cc = 0; cc < 4; cc++) {
        #pragma unroll
        for (int it = 0; it < 8; it++) {
            int oc = cc * 8 + it;
            float wv[9];
            #pragma unroll
            for (int q = 0; q < 9; q++) wv[q] = s_w1[oc * 9 + q];
            float bb = s_b1[oc];
            #pragma unroll
            for (int sy = 0; sy < 2; sy++)
                #pragma unroll
                for (int sx = 0; sx < 2; sx++) {
                    float a = bb;
                    #pragma unroll
                    for (int dy = 0; dy < 3; dy++)
                        #pragma unroll
                        for (int dx = 0; dx < 3; dx++)
                            a += wv[dy * 3 + dx] * inp1[sy * 2 + dy][sx * 2 + dx];
                    s_c1p[it * 1089 + (c1y + sy + 1) * 33 + (c1x + sx + 1)] = fmaxf(a, 0.f);
                }
        }
        __syncthreads();
        #pragma unroll
        for (int kk = 0; kk < 9; kk++) {
            int kb = kk * 8;
            int ko1 = s_ko[kb + tig], ko2 = s_ko[kb + tig + 4];
            uint32_t a[2][4], bf[2][2];
            #pragma unroll
            for (int mt = 0; mt < 2; mt++) {
                int mtile = w * 2 + mt;
                int base1 = mtile * 66 + grp * 2;
                int base2 = mtile * 66 + (grp + 8) * 2;
                a[mt][0] = __float_as_uint(s_c1p[ko1 + base1]);
                a[mt][1] = __float_as_uint(s_c1p[ko1 + base2]);
                a[mt][2] = __float_as_uint(s_c1p[ko2 + base1]);
                a[mt][3] = __float_as_uint(s_c1p[ko2 + base2]);
            }
            #pragma unroll
            for (int t = 0; t < 2; t++) {
                bf[t][0] = __float_as_uint(s_w2p[(cc * 72 + kb + tig) * 17 + t * 8 + grp]);
                bf[t][1] = __float_as_uint(s_w2p[(cc * 72 + kb + tig + 4) * 17 + t * 8 + grp]);
            }
            #pragma unroll
            for (int mt = 0; mt < 2; mt++)
                #pragma unroll
                for (int t = 0; t < 2; t++)
                    MMA_TF32(acc[mt][t], a[mt], bf[t]);
        }
        __syncthreads();
    }

    #pragma unroll
    for (int mt = 0; mt < 2; mt++) {
        int mtile = w * 2 + mt;
        int m1 = mtile * 16 + grp, m2 = m1 + 8;
        #pragma unroll
        for (int t = 0; t < 2; t++) {
            int oc0 = t * 8 + 2 * tig;
            float bb0 = s_b2[oc0], bb1 = s_b2[oc0 + 1];
            s_c2[oc0 * 256 + m1]       = fmaxf(acc[mt][t][0] + bb0, 0.f);
            s_c2[(oc0 + 1) * 256 + m1] = fmaxf(acc[mt][t][1] + bb1, 0.f);
            s_c2[oc0 * 256 + m2]       = fmaxf(acc[mt][t][2] + bb0, 0.f);
            s_c2[(oc0 + 1) * 256 + m2] = fmaxf(acc[mt][t][3] + bb1, 0.f);
        }
    }
    __syncthreads();
    for (int o = tid; o < 400; o += 256) {
        int c = o / 25;
        int rem = o - c * 25;
        int py = rem / 5, px = rem - (rem / 5) * 5;
        float s = 0.f;
        #pragma unroll
        for (int dy = 0; dy < 3; dy++)
            #pragma unroll
            for (int dx = 0; dx < 3; dx++)
                s += s_c2[c * 256 + (py * 3 + dy) * 16 + (px * 3 + dx)];
        obs_emb[(size_t)b * OBS_D + o] = s * (1.f / 9.f);
    }
}

// ---------------- tf32 GEMM phase (generic, used by xpre): m64 x 256 cols ----------------
__device__ __forceinline__ void tf32_gemm_phase(
    const float* __restrict__ A, int astride,
    const float* __restrict__ Bsrc, int nslabs, int u_base,
    uint32_t* __restrict__ sm, uint32_t smaddr,
    float acc[2][8][4],
    int tid, int grp, int tig, int mrow_base, int u_warp)
{
    const int am = tid >> 2, ak = (tid & 3) * 4;
    const int bkr = tid >> 4, bc0 = (tid & 15) * 16;
    const int bj = ((bc0 >> 6) << 8) + u_base + (bc0 & 63);
    uint32_t* sAp[2] = { sm, sm + 1280 };
    uint32_t* sBp[2] = { sm + 2560, sm + 2560 + 4224 };
    const uint32_t sAo[2] = { smaddr, smaddr + 5120u };
    const uint32_t sBo[2] = { smaddr + 10240u, smaddr + 10240u + 16896u };

    cp16(sAo[0] + (uint32_t)(am * 20 + ak) * 4u, A + (size_t)am * astride + ak);
    {
        const float* bp = Bsrc + (size_t)bkr * 1024 + bj;
        #pragma unroll
        for (int q = 0; q < 4; q++)
            cp16(sBo[0] + (uint32_t)(bkr * 264 + bc0 + q * 4) * 4u, bp + q * 4);
    }
    CP_COMMIT();

    for (int s = 0; s < nslabs; s++) {
        CP_WAIT0();
        __syncthreads();
        if (s + 1 < nslabs) {
            int nb = (s + 1) & 1;
            cp16(sAo[nb] + (uint32_t)(am * 20 + ak) * 4u, A + (size_t)am * astride + (s + 1) * 16 + ak);
            const float* bp = Bsrc + (size_t)((s + 1) * 16 + bkr) * 1024 + bj;
            #pragma unroll
            for (int q = 0; q < 4; q++)
                cp16(sBo[nb] + (uint32_t)(bkr * 264 + bc0 + q * 4) * 4u, bp + q * 4);
            CP_COMMIT();
        }
        const uint32_t* cA = sAp[s & 1];
        const uint32_t* cB = sBp[s & 1];
        #pragma unroll
        for (int k8 = 0; k8 < 16; k8 += 8) {
            uint32_t a[2][4], b[8][2];
            #pragma unroll
            for (int mi = 0; mi < 2; mi++) {
                int r = mrow_base + mi * 16 + grp;
                a[mi][0] = cA[r * 20 + k8 + tig];
                a[mi][1] = cA[(r + 8) * 20 + k8 + tig];
                a[mi][2] = cA[r * 20 + k8 + tig + 4];
                a[mi][3] = cA[(r + 8) * 20 + k8 + tig + 4];
            }
            #pragma unroll
            for (int t = 0; t < 8; t++) {
                int col = (t >> 1) * 64 + u_warp + (t & 1) * 8 + grp;
                b[t][0] = cB[(k8 + tig) * 264 + col];
                b[t][1] = cB[(k8 + tig + 4) * 264 + col];
            }
            #pragma unroll
            for (int mi = 0; mi < 2; mi++)
                #pragma unroll
                for (int t = 0; t < 8; t++)
                    MMA_TF32(acc[mi][t], a[mi], b[t]);
        }
        __syncthreads();
    }
}

// ---------------- fused LSTM GEMM: 16 h-slabs + 1 samp-slab in ONE pipeline ----------------
__device__ __forceinline__ void lstm_fused_gemm(
    const float* __restrict__ hA, const float* __restrict__ sampA,
    const float* __restrict__ WhhT, const float* __restrict__ WextT, int u_base,
    uint32_t* __restrict__ sm, uint32_t smaddr,
    float acc[2][8][4],
    int tid, int grp, int tig, int mrow_base, int u_warp)
{
    const int am = tid >> 2, ak = (tid & 3) * 4;
    const int bkr = tid >> 4, bc0 = (tid & 15) * 16;
    const int bj = ((bc0 >> 6) << 8) + u_base + (bc0 & 63);
    uint32_t* sAp[2] = { sm, sm + 1280 };
    uint32_t* sBp[2] = { sm + 2560, sm + 2560 + 4224 };
    const uint32_t sAo[2] = { smaddr, smaddr + 5120u };
    const uint32_t sBo[2] = { smaddr + 10240u, smaddr + 10240u + 16896u };

    cp16(sAo[0] + (uint32_t)(am * 20 + ak) * 4u, hA + (size_t)am * 256 + ak);
    {
        const float* bp = WhhT + (size_t)bkr * 1024 + bj;
        #pragma unroll
        for (int q = 0; q < 4; q++)
            cp16(sBo[0] + (uint32_t)(bkr * 264 + bc0 + q * 4) * 4u, bp + q * 4);
    }
    CP_COMMIT();

    for (int s = 0; s < 17; s++) {
        CP_WAIT0();
        __syncthreads();
        if (s + 1 < 17) {
            int nb = (s + 1) & 1;
            const float* aptr = (s + 1 < 16) ? hA + (size_t)am * 256 + (s + 1) * 16 + ak
                                             : sampA + (size_t)am * 16 + ak;
            const float* bptr = (s + 1 < 16) ? WhhT + (size_t)((s + 1) * 16 + bkr) * 1024 + bj
                                             : WextT + (size_t)bkr * 1024 + bj;
            cp16(sAo[nb] + (uint32_t)(am * 20 + ak) * 4u, aptr);
            #pragma unroll
            for (int q = 0; q < 4; q++)
                cp16(sBo[nb] + (uint32_t)(bkr * 264 + bc0 + q * 4) * 4u, bptr + q * 4);
            CP_COMMIT();
        }
        const uint32_t* cA = sAp[s & 1];
        const uint32_t* cB = sBp[s & 1];
        #pragma unroll
        for (int k8 = 0; k8 < 16; k8 += 8) {
            uint32_t a[2][4], b[8][2];
            #pragma unroll
            for (int mi = 0; mi < 2; mi++) {
                int r = mrow_base + mi * 16 + grp;
                a[mi][0] = cA[r * 20 + k8 + tig];
                a[mi][1] = cA[(r + 8) * 20 + k8 + tig];
                a[mi][2] = cA[r * 20 + k8 + tig + 4];
                a[mi][3] = cA[(r + 8) * 20 + k8 + tig + 4];
            }
            #pragma unroll
            for (int t = 0; t < 8; t++) {
                int col = (t >> 1) * 64 + u_warp + (t & 1) * 8 + grp;
                b[t][0] = cB[(k8 + tig) * 264 + col];
                b[t][1] = cB[(k8 + tig + 4) * 264 + col];
            }
            #pragma unroll
            for (int mi = 0; mi < 2; mi++)
                #pragma unroll
                for (int t = 0; t < 8; t++)
                    MMA_TF32(acc[mi][t], a[mi], b[t]);
        }
        __syncthreads();
    }
}

// ---------------- xpre = obs_emb @ W0T (NO bias; bias lives in addrpre) ----------------
__global__ void __launch_bounds__(256, 2) gemm_xpre_tf32_kernel(
    const float* __restrict__ A, const float* __restrict__ W0T, float* __restrict__ out) {
    __shared__ __align__(16) uint32_t sm[2 * 1280 + 2 * 4224];
    uint32_t smaddr = (uint32_t)__cvta_generic_to_shared(sm);

    const int tid = threadIdx.x;
    const int lane = tid & 31, w = tid >> 5;
    const int grp = lane >> 2, tig = lane & 3;
    const int mrow_base = (w >> 2) * 32;
    const int u_warp = (w & 3) * 16;
    const int u_base = blockIdx.x * 64;
    const int row0 = blockIdx.y * 64;

    float acc[2][8][4];
    #pragma unroll
    for (int mi = 0; mi < 2; mi++)
        #pragma unroll
        for (int t = 0; t < 8; t++)
            #pragma unroll
            for (int q = 0; q < 4; q++) acc[mi][t][q] = 0.f;

    tf32_gemm_phase(A + (size_t)row0 * OBS_D, OBS_D, W0T, 25, u_base, sm, smaddr,
                    acc, tid, grp, tig, mrow_base, u_warp);

    #pragma unroll
    for (int mi = 0; mi < 2; mi++)
        #pragma unroll
        for (int rr = 0; rr < 2; rr++) {
            size_t b = (size_t)(row0 + mrow_base + mi * 16 + grp + rr * 8);
            #pragma unroll
            for (int t = 0; t < 8; t++) {
                int g = t >> 1, uh = t & 1;
                int col = g * 256 + u_base + u_warp + uh * 8 + 2 * tig;
                *(float2*)&out[b * 1024 + col] =
                    make_float2(acc[mi][t][rr * 2 + 0], acc[mi][t][rr * 2 + 1]);
            }
        }
}

// ---------------- step0: h=c=samp=0 -> pure elementwise on xpre + addrpre[0] ----------------
__global__ void lstm_step0_kernel(const float* __restrict__ xpre, const float* __restrict__ ap,
                                  float* __restrict__ h0, float* __restrict__ c0) {
    int i = blockIdx.x * blockDim.x + threadIdx.x;
    if (i >= B_N * 64) return;
    int b = i >> 6, u4 = (i & 63) * 4;
    const float* xp = xpre + (size_t)b * 1024;
    float4 xi = *(const float4*)&xp[0   + u4];
    float4 xf = *(const float4*)&xp[256 + u4];   (void)xf;
    float4 xg = *(const float4*)&xp[512 + u4];
    float4 xo = *(const float4*)&xp[768 + u4];
    float4 ai = *(const float4*)&ap[0   + u4];
    float4 ag = *(const float4*)&ap[512 + u4];
    float4 ao = *(const float4*)&ap[768 + u4];
    float4 cv, hv;
    #define G0(comp) { \
        float iv = sigf(xi.comp + ai.comp); \
        float gv = tanh_fast(xg.comp + ag.comp); \
        float ov = sigf(xo.comp + ao.comp); \
        float cn = iv * gv; \
        cv.comp = cn; hv.comp = ov * tanh_fast(cn); }
    G0(x) G0(y) G0(z) G0(w)
    #undef G0
    *(float4*)&h0[(size_t)b * 256 + u4] = hv;
    *(float4*)&c0[(size_t)b * 256 + u4] = cv;
}

// ---------------- tf32 LSTM step: fused 17-slab GEMM + register gate epilogue ----------------
__global__ void __launch_bounds__(256, 2) lstm_step_tf32_kernel(
    const float* __restrict__ xpre, const float* __restrict__ addrpre,
    const float* __restrict__ WhhT, const float* __restrict__ WextT,
    const float* h_inA, const float* c_inA, const float* sampA, int aidA, float* h_outA, float* c_outA,
    const float* h_inB, const float* c_inB, const float* sampB, int aidB, float* h_outB, float* c_outB) {
    __shared__ __align__(16) uint32_t sm[2 * 1280 + 2 * 4224];
    uint32_t smaddr = (uint32_t)__cvta_generic_to_shared(sm);

    const float* h_in; const float* c_in; const float* samp; int aid; float* h_out; float* c_out;
    if (blockIdx.z == 0) { h_in = h_inA; c_in = c_inA; samp = sampA; aid = aidA; h_out = h_outA; c_out = c_outA; }
    else                 { h_in = h_inB; c_in = c_inB; samp = sampB; aid = aidB; h_out = h_outB; c_out = c_outB; }

    const int tid = threadIdx.x;
    const int lane = tid & 31, w = tid >> 5;
    const int grp = lane >> 2, tig = lane & 3;
    const int mrow_base = (w >> 2) * 32;
    const int u_warp = (w & 3) * 16;
    const int u_base = blockIdx.x * 64;
    const int row0 = blockIdx.y * 64;

    float acc[2][8][4];
    #pragma unroll
    for (int mi = 0; mi < 2; mi++)
        #pragma unroll
        for (int t = 0; t < 8; t++)
            #pragma unroll
            for (int q = 0; q < 4; q++) acc[mi][t][q] = 0.f;

    lstm_fused_gemm(h_in + (size_t)row0 * 256, samp + (size_t)row0 * 16,
                    WhhT, WextT, u_base, sm, smaddr,
                    acc, tid, grp, tig, mrow_base, u_warp);

    const int ub = u_base + u_warp;
    const float* ap = addrpre + aid * 1024;
    #pragma unroll
    for (int mi = 0; mi < 2; mi++)
        #pragma unroll
        for (int rr = 0; rr < 2; rr++) {
            size_t b = (size_t)(row0 + mrow_base + mi * 16 + grp + rr * 8);
            const float* xp = xpre + b * 1024;
            #pragma unroll
            for (int uh = 0; uh < 2; uh++) {
                int ug = ub + uh * 8 + 2 * tig;
                float2 xi = *(const float2*)&xp[0 * 256 + ug];
                float2 xf = *(const float2*)&xp[1 * 256 + ug];
                float2 xg = *(const float2*)&xp[2 * 256 + ug];
                float2 xo = *(const float2*)&xp[3 * 256 + ug];
                float2 ai = *(const float2*)&ap[0 * 256 + ug];
                float2 af = *(const float2*)&ap[1 * 256 + ug];
                float2 ag = *(const float2*)&ap[2 * 256 + ug];
                float2 ao = *(const float2*)&ap[3 * 256 + ug];
                float2 cold = *(const float2*)&c_in[b * 256 + ug];
                int q0 = rr * 2;
                float i0 = sigf(acc[mi][0 + uh][q0]     + xi.x + ai.x);
                float i1 = sigf(acc[mi][0 + uh][q0 + 1] + xi.y + ai.y);
                float f0 = sigf(acc[mi][2 + uh][q0]     + xf.x + af.x);
                float f1 = sigf(acc[mi][2 + uh][q0 + 1] + xf.y + af.y);
                float g0 = tanh_fast(acc[mi][4 + uh][q0]     + xg.x + ag.x);
                float g1 = tanh_fast(acc[mi][4 + uh][q0 + 1] + xg.y + ag.y);
                float o0 = sigf(acc[mi][6 + uh][q0]     + xo.x + ao.x);
                float o1 = sigf(acc[mi][6 + uh][q0 + 1] + xo.y + ao.y);
                float cn0 = f0 * cold.x + i0 * g0;
                float cn1 = f1 * cold.y + i1 * g1;
                *(float2*)&c_out[b * 256 + ug] = make_float2(cn0, cn1);
                *(float2*)&h_out[b * 256 + ug] = make_float2(o0 * tanh_fast(cn0), o1 * tanh_fast(cn1));
            }
        }
}

// ---------------- heads ----------------
__device__ __forceinline__ float warp_dot256(const float* __restrict__ h, const float* __restrict__ w, int lane) {
    const float* hp = h + lane * 8;
    const float* wp = w + lane * 8;
    float4 a0 = *(const float4*)hp;
    float4 a1 = *(const float4*)(hp + 4);
    float4 b0 = *(const float4*)wp;
    float4 b1 = *(const float4*)(wp + 4);
    float s = a0.x * b0.x + a0.y * b0.y + a0.z * b0.z + a0.w * b0.w
            + a1.x * b1.x + a1.y * b1.y + a1.z * b1.z + a1.w * b1.w;
    #pragma unroll
    for (int off = 16; off; off >>= 1) s += __shfl_down_sync(0xffffffffu, s, off);
    return s;  // valid on lane 0
}

__global__ void head_rp_kernel(const float* __restrict__ h, const float* __restrict__ W,
                               const float* __restrict__ bias, const float* __restrict__ eps,
                               int col0, float* __restrict__ out, float* __restrict__ save) {
    int gw = (blockIdx.x * blockDim.x + threadIdx.x) >> 5;
    int lane = threadIdx.x & 31;
    if (gw >= B_N) return;
    const float* hp = h + (size_t)gw * 256;
    float d[4];
    #pragma unroll
    for (int o = 0; o < 4; o++) d[o] = warp_dot256(hp, W + o * 256, lane);
    if (lane == 0) {
        float r0 = d[0] + bias[0] + __expf(d[2] + bias[2]) * eps[(size_t)gw * 2 + 0];
        float r1 = d[1] + bias[1] + __expf(d[3] + bias[3]) * eps[(size_t)gw * 2 + 1];
        out[(size_t)gw * 15 + col0 + 0] = r0;
        out[(size_t)gw * 15 + col0 + 1] = r1;
        if (save) { save[(size_t)gw * 2 + 0] = r0; save[(size_t)gw * 2 + 1] = r1; }
    }
}

__global__ void final_heads_kernel(
    const float* __restrict__ h0, const float* __restrict__ h1, const float* __restrict__ h2,
    const float* __restrict__ h1b, const float* __restrict__ h2b, const float* __restrict__ h4b,
    const float* __restrict__ pid_w, const float* __restrict__ pid_b,
    const float* __restrict__ sid_w, const float* __restrict__ sid_b,
    const float* __restrict__ rp_w, const float* __restrict__ rp_b,
    const float* __restrict__ eps_rp, const float* __restrict__ eps_rp1,
    float* __restrict__ out) {
    int gw = (blockIdx.x * blockDim.x + threadIdx.x) >> 5;
    int lane = threadIdx.x & 31;
    if (gw >= B_N) return;
    size_t off = (size_t)gw * 256;
    float* o = out + (size_t)gw * 15;
    for (int q = 0; q < 3; q++) {
        float s = warp_dot256(h0 + off, pid_w + q * 256, lane);
        if (lane == 0) o[q] = s + pid_b[q];
    }
    for (int q = 0; q < 2; q++) {
        float s = warp_dot256(h1 + off, sid_w + q * 256, lane);
        if (lane == 0) o[3 + q] = s + sid_b[q];
    }
    {
        float d[4];
        #pragma unroll
        for (int q = 0; q < 4; q++) d[q] = warp_dot256(h2 + off, rp_w + q * 256, lane);
        if (lane == 0) {
            o[5] = d[0] + rp_b[0] + __expf(d[2] + rp_b[2]) * eps_rp[(size_t)gw * 2 + 0];
            o[6] = d[1] + rp_b[1] + __expf(d[3] + rp_b[3]) * eps_rp[(size_t)gw * 2 + 1];
        }
    }
    for (int q = 0; q < 2; q++) {
        float s = warp_dot256(h1b + off, sid_w + q * 256, lane);
        if (lane == 0) o[7 + q] = s + sid_b[q];
    }
    for (int q = 0; q < 2; q++) {
        float s = warp_dot256(h2b + off, sid_w + q * 256, lane);
        if (lane == 0) o[9 + q] = s + sid_b[q];
    }
    {
        float d[4];
        #pragma unroll
        for (int q = 0; q < 4; q++) d[q] = warp_dot256(h4b + off, rp_w + q * 256, lane);
        if (lane == 0) {
            o[13] = d[0] + rp_b[0] + __expf(d[2] + rp_b[2]) * eps_rp1[(size_t)gw * 2 + 0];
            o[14] = d[1] + rp_b[1] + __expf(d[3] + rp_b[3]) * eps_rp1[(size_t)gw * 2 + 1];
        }
    }
}

// ---------------- MLP: rp0(2) -> 100 -> 100 -> 16 ----------------
__global__ void mlp1_kernel(const float* __restrict__ rp0, const float* __restrict__ w1,
                            const float* __restrict__ b1, float* __restrict__ z1) {
    int i = blockIdx.x * blockDim.x + threadIdx.x;
    if (i >= B_N * 100) return;
    int b = i / 100, j = i - b * 100;
    float v = rp0[b * 2] * w1[j * 2] + rp0[b * 2 + 1] * w1[j * 2 + 1] + b1[j];
    z1[i] = tanh_fast(v);
}

__global__ void __launch_bounds__(128) mlp2_kernel(const float* __restrict__ z1, const float* __restrict__ w2,
                                                   const float* __restrict__ b2, float* __restrict__ z2) {
    __shared__ float w2s[100 * 101];
    __shared__ float z1s[8 * 100];
    __shared__ float b2s[100];
    int tid = threadIdx.x;
    int b0 = blockIdx.x * 8;
    for (int i = tid; i < 100 * 100; i += 128) { int j = i / 100, k = i - j * 100; w2s[j * 101 + k] = w2[i]; }
    for (int i = tid; i < 800; i += 128) z1s[i] = z1[(size_t)b0 * 100 + i];
    for (int i = tid; i < 100; i += 128) b2s[i] = b2[i];
    __syncthreads();
    for (int t = tid; t < 800; t += 128) {
        int r = t / 100, j = t - r * 100;
        float s = b2s[j];
        const float* zz = z1s + r * 100;
        const float* ww = w2s + j * 101;
        #pragma unroll 4
        for (int k = 0; k < 100; k++) s += zz[k] * ww[k];
        z2[(size_t)(b0 + r) * 100 + j] = tanh_fast(s);
    }
}

__global__ void mlp3_kernel(const float* __restrict__ z2, const float* __restrict__ w3,
                            const float* __restrict__ b3, float* __restrict__ remb) {
    int i = blockIdx.x * blockDim.x + threadIdx.x;
    if (i >= B_N * 16) return;
    int b = i >> 4, o = i & 15;
    float s = b3[o];
    const float* zz = z2 + (size_t)b * 100;
    const float* ww = w3 + o * 100;
    #pragma unroll 4
    for (int k = 0; k < 100; k++) s += zz[k] * ww[k];
    remb[i] = s;
}

// ---------------- host ----------------
static float* getsym(const void* symbol) {
    void* p = nullptr;
    cudaGetSymbolAddress(&p, symbol);
    return (float*)p;
}

extern "C" void kernel_launch(void* const* d_in, const int* in_sizes, int n_in,
                              void* d_out, int out_size) {
    const float* obs        = (const float*)d_in[0];
    const int*   program_id = (const int*)  d_in[1];
    const int*   shape_id   = (const int*)  d_in[2];
    const int*   shape_id_0 = (const int*)  d_in[3];
    const int*   shape_id_1 = (const int*)  d_in[4];
    const float* eps_rp     = (const float*)d_in[5];
    const float* eps_rp0    = (const float*)d_in[6];
    const float* eps_rp1    = (const float*)d_in[7];
    const float* conv1_w    = (const float*)d_in[8];
    const float* conv1_b    = (const float*)d_in[9];
    const float* conv2_w    = (const float*)d_in[10];
    const float* conv2_b    = (const float*)d_in[11];
    const float* mlp_w1     = (const float*)d_in[12];
    const float* mlp_b1     = (const float*)d_in[13];
    const float* mlp_w2     = (const float*)d_in[14];
    const float* mlp_b2     = (const float*)d_in[15];
    const float* mlp_w3     = (const float*)d_in[16];
    const float* mlp_b3     = (const float*)d_in[17];
    const float* W_ih       = (const float*)d_in[18];
    const float* b_ih       = (const float*)d_in[19];
    const float* W_hh       = (const float*)d_in[20];
    const float* b_hh       = (const float*)d_in[21];
    const float* addr_emb   = (const float*)d_in[22];
    const float* pid_emb    = (const float*)d_in[23];
    const float* sid_emb    = (const float*)d_in[24];
    const float* pid_ext_w  = (const float*)d_in[25];
    const float* pid_ext_b  = (const float*)d_in[26];
    const float* sid_ext_w  = (const float*)d_in[27];
    const float* sid_ext_b  = (const float*)d_in[28];
    const float* rp_ext_w   = (const float*)d_in[29];
    const float* rp_ext_b   = (const float*)d_in[30];
    float* out = (float*)d_out;

    float* st      = getsym(g_state);
    const int SZ   = B_N * HID;
    float* h0  = st + 0 * SZ;  float* c0  = st + 1 * SZ;
    float* h1  = st + 2 * SZ;  float* c1  = st + 3 * SZ;
    float* h1b = st + 4 * SZ;  float* c1b = st + 5 * SZ;
    float* h2  = st + 6 * SZ;  float* c2  = st + 7 * SZ;
    float* h2b = st + 8 * SZ;  float* c2b = st + 9 * SZ;
    float* h3b = st + 10 * SZ; float* c3b = st + 11 * SZ;
    float* h4b = st + 12 * SZ; float* c4b = st + 13 * SZ;

    float* samp   = getsym(g_samp);
    float* s_pid  = samp + 0 * B_N * 16;
    float* s_sid  = samp + 1 * B_N * 16;
    float* s_sid0 = samp + 2 * B_N * 16;
    float* s_sid1 = samp + 3 * B_N * 16;

    float* obs_e  = getsym(g_obs_emb);
    float* xpre   = getsym(g_xpre);
    float* WhhT   = getsym(g_WhhT);
    float* W0T    = getsym(g_W0T);
    float* WextT  = getsym(g_WextT);
    float* bias   = getsym(g_bias);
    float* addrpre= getsym(g_addrpre);
    float* rp0    = getsym(g_rp0);
    float* z1     = getsym(g_z1);
    float* z2     = getsym(g_z2);
    float* rp0emb = getsym(g_rp0emb);

    const int CONV_SMEM = CONV_SMEM_WORDS * 4;
    cudaFuncSetAttribute(conv_fused_kernel, cudaFuncAttributeMaxDynamicSharedMemorySize, CONV_SMEM);

    prep_weights_kernel<<<512, 256>>>(W_ih, b_ih, W_hh, b_hh, WhhT, W0T, WextT, bias);
    gather_kernel<<<B_N * 16 / 256, 256>>>(program_id, shape_id, shape_id_0, shape_id_1,
                                           pid_emb, sid_emb, addr_emb, WextT, bias, addrpre,
                                           s_pid, s_sid, s_sid0, s_sid1);
    conv_fused_kernel<<<B_N, 256, CONV_SMEM>>>(obs, conv1_w, conv1_b, conv2_w, conv2_b, obs_e);
    gemm_xpre_tf32_kernel<<<dim3(4, B_N / 64), 256>>>(obs_e, W0T, xpre);

    // step0: pure elementwise
    lstm_step0_kernel<<<B_N * 64 / 256, 256>>>(xpre, addrpre, h0, c0);

    dim3 t1(4, B_N / 64, 1);
    dim3 t2(4, B_N / 64, 2);
    // pair: step1A (aid=1) + step1B (aid=2), both from (h0,c0,s_pid)
    lstm_step_tf32_kernel<<<t2, 256>>>(xpre, addrpre, WhhT, WextT,
        h0, c0, s_pid, 1, h1, c1,
        h0, c0, s_pid, 2, h1b, c1b);
    // pair: step2A (h1,s_sid,aid=4) + step2B (h1b,s_sid0,aid=3)
    lstm_step_tf32_kernel<<<t2, 256>>>(xpre, addrpre, WhhT, WextT,
        h1, c1, s_sid, 4, h2, c2,
        h1b, c1b, s_sid0, 3, h2b, c2b);
    // step3B
    lstm_step_tf32_kernel<<<t1, 256>>>(xpre, addrpre, WhhT, WextT,
        h2b, c2b, s_sid1, 5, h3b, c3b,
        nullptr, nullptr, nullptr, 0, nullptr, nullptr);
    head_rp_kernel<<<B_N / 8, 256>>>(h3b, rp_ext_w, rp_ext_b, eps_rp0, 11, out, rp0);
    // MLP on rp0
    mlp1_kernel<<<(B_N * 100 + 255) / 256, 256>>>(rp0, mlp_w1, mlp_b1, z1);
    mlp2_kernel<<<B_N / 8, 128>>>(z1, mlp_w2, mlp_b2, z2);
    mlp3_kernel<<<B_N * 16 / 256, 256>>>(z2, mlp_w3, mlp_b3, rp0emb);
    // step4B
    lstm_step_tf32_kernel<<<t1, 256>>>(xpre, addrpre, WhhT, WextT,
        h3b, c3b, rp0emb, 6, h4b, c4b,
        nullptr, nullptr, nullptr, 0, nullptr, nullptr);
    // all remaining heads
    final_heads_kernel<<<B_N / 8, 256>>>(h0, h1, h2, h1b, h2b, h4b,
        pid_ext_w, pid_ext_b, sid_ext_w, sid_ext_b, rp_ext_w, rp_ext_b,
        eps_rp, eps_rp1, out);
}